// round 10
// baseline (speedup 1.0000x reference)
#include <cuda_runtime.h>
#include <math.h>
#include <stdint.h>

#define D_NUM 4000
#define T_NUM 2000
#define FEAT  256
#define UNITS 200
#define TOPK  10
#define NCHUNK 16

// ---------------- scratch ----------------
__device__ float g_S[(size_t)D_NUM * T_NUM];
__device__ float g_RT[(size_t)T_NUM * D_NUM];
__device__ float g_catd[(size_t)D_NUM * 3 * FEAT];
__device__ float g_catt[(size_t)T_NUM * 3 * FEAT];
__device__ float g_hd[(size_t)D_NUM * FEAT];
__device__ float g_ht[(size_t)T_NUM * FEAT];
__device__ float g_hdp[(size_t)D_NUM * UNITS];
__device__ float g_htp[(size_t)T_NUM * UNITS];
__device__ float g_htpT[(size_t)UNITS * T_NUM];
__device__ float g_bsd[(size_t)D_NUM * FEAT];
__device__ float g_bst[(size_t)D_NUM * FEAT];
__device__ float g_bsd2[(size_t)D_NUM * FEAT];
__device__ float g_bst2[(size_t)D_NUM * FEAT];
__device__ float g_pa[(size_t)4 * D_NUM * FEAT];   // split-K partials, problem 0
__device__ float g_pb[(size_t)4 * D_NUM * FEAT];   // split-K partials, problem 1
__device__ float g_sd[D_NUM];
__device__ float g_st[T_NUM];
__device__ float g_nd[D_NUM];
__device__ float g_nt[T_NUM];
__device__ float g_ntraw[T_NUM];
__device__ float g_part[NCHUNK * T_NUM];
__device__ int   g_selidx[D_NUM * TOPK];
__device__ float g_selval[D_NUM * TOPK];

__device__ __forceinline__ uint32_t f2tf(float x) {
    uint32_t r;
    asm("cvt.rna.tf32.f32 %0, %1;" : "=r"(r) : "f"(x));
    return r;
}
__device__ __forceinline__ float roundtf(float x) {
    return __uint_as_float(f2tf(x));
}

// ---------------- reductions ----------------
__global__ void rowsum_rsqrt(const float* __restrict__ A, int rows, int cols,
                             float* __restrict__ out) {
    int row = blockIdx.x;
    if (row >= rows) return;
    const float* a = A + (size_t)row * cols;
    float s = 0.f;
    for (int j = threadIdx.x; j < cols; j += blockDim.x) s += a[j];
    __shared__ float red[256];
    red[threadIdx.x] = s;
    __syncthreads();
    for (int off = 128; off > 0; off >>= 1) {
        if (threadIdx.x < off) red[threadIdx.x] += red[threadIdx.x + off];
        __syncthreads();
    }
    if (threadIdx.x == 0) {
        float n = red[0];
        if (n == 0.f) n = 1.f;
        out[row] = rsqrtf(n);
    }
}

__global__ void colsum_partial(const float* __restrict__ A, int rows, int cols,
                               float* __restrict__ part) {
    int j = blockIdx.x * blockDim.x + threadIdx.x;
    if (j >= cols) return;
    int chunk = (rows + NCHUNK - 1) / NCHUNK;
    int r0 = blockIdx.y * chunk;
    int r1 = r0 + chunk; if (r1 > rows) r1 = rows;
    float s = 0.f;
    for (int i = r0; i < r1; i++) s += A[(size_t)i * cols + j];
    part[blockIdx.y * cols + j] = s;
}

__global__ void colsum_finish(const float* __restrict__ part, int cols,
                              float* __restrict__ out) {
    int j = blockIdx.x * blockDim.x + threadIdx.x;
    if (j >= cols) return;
    float s = 0.f;
    for (int c = 0; c < NCHUNK; c++) s += part[c * cols + j];
    if (s == 0.f) s = 1.f;
    out[j] = rsqrtf(s);
}

// ---------------- prep kernels ----------------
__global__ void prescale2(float* dst0, const float* src0, const float* sc0, int rows0,
                          float* dst1, const float* src1, const float* sc1, int rows1,
                          int cols4) {
    int c4 = blockIdx.x * blockDim.x + threadIdx.x;
    int r = blockIdx.y;
    float* dst = blockIdx.z ? dst1 : dst0;
    const float* src = blockIdx.z ? src1 : src0;
    const float* sc = blockIdx.z ? sc1 : sc0;
    int rows = blockIdx.z ? rows1 : rows0;
    if (c4 >= cols4 || r >= rows) return;
    float s = sc[r];
    float4 v = reinterpret_cast<const float4*>(src + (size_t)r * cols4 * 4)[c4];
    v.x = roundtf(v.x * s); v.y = roundtf(v.y * s);
    v.z = roundtf(v.z * s); v.w = roundtf(v.w * s);
    reinterpret_cast<float4*>(dst + (size_t)r * cols4 * 4)[c4] = v;
}

__global__ void transpose_kernel(float* __restrict__ dst, const float* __restrict__ src,
                                 int rows, int cols) {
    __shared__ float t[32][33];
    int bx = blockIdx.x * 32, by = blockIdx.y * 32;
    int x = bx + threadIdx.x;
    #pragma unroll
    for (int i = 0; i < 32; i += 8) {
        int y = by + threadIdx.y + i;
        if (x < cols && y < rows) t[threadIdx.y + i][threadIdx.x] = src[(size_t)y * cols + x];
    }
    __syncthreads();
    int x2 = by + threadIdx.x;
    #pragma unroll
    for (int i = 0; i < 32; i += 8) {
        int y2 = bx + threadIdx.y + i;
        if (x2 < rows && y2 < cols) dst[(size_t)y2 * rows + x2] = t[threadIdx.x][threadIdx.y + i];
    }
}

__global__ void zero_vec(float* __restrict__ p, int n) {
    int i = blockIdx.x * blockDim.x + threadIdx.x;
    if (i < n) p[i] = 0.f;
}

__global__ void zero_strided(float* __restrict__ dst, int ld, int rows, int cols) {
    int c = blockIdx.x * blockDim.x + threadIdx.x;
    int r = blockIdx.y;
    if (c < cols && r < rows) dst[(size_t)r * ld + c] = 0.f;
}

__global__ void relu_round_strided(float* __restrict__ dst, int ld, int rows, int cols) {
    int c = blockIdx.x * blockDim.x + threadIdx.x;
    int r = blockIdx.y;
    if (c < cols && r < rows) {
        size_t o = (size_t)r * ld + c;
        dst[o] = roundtf(fmaxf(dst[o], 0.f));
    }
}

__global__ void copy_round2(float* dst0, int ldd0, const float* src0, int lds0, int rows0,
                            float* dst1, int ldd1, const float* src1, int lds1, int rows1,
                            int cols) {
    int c = blockIdx.x * blockDim.x + threadIdx.x;
    int r = blockIdx.y;
    float* dst = blockIdx.z ? dst1 : dst0;
    const float* src = blockIdx.z ? src1 : src0;
    int ldd = blockIdx.z ? ldd1 : ldd0;
    int lds = blockIdx.z ? lds1 : lds0;
    int rows = blockIdx.z ? rows1 : rows0;
    if (c < cols && r < rows)
        dst[(size_t)r * ldd + c] = roundtf(src[(size_t)r * lds + c]);
}

// split-K reduce + epilogue, z-fused pair, NS slabs.
template <int EPI, int NS>
__global__ void reduce2(float* out0, int ld0, const float* part0, const float* rs0, int M0, int N0,
                        float* out1, int ld1, const float* part1, const float* rs1, int M1, int N1) {
    int c = blockIdx.x * blockDim.x + threadIdx.x;
    int r = blockIdx.y;
    float* out = blockIdx.z ? out1 : out0;
    const float* part = blockIdx.z ? part1 : part0;
    const float* rs = blockIdx.z ? rs1 : rs0;
    int M = blockIdx.z ? M1 : M0;
    int N = blockIdx.z ? N1 : N0;
    int ld = blockIdx.z ? ld1 : ld0;
    if (r >= M || c >= N) return;
    size_t o = (size_t)r * N + c;
    size_t slab = (size_t)M * N;
    float v = 0.f;
    #pragma unroll
    for (int s = 0; s < NS; s++) v += part[s * slab + o];
    if (rs) v *= rs[r];
    if (EPI == 1 || EPI == 4) v = fmaxf(v, 0.f);
    if (EPI >= 3) v = roundtf(v);
    out[(size_t)r * ld + c] = v;
}

// ---------------- top-k ----------------
__global__ void topk_kernel(const float* __restrict__ S,
                            int* __restrict__ selidx, float* __restrict__ selval,
                            float* __restrict__ nd_out, float* __restrict__ ntraw) {
    int row = blockIdx.x;
    int tid = threadIdx.x;
    int lane = tid & 31, wid = tid >> 5;
    const float* srow = S + (size_t)row * T_NUM;

    float v[8];
    #pragma unroll
    for (int i = 0; i < 8; i++) {
        int j = tid + i * 256;
        v[i] = (j < T_NUM) ? srow[j] : -3.f;
    }

    __shared__ float wv[8];
    __shared__ int   wi[8];
    __shared__ int   bidx_s;
    __shared__ int   sel[TOPK];
    __shared__ float selv[TOPK];

    for (int it = 0; it < TOPK; it++) {
        float best = v[0]; int bi = tid;
        #pragma unroll
        for (int i = 1; i < 8; i++) {
            int j = tid + i * 256;
            if (v[i] > best) { best = v[i]; bi = j; }
        }
        #pragma unroll
        for (int off = 16; off > 0; off >>= 1) {
            float ov = __shfl_xor_sync(0xffffffffu, best, off);
            int   oi = __shfl_xor_sync(0xffffffffu, bi, off);
            if (ov > best || (ov == best && oi < bi)) { best = ov; bi = oi; }
        }
        if (lane == 0) { wv[wid] = best; wi[wid] = bi; }
        __syncthreads();
        if (tid == 0) {
            float b = wv[0]; int x = wi[0];
            #pragma unroll
            for (int w = 1; w < 8; w++)
                if (wv[w] > b || (wv[w] == b && wi[w] < x)) { b = wv[w]; x = wi[w]; }
            bidx_s = x; sel[it] = x; selv[it] = b;
        }
        __syncthreads();
        int x = bidx_s;
        if ((x & 255) == tid) v[x >> 8] = -3.f;
    }

    if (tid < TOPK) {
        selidx[row * TOPK + tid] = sel[tid];
        selval[row * TOPK + tid] = selv[tid];
        atomicAdd(&ntraw[sel[tid]], selv[tid]);
    }
    if (tid == 0) {
        float s = 0.f;
        #pragma unroll
        for (int t = 0; t < TOPK; t++) s += selv[t];
        if (s == 0.f) s = 1.f;
        nd_out[row] = rsqrtf(s);
    }
}

// ---------------- sparse CGC ----------------
__global__ void gather_dt(const int* __restrict__ selidx, const float* __restrict__ selval,
                          const float* __restrict__ nd, const float* __restrict__ ntraw,
                          const float* __restrict__ ht, int F,
                          float* __restrict__ outd, int ldo) {
    int d = blockIdx.x;
    __shared__ int   ci[TOPK];
    __shared__ float cw[TOPK];
    if (threadIdx.x < TOPK) {
        int c = selidx[d * TOPK + threadIdx.x];
        float s = ntraw[c];
        if (s == 0.f) s = 1.f;
        ci[threadIdx.x] = c;
        cw[threadIdx.x] = selval[d * TOPK + threadIdx.x] * rsqrtf(s);
    }
    __syncthreads();
    float ndv = nd[d];
    for (int f = threadIdx.x; f < F; f += blockDim.x) {
        float s = 0.f;
        #pragma unroll
        for (int j = 0; j < TOPK; j++) s += cw[j] * ht[(size_t)ci[j] * F + f];
        outd[(size_t)d * ldo + f] = roundtf(fmaxf(s * ndv, 0.f));
    }
}

__global__ void scatter_td(const int* __restrict__ selidx, const float* __restrict__ selval,
                           const float* __restrict__ nd, const float* __restrict__ ntraw,
                           const float* __restrict__ hd, int F,
                           float* __restrict__ outt, int ldo) {
    int e = blockIdx.x;
    int d = e / TOPK;
    int t = selidx[e];
    float s = ntraw[t];
    if (s == 0.f) s = 1.f;
    float w = selval[e] * nd[d] * rsqrtf(s);
    const float* src = hd + (size_t)d * F;
    float* dst = outt + (size_t)t * ldo;
    for (int f = threadIdx.x; f < F; f += blockDim.x)
        atomicAdd(&dst[f], w * src[f]);
}

// ---------------- TF32 GEMM: 128x64 block, 64x32 warp tile, split-K NS ----------
struct GemmP {
    const float* A;
    const float* B;
    float* C;            // output, or split-K partial base (ld = N, NS slabs)
    int M, N, K, lda, ldb, ldc;
    const float* rowscale;
};

__device__ __forceinline__ void mma_tf32(float c[4], uint32_t a0, uint32_t a1,
                                         uint32_t a2, uint32_t a3,
                                         uint32_t b0, uint32_t b1) {
    asm volatile(
        "mma.sync.aligned.m16n8k8.row.col.f32.tf32.tf32.f32 "
        "{%0,%1,%2,%3}, {%4,%5,%6,%7}, {%8,%9}, {%0,%1,%2,%3};"
        : "+f"(c[0]), "+f"(c[1]), "+f"(c[2]), "+f"(c[3])
        : "r"(a0), "r"(a1), "r"(a2), "r"(a3), "r"(b0), "r"(b1));
}

__device__ __forceinline__ uint32_t cvt_bits(uint32_t raw) {
    return f2tf(__uint_as_float(raw));
}

__device__ __forceinline__ void cp_async16(uint32_t dst_smem, const void* src, bool pred) {
    int sz = pred ? 16 : 0;
    asm volatile("cp.async.cg.shared.global [%0], [%1], 16, %2;"
                 :: "r"(dst_smem), "l"(src), "r"(sz));
}
#define CP_COMMIT() asm volatile("cp.async.commit_group;")
#define CP_WAIT1()  asm volatile("cp.async.wait_group 1;")

#define GBM 128
#define GBN 64
#define GBK 16
#define NSTAGE 3
#define GTHREADS 128
#define ASTR (GBK + 4)
#define BSTR (GBN + 8)

template <int EPI, bool ACVT, bool BCVT, int NS>
__global__ __launch_bounds__(GTHREADS)
void mma_gemm_f(GemmP p0, GemmP p1) {
    int prob = blockIdx.z / NS;
    int split = blockIdx.z % NS;
    const GemmP p = prob ? p1 : p0;
    int bm = blockIdx.y * GBM;
    int bn = blockIdx.x * GBN;
    if (bm >= p.M || bn >= p.N) return;

    __shared__ uint32_t As[NSTAGE][GBM][ASTR];
    __shared__ uint32_t Bs[NSTAGE][GBK][BSTR];

    int tid = threadIdx.x;
    int lane = tid & 31;
    int warp = tid >> 5;
    int gid = lane >> 2, tig = lane & 3;
    int mw = (warp & 1) * 64;
    int nw = (warp >> 1) * 32;

    uint32_t sa = (uint32_t)__cvta_generic_to_shared(&As[0][0][0]);
    uint32_t sb = (uint32_t)__cvta_generic_to_shared(&Bs[0][0][0]);

    float acc[4][4][4];
    #pragma unroll
    for (int i = 0; i < 4; i++)
        #pragma unroll
        for (int j = 0; j < 4; j++)
            #pragma unroll
            for (int l = 0; l < 4; l++) acc[i][j][l] = 0.f;

    int nkt_total = (p.K + GBK - 1) / GBK;
    int chunk = (nkt_total + NS - 1) / NS;
    int kt_begin = split * chunk;
    int kt_end = min(nkt_total, kt_begin + chunk);
    int niter = kt_end - kt_begin;
    if (niter <= 0) niter = 0;

    // A: 128 rows x 16 k -> 1 row/thread, 4 chunks.  B: 16 x 64 -> 2 chunks/thread.
    int b_kb = tid >> 3;
    int b_nq = (tid & 7) * 8;

    auto issue_tile = [&](int kt, int st) {
        int k0 = kt * GBK;
        {
            int gm = bm + tid;
            const float* src = p.A + (size_t)gm * p.lda + k0;
            uint32_t dst = sa + ((st * GBM + tid) * ASTR) * 4;
            bool rowok = (gm < p.M);
            #pragma unroll
            for (int u = 0; u < 4; u++)
                cp_async16(dst + u * 16, src + u * 4, rowok && (k0 + u * 4 < p.K));
        }
        {
            int gk = k0 + b_kb;
            const float* src = p.B + (size_t)gk * p.ldb + bn + b_nq;
            uint32_t dst = sb + (((st * GBK + b_kb) * BSTR) + b_nq) * 4;
            bool kok = (gk < p.K);
            cp_async16(dst,      src,     kok && (bn + b_nq     < p.N));
            cp_async16(dst + 16, src + 4, kok && (bn + b_nq + 4 < p.N));
        }
    };

    #pragma unroll
    for (int s = 0; s < NSTAGE - 1; s++) {
        if (s < niter) issue_tile(kt_begin + s, s);
        CP_COMMIT();
    }

    int cur = 0;
    for (int it = 0; it < niter; it++) {
        CP_WAIT1();
        __syncthreads();

        #pragma unroll
        for (int kk = 0; kk < GBK; kk += 8) {
            uint32_t b0[4], b1[4];
            #pragma unroll
            for (int nt = 0; nt < 4; nt++) {
                b0[nt] = Bs[cur][kk + tig][nw + nt * 8 + gid];
                b1[nt] = Bs[cur][kk + tig + 4][nw + nt * 8 + gid];
                if (BCVT) { b0[nt] = cvt_bits(b0[nt]); b1[nt] = cvt_bits(b1[nt]); }
            }
            #pragma unroll
            for (int mt = 0; mt < 4; mt++) {
                int mb = mw + mt * 16;
                uint32_t a0 = As[cur][mb + gid][kk + tig];
                uint32_t a1 = As[cur][mb + gid + 8][kk + tig];
                uint32_t a2 = As[cur][mb + gid][kk + tig + 4];
                uint32_t a3 = As[cur][mb + gid + 8][kk + tig + 4];
                if (ACVT) {
                    a0 = cvt_bits(a0); a1 = cvt_bits(a1);
                    a2 = cvt_bits(a2); a3 = cvt_bits(a3);
                }
                #pragma unroll
                for (int nt = 0; nt < 4; nt++)
                    mma_tf32(acc[mt][nt], a0, a1, a2, a3, b0[nt], b1[nt]);
            }
        }

        if (it + NSTAGE - 1 < niter) {
            int st = (cur + NSTAGE - 1) % NSTAGE;
            issue_tile(kt_begin + it + NSTAGE - 1, st);
        }
        CP_COMMIT();
        cur = (cur + 1) % NSTAGE;
    }

    // ---------- epilogue ----------
    if (NS > 1) {
        float* dst = p.C + (size_t)split * p.M * p.N;
        #pragma unroll
        for (int mt = 0; mt < 4; mt++) {
            int gm0 = bm + mw + mt * 16 + gid;
            int gm1 = gm0 + 8;
            #pragma unroll
            for (int nt = 0; nt < 4; nt++) {
                int gn0 = bn + nw + nt * 8 + 2 * tig;
                int gn1 = gn0 + 1;
                #pragma unroll
                for (int q = 0; q < 4; q++) {
                    int gm = (q < 2) ? gm0 : gm1;
                    int gn = (q & 1) ? gn1 : gn0;
                    if (gm >= p.M || gn >= p.N) continue;
                    dst[(size_t)gm * p.N + gn] = acc[mt][nt][q];
                }
            }
        }
        return;
    }

    #pragma unroll
    for (int mt = 0; mt < 4; mt++) {
        int gm0 = bm + mw + mt * 16 + gid;
        int gm1 = gm0 + 8;
        float rs0 = 1.f, rs1 = 1.f;
        if (p.rowscale) {
            if (gm0 < p.M) rs0 = p.rowscale[gm0];
            if (gm1 < p.M) rs1 = p.rowscale[gm1];
        }
        #pragma unroll
        for (int nt = 0; nt < 4; nt++) {
            int gn0 = bn + nw + nt * 8 + 2 * tig;
            int gn1 = gn0 + 1;
            #pragma unroll
            for (int q = 0; q < 4; q++) {
                int gm = (q < 2) ? gm0 : gm1;
                int gn = (q & 1) ? gn1 : gn0;
                if (gm >= p.M || gn >= p.N) continue;
                float v = acc[mt][nt][q] * ((q < 2) ? rs0 : rs1);
                if (EPI == 1 || EPI == 4) v = fmaxf(v, 0.f);
                else if (EPI == 2) v = 1.f / (1.f + __expf(-v));
                if (EPI >= 3) v = roundtf(v);
                p.C[(size_t)gm * p.ldc + gn] = v;
            }
        }
    }
}

static inline GemmP mk(const float* A, const float* B, float* C,
                       int M, int N, int K, int lda, int ldb, int ldc,
                       const float* rs) {
    GemmP p; p.A = A; p.B = B; p.C = C; p.M = M; p.N = N; p.K = K;
    p.lda = lda; p.ldb = ldb; p.ldc = ldc; p.rowscale = rs; return p;
}
static inline dim3 grid1(const GemmP& p) {
    return dim3((p.N + GBN - 1) / GBN, (p.M + GBM - 1) / GBM, 1);
}
static inline dim3 grid2(const GemmP& a, const GemmP& b, int ns) {
    int gx = max((a.N + GBN - 1) / GBN, (b.N + GBN - 1) / GBN);
    int gy = max((a.M + GBM - 1) / GBM, (b.M + GBM - 1) / GBM);
    return dim3(gx, gy, 2 * ns);
}
static inline dim3 tr_grid(int rows, int cols) {
    return dim3((cols + 31) / 32, (rows + 31) / 32);
}
static inline dim3 red_grid(const GemmP& a, const GemmP& b) {
    int n = max(a.N, b.N);
    int m = max(a.M, b.M);
    return dim3((n + 255) / 256, m, 2);
}

// ---------------- host orchestration ----------------
extern "C" void kernel_launch(void* const* d_in, const int* in_sizes, int n_in,
                              void* d_out, int out_size) {
    const float* R    = (const float*)d_in[0];
    const float* Dm   = (const float*)d_in[1];
    const float* Tm   = (const float*)d_in[2];
    const float* H_d  = (const float*)d_in[3];
    const float* H_t  = (const float*)d_in[4];
    const float* W1g[2] = {(const float*)d_in[5], (const float*)d_in[7]};
    const float* W2g[2] = {(const float*)d_in[6], (const float*)d_in[8]};
    const float* Wd[2]  = {(const float*)d_in[9], (const float*)d_in[11]};
    const float* Wt[2]  = {(const float*)d_in[10], (const float*)d_in[12]};
    const float* WdO  = (const float*)d_in[13];
    const float* WtO  = (const float*)d_in[14];
    float* out = (float*)d_out;

    float *S, *RT, *catd, *catt, *hdb, *htb, *hdp, *htp, *htpT;
    float *bsd, *bst, *bsd2, *bst2, *pa, *pb;
    float *sd, *st, *nd, *nt, *ntraw, *part, *selval;
    int* selidx;
    cudaGetSymbolAddress((void**)&S,     g_S);
    cudaGetSymbolAddress((void**)&RT,    g_RT);
    cudaGetSymbolAddress((void**)&catd,  g_catd);
    cudaGetSymbolAddress((void**)&catt,  g_catt);
    cudaGetSymbolAddress((void**)&hdb,   g_hd);
    cudaGetSymbolAddress((void**)&htb,   g_ht);
    cudaGetSymbolAddress((void**)&hdp,   g_hdp);
    cudaGetSymbolAddress((void**)&htp,   g_htp);
    cudaGetSymbolAddress((void**)&htpT,  g_htpT);
    cudaGetSymbolAddress((void**)&bsd,   g_bsd);
    cudaGetSymbolAddress((void**)&bst,   g_bst);
    cudaGetSymbolAddress((void**)&bsd2,  g_bsd2);
    cudaGetSymbolAddress((void**)&bst2,  g_bst2);
    cudaGetSymbolAddress((void**)&pa,    g_pa);
    cudaGetSymbolAddress((void**)&pb,    g_pb);
    cudaGetSymbolAddress((void**)&sd,    g_sd);
    cudaGetSymbolAddress((void**)&st,    g_st);
    cudaGetSymbolAddress((void**)&nd,    g_nd);
    cudaGetSymbolAddress((void**)&nt,    g_nt);
    cudaGetSymbolAddress((void**)&ntraw, g_ntraw);
    cudaGetSymbolAddress((void**)&part,  g_part);
    cudaGetSymbolAddress((void**)&selidx, g_selidx);
    cudaGetSymbolAddress((void**)&selval, g_selval);

    rowsum_rsqrt<<<D_NUM, 256>>>(Dm, D_NUM, D_NUM, sd);
    rowsum_rsqrt<<<T_NUM, 256>>>(Tm, T_NUM, T_NUM, st);

    const float* hd = H_d;
    const float* ht = H_t;
    int F = FEAT;

    for (int lvl = 0; lvl < 2; lvl++) {
        prescale2<<<dim3((F / 4 + 255) / 256, D_NUM, 2), 256>>>(
            bsd, hd, sd, D_NUM, bst, ht, st, T_NUM, F / 4);
        // split-K(4) Dn/Tn
        {
            GemmP pD = mk(Dm, bsd, pa, D_NUM, F, D_NUM, D_NUM, F, F, nullptr);
            GemmP pT = mk(Tm, bst, pb, T_NUM, F, T_NUM, T_NUM, F, F, nullptr);
            mma_gemm_f<0, true, false, 4><<<grid2(pD, pT, 4), GTHREADS>>>(pD, pT);
            reduce2<4, 4><<<red_grid(pD, pT), 256>>>(
                catd + 2 * F, 3 * F, pa, sd, D_NUM, F,
                catt + 2 * F, 3 * F, pb, st, T_NUM, F);
        }
        // projections (small K, no split)
        {
            GemmP pd = mk(hd, W1g[lvl], hdp, D_NUM, UNITS, F, F, UNITS, UNITS, nullptr);
            GemmP pt = mk(ht, W2g[lvl], htp, T_NUM, UNITS, F, F, UNITS, UNITS, nullptr);
            mma_gemm_f<3, true, true, 1><<<grid2(pd, pt, 1), GTHREADS>>>(pd, pt);
        }
        transpose_kernel<<<tr_grid(T_NUM, UNITS), dim3(32, 8)>>>(htpT, htp, T_NUM, UNITS);
        {
            GemmP ps = mk(hdp, htpT, S, D_NUM, T_NUM, UNITS, UNITS, T_NUM, T_NUM, nullptr);
            mma_gemm_f<2, false, false, 1><<<grid1(ps), GTHREADS>>>(ps, ps);
        }

        zero_vec<<<(T_NUM + 255) / 256, 256>>>(ntraw, T_NUM);
        topk_kernel<<<D_NUM, 256>>>(S, selidx, selval, nd, ntraw);

        gather_dt<<<D_NUM, 256>>>(selidx, selval, nd, ntraw, ht, F, catd + F, 3 * F);
        zero_strided<<<dim3((F + 255) / 256, T_NUM), 256>>>(catt + F, 3 * F, T_NUM, F);
        scatter_td<<<D_NUM * TOPK, 256>>>(selidx, selval, nd, ntraw, hd, F, catt + F, 3 * F);
        relu_round_strided<<<dim3((F + 255) / 256, T_NUM), 256>>>(catt + F, 3 * F, T_NUM, F);
        copy_round2<<<dim3((F + 255) / 256, D_NUM, 2), 256>>>(
            catd, 3 * F, hd, F, D_NUM, catt, 3 * F, ht, F, T_NUM, F);

        // split-K(2) concat dense (K = 768)
        {
            GemmP pd = mk(catd, Wd[lvl], pa, D_NUM, UNITS, 3 * F, 3 * F, UNITS, UNITS, nullptr);
            GemmP pt = mk(catt, Wt[lvl], pb, T_NUM, UNITS, 3 * F, 3 * F, UNITS, UNITS, nullptr);
            mma_gemm_f<0, false, true, 2><<<grid2(pd, pt, 2), GTHREADS>>>(pd, pt);
            reduce2<1, 2><<<red_grid(pd, pt), 256>>>(
                hdb, UNITS, pa, nullptr, D_NUM, UNITS,
                htb, UNITS, pb, nullptr, T_NUM, UNITS);
        }
        hd = hdb; ht = htb; F = UNITS;
    }

    // ---- output CGC on original (dense) R ----
    rowsum_rsqrt<<<D_NUM, 256>>>(R, D_NUM, T_NUM, nd);
    colsum_partial<<<dim3((T_NUM + 255) / 256, NCHUNK), 256>>>(R, D_NUM, T_NUM, part);
    colsum_finish<<<(T_NUM + 255) / 256, 256>>>(part, T_NUM, nt);
    transpose_kernel<<<tr_grid(D_NUM, T_NUM), dim3(32, 8)>>>(RT, R, D_NUM, T_NUM);

    prescale2<<<dim3((F / 4 + 255) / 256, D_NUM, 2), 256>>>(
        bsd, ht, nt, T_NUM, bst, hd, nd, D_NUM, F / 4);
    prescale2<<<dim3((F / 4 + 255) / 256, D_NUM, 2), 256>>>(
        bsd2, hd, sd, D_NUM, bst2, ht, st, T_NUM, F / 4);

    // split-K(4) R-pair
    {
        GemmP pra = mk(R,  bsd, pa, D_NUM, F, T_NUM, T_NUM, F, F, nullptr);
        GemmP prb = mk(RT, bst, pb, T_NUM, F, D_NUM, D_NUM, F, F, nullptr);
        mma_gemm_f<0, true, false, 4><<<grid2(pra, prb, 4), GTHREADS>>>(pra, prb);
        reduce2<4, 4><<<red_grid(pra, prb), 256>>>(
            catd + F, 3 * F, pa, nd, D_NUM, F,
            catt + F, 3 * F, pb, nt, T_NUM, F);
    }
    // split-K(4) Dn/Tn pair
    {
        GemmP pD = mk(Dm, bsd2, pa, D_NUM, F, D_NUM, D_NUM, F, F, nullptr);
        GemmP pT = mk(Tm, bst2, pb, T_NUM, F, T_NUM, T_NUM, F, F, nullptr);
        mma_gemm_f<0, true, false, 4><<<grid2(pD, pT, 4), GTHREADS>>>(pD, pT);
        reduce2<4, 4><<<red_grid(pD, pT), 256>>>(
            catd + 2 * F, 3 * F, pa, sd, D_NUM, F,
            catt + 2 * F, 3 * F, pb, st, T_NUM, F);
    }

    copy_round2<<<dim3((F + 255) / 256, D_NUM, 2), 256>>>(
        catd, 3 * F, hd, F, D_NUM, catt, 3 * F, ht, F, T_NUM, F);

    // split-K(2) output dense (K = 600)
    {
        GemmP pd = mk(catd, WdO, pa, D_NUM, UNITS, 3 * F, 3 * F, UNITS, UNITS, nullptr);
        GemmP pt = mk(catt, WtO, pb, T_NUM, UNITS, 3 * F, 3 * F, UNITS, UNITS, nullptr);
        mma_gemm_f<0, false, true, 2><<<grid2(pd, pt, 2), GTHREADS>>>(pd, pt);
        reduce2<4, 2><<<red_grid(pd, pt), 256>>>(
            hdp, UNITS, pa, nullptr, D_NUM, UNITS,
            htp, UNITS, pb, nullptr, T_NUM, UNITS);
    }

    // R_pred = sigmoid(hd_out @ ht_out^T)
    transpose_kernel<<<tr_grid(T_NUM, UNITS), dim3(32, 8)>>>(htpT, htp, T_NUM, UNITS);
    {
        GemmP ps = mk(hdp, htpT, out, D_NUM, T_NUM, UNITS, UNITS, T_NUM, T_NUM, nullptr);
        mma_gemm_f<2, false, false, 1><<<grid1(ps), GTHREADS>>>(ps, ps);
    }
}

// round 11
// speedup vs baseline: 1.0707x; 1.0707x over previous
#include <cuda_runtime.h>
#include <math.h>
#include <stdint.h>

#define D_NUM 4000
#define T_NUM 2000
#define FEAT  256
#define UNITS 200
#define TOPK  10
#define NCHUNK 16

// ---------------- scratch ----------------
__device__ float g_S[(size_t)D_NUM * T_NUM];
__device__ float g_RT[(size_t)T_NUM * D_NUM];
__device__ float g_catd[(size_t)D_NUM * 3 * FEAT];
__device__ float g_catt[(size_t)T_NUM * 3 * FEAT];
__device__ float g_hd[(size_t)D_NUM * FEAT];
__device__ float g_ht[(size_t)T_NUM * FEAT];
__device__ float g_hdp[(size_t)D_NUM * UNITS];
__device__ float g_htp[(size_t)T_NUM * UNITS];
__device__ float g_htpT[(size_t)UNITS * T_NUM];
__device__ float g_bsd[(size_t)D_NUM * FEAT];
__device__ float g_bst[(size_t)D_NUM * FEAT];
__device__ float g_bsd2[(size_t)D_NUM * FEAT];
__device__ float g_bst2[(size_t)D_NUM * FEAT];
__device__ float g_pa[(size_t)4 * D_NUM * FEAT];
__device__ float g_pb[(size_t)4 * D_NUM * FEAT];
__device__ float g_sd[D_NUM];
__device__ float g_st[T_NUM];
__device__ float g_nd[D_NUM];
__device__ float g_nt[T_NUM];
__device__ float g_ntraw[T_NUM];
__device__ float g_part[NCHUNK * T_NUM];
__device__ int   g_selidx[D_NUM * TOPK];
__device__ float g_selval[D_NUM * TOPK];

__device__ __forceinline__ uint32_t f2tf(float x) {
    uint32_t r;
    asm("cvt.rna.tf32.f32 %0, %1;" : "=r"(r) : "f"(x));
    return r;
}
__device__ __forceinline__ float roundtf(float x) {
    return __uint_as_float(f2tf(x));
}

// ---------------- reductions ----------------
__global__ void rowsum_rsqrt(const float* __restrict__ A, int rows, int cols,
                             float* __restrict__ out) {
    int row = blockIdx.x;
    if (row >= rows) return;
    const float* a = A + (size_t)row * cols;
    float s = 0.f;
    for (int j = threadIdx.x; j < cols; j += blockDim.x) s += a[j];
    __shared__ float red[256];
    red[threadIdx.x] = s;
    __syncthreads();
    for (int off = 128; off > 0; off >>= 1) {
        if (threadIdx.x < off) red[threadIdx.x] += red[threadIdx.x + off];
        __syncthreads();
    }
    if (threadIdx.x == 0) {
        float n = red[0];
        if (n == 0.f) n = 1.f;
        out[row] = rsqrtf(n);
    }
}

__global__ void colsum_partial(const float* __restrict__ A, int rows, int cols,
                               float* __restrict__ part) {
    int j = blockIdx.x * blockDim.x + threadIdx.x;
    if (j >= cols) return;
    int chunk = (rows + NCHUNK - 1) / NCHUNK;
    int r0 = blockIdx.y * chunk;
    int r1 = r0 + chunk; if (r1 > rows) r1 = rows;
    float s = 0.f;
    for (int i = r0; i < r1; i++) s += A[(size_t)i * cols + j];
    part[blockIdx.y * cols + j] = s;
}

__global__ void colsum_finish(const float* __restrict__ part, int cols,
                              float* __restrict__ out) {
    int j = blockIdx.x * blockDim.x + threadIdx.x;
    if (j >= cols) return;
    float s = 0.f;
    for (int c = 0; c < NCHUNK; c++) s += part[c * cols + j];
    if (s == 0.f) s = 1.f;
    out[j] = rsqrtf(s);
}

// ---------------- prep kernels ----------------
__global__ void prescale2(float* dst0, const float* src0, const float* sc0, int rows0,
                          float* dst1, const float* src1, const float* sc1, int rows1,
                          int cols4) {
    int c4 = blockIdx.x * blockDim.x + threadIdx.x;
    int r = blockIdx.y;
    float* dst = blockIdx.z ? dst1 : dst0;
    const float* src = blockIdx.z ? src1 : src0;
    const float* sc = blockIdx.z ? sc1 : sc0;
    int rows = blockIdx.z ? rows1 : rows0;
    if (c4 >= cols4 || r >= rows) return;
    float s = sc[r];
    float4 v = reinterpret_cast<const float4*>(src + (size_t)r * cols4 * 4)[c4];
    v.x = roundtf(v.x * s); v.y = roundtf(v.y * s);
    v.z = roundtf(v.z * s); v.w = roundtf(v.w * s);
    reinterpret_cast<float4*>(dst + (size_t)r * cols4 * 4)[c4] = v;
}

__global__ void transpose_kernel(float* __restrict__ dst, const float* __restrict__ src,
                                 int rows, int cols) {
    __shared__ float t[32][33];
    int bx = blockIdx.x * 32, by = blockIdx.y * 32;
    int x = bx + threadIdx.x;
    #pragma unroll
    for (int i = 0; i < 32; i += 8) {
        int y = by + threadIdx.y + i;
        if (x < cols && y < rows) t[threadIdx.y + i][threadIdx.x] = src[(size_t)y * cols + x];
    }
    __syncthreads();
    int x2 = by + threadIdx.x;
    #pragma unroll
    for (int i = 0; i < 32; i += 8) {
        int y2 = bx + threadIdx.y + i;
        if (x2 < rows && y2 < cols) dst[(size_t)y2 * rows + x2] = t[threadIdx.x][threadIdx.y + i];
    }
}

__global__ void zero_vec(float* __restrict__ p, int n) {
    int i = blockIdx.x * blockDim.x + threadIdx.x;
    if (i < n) p[i] = 0.f;
}

__global__ void zero_strided(float* __restrict__ dst, int ld, int rows, int cols) {
    int c = blockIdx.x * blockDim.x + threadIdx.x;
    int r = blockIdx.y;
    if (c < cols && r < rows) dst[(size_t)r * ld + c] = 0.f;
}

__global__ void relu_round_strided(float* __restrict__ dst, int ld, int rows, int cols) {
    int c = blockIdx.x * blockDim.x + threadIdx.x;
    int r = blockIdx.y;
    if (c < cols && r < rows) {
        size_t o = (size_t)r * ld + c;
        dst[o] = roundtf(fmaxf(dst[o], 0.f));
    }
}

__global__ void copy_round2(float* dst0, int ldd0, const float* src0, int lds0, int rows0,
                            float* dst1, int ldd1, const float* src1, int lds1, int rows1,
                            int cols) {
    int c = blockIdx.x * blockDim.x + threadIdx.x;
    int r = blockIdx.y;
    float* dst = blockIdx.z ? dst1 : dst0;
    const float* src = blockIdx.z ? src1 : src0;
    int ldd = blockIdx.z ? ldd1 : ldd0;
    int lds = blockIdx.z ? lds1 : lds0;
    int rows = blockIdx.z ? rows1 : rows0;
    if (c < cols && r < rows)
        dst[(size_t)r * ldd + c] = roundtf(src[(size_t)r * lds + c]);
}

// split-K reduce + epilogue, z-fused pair, NS slabs.
template <int EPI, int NS>
__global__ void reduce2(float* out0, int ld0, const float* part0, const float* rs0, int M0, int N0,
                        float* out1, int ld1, const float* part1, const float* rs1, int M1, int N1) {
    int c = blockIdx.x * blockDim.x + threadIdx.x;
    int r = blockIdx.y;
    float* out = blockIdx.z ? out1 : out0;
    const float* part = blockIdx.z ? part1 : part0;
    const float* rs = blockIdx.z ? rs1 : rs0;
    int M = blockIdx.z ? M1 : M0;
    int N = blockIdx.z ? N1 : N0;
    int ld = blockIdx.z ? ld1 : ld0;
    if (r >= M || c >= N) return;
    size_t o = (size_t)r * N + c;
    size_t slab = (size_t)M * N;
    float v = 0.f;
    #pragma unroll
    for (int s = 0; s < NS; s++) v += part[s * slab + o];
    if (rs) v *= rs[r];
    if (EPI == 1 || EPI == 4) v = fmaxf(v, 0.f);
    if (EPI >= 3) v = roundtf(v);
    out[(size_t)r * ld + c] = v;
}

// ---------------- top-k ----------------
__global__ void topk_kernel(const float* __restrict__ S,
                            int* __restrict__ selidx, float* __restrict__ selval,
                            float* __restrict__ nd_out, float* __restrict__ ntraw) {
    int row = blockIdx.x;
    int tid = threadIdx.x;
    int lane = tid & 31, wid = tid >> 5;
    const float* srow = S + (size_t)row * T_NUM;

    float v[8];
    #pragma unroll
    for (int i = 0; i < 8; i++) {
        int j = tid + i * 256;
        v[i] = (j < T_NUM) ? srow[j] : -3.f;
    }

    __shared__ float wv[8];
    __shared__ int   wi[8];
    __shared__ int   bidx_s;
    __shared__ int   sel[TOPK];
    __shared__ float selv[TOPK];

    for (int it = 0; it < TOPK; it++) {
        float best = v[0]; int bi = tid;
        #pragma unroll
        for (int i = 1; i < 8; i++) {
            int j = tid + i * 256;
            if (v[i] > best) { best = v[i]; bi = j; }
        }
        #pragma unroll
        for (int off = 16; off > 0; off >>= 1) {
            float ov = __shfl_xor_sync(0xffffffffu, best, off);
            int   oi = __shfl_xor_sync(0xffffffffu, bi, off);
            if (ov > best || (ov == best && oi < bi)) { best = ov; bi = oi; }
        }
        if (lane == 0) { wv[wid] = best; wi[wid] = bi; }
        __syncthreads();
        if (tid == 0) {
            float b = wv[0]; int x = wi[0];
            #pragma unroll
            for (int w = 1; w < 8; w++)
                if (wv[w] > b || (wv[w] == b && wi[w] < x)) { b = wv[w]; x = wi[w]; }
            bidx_s = x; sel[it] = x; selv[it] = b;
        }
        __syncthreads();
        int x = bidx_s;
        if ((x & 255) == tid) v[x >> 8] = -3.f;
    }

    if (tid < TOPK) {
        selidx[row * TOPK + tid] = sel[tid];
        selval[row * TOPK + tid] = selv[tid];
        atomicAdd(&ntraw[sel[tid]], selv[tid]);
    }
    if (tid == 0) {
        float s = 0.f;
        #pragma unroll
        for (int t = 0; t < TOPK; t++) s += selv[t];
        if (s == 0.f) s = 1.f;
        nd_out[row] = rsqrtf(s);
    }
}

// ---------------- sparse CGC ----------------
__global__ void gather_dt(const int* __restrict__ selidx, const float* __restrict__ selval,
                          const float* __restrict__ nd, const float* __restrict__ ntraw,
                          const float* __restrict__ ht, int F,
                          float* __restrict__ outd, int ldo) {
    int d = blockIdx.x;
    __shared__ int   ci[TOPK];
    __shared__ float cw[TOPK];
    if (threadIdx.x < TOPK) {
        int c = selidx[d * TOPK + threadIdx.x];
        float s = ntraw[c];
        if (s == 0.f) s = 1.f;
        ci[threadIdx.x] = c;
        cw[threadIdx.x] = selval[d * TOPK + threadIdx.x] * rsqrtf(s);
    }
    __syncthreads();
    float ndv = nd[d];
    for (int f = threadIdx.x; f < F; f += blockDim.x) {
        float s = 0.f;
        #pragma unroll
        for (int j = 0; j < TOPK; j++) s += cw[j] * ht[(size_t)ci[j] * F + f];
        outd[(size_t)d * ldo + f] = roundtf(fmaxf(s * ndv, 0.f));
    }
}

__global__ void scatter_td(const int* __restrict__ selidx, const float* __restrict__ selval,
                           const float* __restrict__ nd, const float* __restrict__ ntraw,
                           const float* __restrict__ hd, int F,
                           float* __restrict__ outt, int ldo) {
    int e = blockIdx.x;
    int d = e / TOPK;
    int t = selidx[e];
    float s = ntraw[t];
    if (s == 0.f) s = 1.f;
    float w = selval[e] * nd[d] * rsqrtf(s);
    const float* src = hd + (size_t)d * F;
    float* dst = outt + (size_t)t * ldo;
    for (int f = threadIdx.x; f < F; f += blockDim.x)
        atomicAdd(&dst[f], w * src[f]);
}

// ---------------- common GEMM bits ----------------
struct GemmP {
    const float* A;
    const float* B;
    float* C;
    int M, N, K, lda, ldb, ldc;
    const float* rowscale;
};

__device__ __forceinline__ void mma_tf32(float c[4], uint32_t a0, uint32_t a1,
                                         uint32_t a2, uint32_t a3,
                                         uint32_t b0, uint32_t b1) {
    asm volatile(
        "mma.sync.aligned.m16n8k8.row.col.f32.tf32.tf32.f32 "
        "{%0,%1,%2,%3}, {%4,%5,%6,%7}, {%8,%9}, {%0,%1,%2,%3};"
        : "+f"(c[0]), "+f"(c[1]), "+f"(c[2]), "+f"(c[3])
        : "r"(a0), "r"(a1), "r"(a2), "r"(a3), "r"(b0), "r"(b1));
}

__device__ __forceinline__ uint32_t cvt_bits(uint32_t raw) {
    return f2tf(__uint_as_float(raw));
}

__device__ __forceinline__ void cp_async16(uint32_t dst_smem, const void* src, bool pred) {
    int sz = pred ? 16 : 0;
    asm volatile("cp.async.cg.shared.global [%0], [%1], 16, %2;"
                 :: "r"(dst_smem), "l"(src), "r"(sz));
}
#define CP_COMMIT() asm volatile("cp.async.commit_group;")
#define CP_WAIT1()  asm volatile("cp.async.wait_group 1;")

#define GBK 16
#define NSTAGE 3
#define GTHREADS 128
#define ASTR (GBK + 4)
#define GBN 64
#define BSTR (GBN + 8)

// ============ 64x64 tile kernel (R9 winner, small/medium launches) ============
#define GBM64 64

template <int EPI, bool ACVT, bool BCVT, int NS>
__global__ __launch_bounds__(GTHREADS)
void mma_gemm_f(GemmP p0, GemmP p1) {
    int prob = blockIdx.z / NS;
    int split = blockIdx.z % NS;
    const GemmP p = prob ? p1 : p0;
    int bm = blockIdx.y * GBM64;
    int bn = blockIdx.x * GBN;
    if (bm >= p.M || bn >= p.N) return;

    __shared__ uint32_t As[NSTAGE][GBM64][ASTR];
    __shared__ uint32_t Bs[NSTAGE][GBK][BSTR];

    int tid = threadIdx.x;
    int lane = tid & 31;
    int warp = tid >> 5;
    int gid = lane >> 2, tig = lane & 3;
    int mw = (warp & 1) * 32;
    int nw = (warp >> 1) * 32;

    uint32_t sa = (uint32_t)__cvta_generic_to_shared(&As[0][0][0]);
    uint32_t sb = (uint32_t)__cvta_generic_to_shared(&Bs[0][0][0]);

    float acc[2][4][4];
    #pragma unroll
    for (int i = 0; i < 2; i++)
        #pragma unroll
        for (int j = 0; j < 4; j++)
            #pragma unroll
            for (int l = 0; l < 4; l++) acc[i][j][l] = 0.f;

    int nkt_total = (p.K + GBK - 1) / GBK;
    int chunk = (nkt_total + NS - 1) / NS;
    int kt_begin = split * chunk;
    int kt_end = min(nkt_total, kt_begin + chunk);
    int niter = kt_end - kt_begin;
    if (niter < 0) niter = 0;

    int a_m0 = tid >> 1;
    int a_kq = (tid & 1) * 8;
    int b_kb = tid >> 3;
    int b_nq = (tid & 7) * 8;

    auto issue_tile = [&](int kt, int st) {
        int k0 = kt * GBK;
        {
            int gm = bm + a_m0;
            const float* src = p.A + (size_t)gm * p.lda + k0 + a_kq;
            uint32_t dst = sa + (((st * GBM64 + a_m0) * ASTR) + a_kq) * 4;
            bool rowok = (gm < p.M);
            cp_async16(dst,      src,     rowok && (k0 + a_kq     < p.K));
            cp_async16(dst + 16, src + 4, rowok && (k0 + a_kq + 4 < p.K));
        }
        {
            int gk = k0 + b_kb;
            const float* src = p.B + (size_t)gk * p.ldb + bn + b_nq;
            uint32_t dst = sb + (((st * GBK + b_kb) * BSTR) + b_nq) * 4;
            bool kok = (gk < p.K);
            cp_async16(dst,      src,     kok && (bn + b_nq     < p.N));
            cp_async16(dst + 16, src + 4, kok && (bn + b_nq + 4 < p.N));
        }
    };

    #pragma unroll
    for (int s = 0; s < NSTAGE - 1; s++) {
        if (s < niter) issue_tile(kt_begin + s, s);
        CP_COMMIT();
    }

    int cur = 0;
    for (int it = 0; it < niter; it++) {
        CP_WAIT1();
        __syncthreads();

        #pragma unroll
        for (int kk = 0; kk < GBK; kk += 8) {
            uint32_t b0[4], b1[4];
            #pragma unroll
            for (int nt = 0; nt < 4; nt++) {
                b0[nt] = Bs[cur][kk + tig][nw + nt * 8 + gid];
                b1[nt] = Bs[cur][kk + tig + 4][nw + nt * 8 + gid];
                if (BCVT) { b0[nt] = cvt_bits(b0[nt]); b1[nt] = cvt_bits(b1[nt]); }
            }
            #pragma unroll
            for (int mt = 0; mt < 2; mt++) {
                int mb = mw + mt * 16;
                uint32_t a0 = As[cur][mb + gid][kk + tig];
                uint32_t a1 = As[cur][mb + gid + 8][kk + tig];
                uint32_t a2 = As[cur][mb + gid][kk + tig + 4];
                uint32_t a3 = As[cur][mb + gid + 8][kk + tig + 4];
                if (ACVT) {
                    a0 = cvt_bits(a0); a1 = cvt_bits(a1);
                    a2 = cvt_bits(a2); a3 = cvt_bits(a3);
                }
                #pragma unroll
                for (int nt = 0; nt < 4; nt++)
                    mma_tf32(acc[mt][nt], a0, a1, a2, a3, b0[nt], b1[nt]);
            }
        }

        if (it + NSTAGE - 1 < niter) {
            int st = (cur + NSTAGE - 1) % NSTAGE;
            issue_tile(kt_begin + it + NSTAGE - 1, st);
        }
        CP_COMMIT();
        cur = (cur + 1) % NSTAGE;
    }

    if (NS > 1) {
        float* dst = p.C + (size_t)split * p.M * p.N;
        #pragma unroll
        for (int mt = 0; mt < 2; mt++) {
            int gm0 = bm + mw + mt * 16 + gid;
            int gm1 = gm0 + 8;
            #pragma unroll
            for (int nt = 0; nt < 4; nt++) {
                int gn0 = bn + nw + nt * 8 + 2 * tig;
                int gn1 = gn0 + 1;
                #pragma unroll
                for (int q = 0; q < 4; q++) {
                    int gm = (q < 2) ? gm0 : gm1;
                    int gn = (q & 1) ? gn1 : gn0;
                    if (gm >= p.M || gn >= p.N) continue;
                    dst[(size_t)gm * p.N + gn] = acc[mt][nt][q];
                }
            }
        }
        return;
    }

    #pragma unroll
    for (int mt = 0; mt < 2; mt++) {
        int gm0 = bm + mw + mt * 16 + gid;
        int gm1 = gm0 + 8;
        float rs0 = 1.f, rs1 = 1.f;
        if (p.rowscale) {
            if (gm0 < p.M) rs0 = p.rowscale[gm0];
            if (gm1 < p.M) rs1 = p.rowscale[gm1];
        }
        #pragma unroll
        for (int nt = 0; nt < 4; nt++) {
            int gn0 = bn + nw + nt * 8 + 2 * tig;
            int gn1 = gn0 + 1;
            #pragma unroll
            for (int q = 0; q < 4; q++) {
                int gm = (q < 2) ? gm0 : gm1;
                int gn = (q & 1) ? gn1 : gn0;
                if (gm >= p.M || gn >= p.N) continue;
                float v = acc[mt][nt][q] * ((q < 2) ? rs0 : rs1);
                if (EPI == 1 || EPI == 4) v = fmaxf(v, 0.f);
                else if (EPI == 2) v = 1.f / (1.f + __expf(-v));
                if (EPI >= 3) v = roundtf(v);
                p.C[(size_t)gm * p.ldc + gn] = v;
            }
        }
    }
}

// ============ 128x64 tile kernel (big split-K pairs only) ============
#define GBM128 128

template <int EPI, bool ACVT, bool BCVT, int NS>
__global__ __launch_bounds__(GTHREADS)
void mma_gemm_b(GemmP p0, GemmP p1) {
    int prob = blockIdx.z / NS;
    int split = blockIdx.z % NS;
    const GemmP p = prob ? p1 : p0;
    int bm = blockIdx.y * GBM128;
    int bn = blockIdx.x * GBN;
    if (bm >= p.M || bn >= p.N) return;

    __shared__ uint32_t As[NSTAGE][GBM128][ASTR];
    __shared__ uint32_t Bs[NSTAGE][GBK][BSTR];

    int tid = threadIdx.x;
    int lane = tid & 31;
    int warp = tid >> 5;
    int gid = lane >> 2, tig = lane & 3;
    int mw = (warp & 1) * 64;
    int nw = (warp >> 1) * 32;

    uint32_t sa = (uint32_t)__cvta_generic_to_shared(&As[0][0][0]);
    uint32_t sb = (uint32_t)__cvta_generic_to_shared(&Bs[0][0][0]);

    float acc[4][4][4];
    #pragma unroll
    for (int i = 0; i < 4; i++)
        #pragma unroll
        for (int j = 0; j < 4; j++)
            #pragma unroll
            for (int l = 0; l < 4; l++) acc[i][j][l] = 0.f;

    int nkt_total = (p.K + GBK - 1) / GBK;
    int chunk = (nkt_total + NS - 1) / NS;
    int kt_begin = split * chunk;
    int kt_end = min(nkt_total, kt_begin + chunk);
    int niter = kt_end - kt_begin;
    if (niter < 0) niter = 0;

    int b_kb = tid >> 3;
    int b_nq = (tid & 7) * 8;

    auto issue_tile = [&](int kt, int st) {
        int k0 = kt * GBK;
        {
            int gm = bm + tid;
            const float* src = p.A + (size_t)gm * p.lda + k0;
            uint32_t dst = sa + ((st * GBM128 + tid) * ASTR) * 4;
            bool rowok = (gm < p.M);
            #pragma unroll
            for (int u = 0; u < 4; u++)
                cp_async16(dst + u * 16, src + u * 4, rowok && (k0 + u * 4 < p.K));
        }
        {
            int gk = k0 + b_kb;
            const float* src = p.B + (size_t)gk * p.ldb + bn + b_nq;
            uint32_t dst = sb + (((st * GBK + b_kb) * BSTR) + b_nq) * 4;
            bool kok = (gk < p.K);
            cp_async16(dst,      src,     kok && (bn + b_nq     < p.N));
            cp_async16(dst + 16, src + 4, kok && (bn + b_nq + 4 < p.N));
        }
    };

    #pragma unroll
    for (int s = 0; s < NSTAGE - 1; s++) {
        if (s < niter) issue_tile(kt_begin + s, s);
        CP_COMMIT();
    }

    int cur = 0;
    for (int it = 0; it < niter; it++) {
        CP_WAIT1();
        __syncthreads();

        #pragma unroll
        for (int kk = 0; kk < GBK; kk += 8) {
            uint32_t b0[4], b1[4];
            #pragma unroll
            for (int nt = 0; nt < 4; nt++) {
                b0[nt] = Bs[cur][kk + tig][nw + nt * 8 + gid];
                b1[nt] = Bs[cur][kk + tig + 4][nw + nt * 8 + gid];
                if (BCVT) { b0[nt] = cvt_bits(b0[nt]); b1[nt] = cvt_bits(b1[nt]); }
            }
            #pragma unroll
            for (int mt = 0; mt < 4; mt++) {
                int mb = mw + mt * 16;
                uint32_t a0 = As[cur][mb + gid][kk + tig];
                uint32_t a1 = As[cur][mb + gid + 8][kk + tig];
                uint32_t a2 = As[cur][mb + gid][kk + tig + 4];
                uint32_t a3 = As[cur][mb + gid + 8][kk + tig + 4];
                if (ACVT) {
                    a0 = cvt_bits(a0); a1 = cvt_bits(a1);
                    a2 = cvt_bits(a2); a3 = cvt_bits(a3);
                }
                #pragma unroll
                for (int nt = 0; nt < 4; nt++)
                    mma_tf32(acc[mt][nt], a0, a1, a2, a3, b0[nt], b1[nt]);
            }
        }

        if (it + NSTAGE - 1 < niter) {
            int st = (cur + NSTAGE - 1) % NSTAGE;
            issue_tile(kt_begin + it + NSTAGE - 1, st);
        }
        CP_COMMIT();
        cur = (cur + 1) % NSTAGE;
    }

    float* dst = p.C + (size_t)split * p.M * p.N;
    #pragma unroll
    for (int mt = 0; mt < 4; mt++) {
        int gm0 = bm + mw + mt * 16 + gid;
        int gm1 = gm0 + 8;
        #pragma unroll
        for (int nt = 0; nt < 4; nt++) {
            int gn0 = bn + nw + nt * 8 + 2 * tig;
            int gn1 = gn0 + 1;
            #pragma unroll
            for (int q = 0; q < 4; q++) {
                int gm = (q < 2) ? gm0 : gm1;
                int gn = (q & 1) ? gn1 : gn0;
                if (gm >= p.M || gn >= p.N) continue;
                dst[(size_t)gm * p.N + gn] = acc[mt][nt][q];
            }
        }
    }
}

static inline GemmP mk(const float* A, const float* B, float* C,
                       int M, int N, int K, int lda, int ldb, int ldc,
                       const float* rs) {
    GemmP p; p.A = A; p.B = B; p.C = C; p.M = M; p.N = N; p.K = K;
    p.lda = lda; p.ldb = ldb; p.ldc = ldc; p.rowscale = rs; return p;
}
static inline dim3 grid1_64(const GemmP& p) {
    return dim3((p.N + GBN - 1) / GBN, (p.M + GBM64 - 1) / GBM64, 1);
}
static inline dim3 grid2_64(const GemmP& a, const GemmP& b, int ns) {
    int gx = max((a.N + GBN - 1) / GBN, (b.N + GBN - 1) / GBN);
    int gy = max((a.M + GBM64 - 1) / GBM64, (b.M + GBM64 - 1) / GBM64);
    return dim3(gx, gy, 2 * ns);
}
static inline dim3 grid2_128(const GemmP& a, const GemmP& b, int ns) {
    int gx = max((a.N + GBN - 1) / GBN, (b.N + GBN - 1) / GBN);
    int gy = max((a.M + GBM128 - 1) / GBM128, (b.M + GBM128 - 1) / GBM128);
    return dim3(gx, gy, 2 * ns);
}
static inline dim3 tr_grid(int rows, int cols) {
    return dim3((cols + 31) / 32, (rows + 31) / 32);
}
static inline dim3 red_grid(const GemmP& a, const GemmP& b) {
    int n = max(a.N, b.N);
    int m = max(a.M, b.M);
    return dim3((n + 255) / 256, m, 2);
}

// ---------------- host orchestration ----------------
extern "C" void kernel_launch(void* const* d_in, const int* in_sizes, int n_in,
                              void* d_out, int out_size) {
    const float* R    = (const float*)d_in[0];
    const float* Dm   = (const float*)d_in[1];
    const float* Tm   = (const float*)d_in[2];
    const float* H_d  = (const float*)d_in[3];
    const float* H_t  = (const float*)d_in[4];
    const float* W1g[2] = {(const float*)d_in[5], (const float*)d_in[7]};
    const float* W2g[2] = {(const float*)d_in[6], (const float*)d_in[8]};
    const float* Wd[2]  = {(const float*)d_in[9], (const float*)d_in[11]};
    const float* Wt[2]  = {(const float*)d_in[10], (const float*)d_in[12]};
    const float* WdO  = (const float*)d_in[13];
    const float* WtO  = (const float*)d_in[14];
    float* out = (float*)d_out;

    float *S, *RT, *catd, *catt, *hdb, *htb, *hdp, *htp, *htpT;
    float *bsd, *bst, *bsd2, *bst2, *pa, *pb;
    float *sd, *st, *nd, *nt, *ntraw, *part, *selval;
    int* selidx;
    cudaGetSymbolAddress((void**)&S,     g_S);
    cudaGetSymbolAddress((void**)&RT,    g_RT);
    cudaGetSymbolAddress((void**)&catd,  g_catd);
    cudaGetSymbolAddress((void**)&catt,  g_catt);
    cudaGetSymbolAddress((void**)&hdb,   g_hd);
    cudaGetSymbolAddress((void**)&htb,   g_ht);
    cudaGetSymbolAddress((void**)&hdp,   g_hdp);
    cudaGetSymbolAddress((void**)&htp,   g_htp);
    cudaGetSymbolAddress((void**)&htpT,  g_htpT);
    cudaGetSymbolAddress((void**)&bsd,   g_bsd);
    cudaGetSymbolAddress((void**)&bst,   g_bst);
    cudaGetSymbolAddress((void**)&bsd2,  g_bsd2);
    cudaGetSymbolAddress((void**)&bst2,  g_bst2);
    cudaGetSymbolAddress((void**)&pa,    g_pa);
    cudaGetSymbolAddress((void**)&pb,    g_pb);
    cudaGetSymbolAddress((void**)&sd,    g_sd);
    cudaGetSymbolAddress((void**)&st,    g_st);
    cudaGetSymbolAddress((void**)&nd,    g_nd);
    cudaGetSymbolAddress((void**)&nt,    g_nt);
    cudaGetSymbolAddress((void**)&ntraw, g_ntraw);
    cudaGetSymbolAddress((void**)&part,  g_part);
    cudaGetSymbolAddress((void**)&selidx, g_selidx);
    cudaGetSymbolAddress((void**)&selval, g_selval);

    rowsum_rsqrt<<<D_NUM, 256>>>(Dm, D_NUM, D_NUM, sd);
    rowsum_rsqrt<<<T_NUM, 256>>>(Tm, T_NUM, T_NUM, st);

    const float* hd = H_d;
    const float* ht = H_t;
    int F = FEAT;

    for (int lvl = 0; lvl < 2; lvl++) {
        prescale2<<<dim3((F / 4 + 255) / 256, D_NUM, 2), 256>>>(
            bsd, hd, sd, D_NUM, bst, ht, st, T_NUM, F / 4);
        // split-K(4) Dn/Tn — big-tile kernel
        {
            GemmP pD = mk(Dm, bsd, pa, D_NUM, F, D_NUM, D_NUM, F, F, nullptr);
            GemmP pT = mk(Tm, bst, pb, T_NUM, F, T_NUM, T_NUM, F, F, nullptr);
            mma_gemm_b<0, true, false, 4><<<grid2_128(pD, pT, 4), GTHREADS>>>(pD, pT);
            reduce2<4, 4><<<red_grid(pD, pT), 256>>>(
                catd + 2 * F, 3 * F, pa, sd, D_NUM, F,
                catt + 2 * F, 3 * F, pb, st, T_NUM, F);
        }
        // projections (small K, 64-tile)
        {
            GemmP pd = mk(hd, W1g[lvl], hdp, D_NUM, UNITS, F, F, UNITS, UNITS, nullptr);
            GemmP pt = mk(ht, W2g[lvl], htp, T_NUM, UNITS, F, F, UNITS, UNITS, nullptr);
            mma_gemm_f<3, true, true, 1><<<grid2_64(pd, pt, 1), GTHREADS>>>(pd, pt);
        }
        transpose_kernel<<<tr_grid(T_NUM, UNITS), dim3(32, 8)>>>(htpT, htp, T_NUM, UNITS);
        {
            GemmP ps = mk(hdp, htpT, S, D_NUM, T_NUM, UNITS, UNITS, T_NUM, T_NUM, nullptr);
            mma_gemm_f<2, false, false, 1><<<grid1_64(ps), GTHREADS>>>(ps, ps);
        }

        zero_vec<<<(T_NUM + 255) / 256, 256>>>(ntraw, T_NUM);
        topk_kernel<<<D_NUM, 256>>>(S, selidx, selval, nd, ntraw);

        gather_dt<<<D_NUM, 256>>>(selidx, selval, nd, ntraw, ht, F, catd + F, 3 * F);
        zero_strided<<<dim3((F + 255) / 256, T_NUM), 256>>>(catt + F, 3 * F, T_NUM, F);
        scatter_td<<<D_NUM * TOPK, 256>>>(selidx, selval, nd, ntraw, hd, F, catt + F, 3 * F);
        relu_round_strided<<<dim3((F + 255) / 256, T_NUM), 256>>>(catt + F, 3 * F, T_NUM, F);
        copy_round2<<<dim3((F + 255) / 256, D_NUM, 2), 256>>>(
            catd, 3 * F, hd, F, D_NUM, catt, 3 * F, ht, F, T_NUM, F);

        // split-K(2) concat dense (K = 768, 64-tile)
        {
            GemmP pd = mk(catd, Wd[lvl], pa, D_NUM, UNITS, 3 * F, 3 * F, UNITS, UNITS, nullptr);
            GemmP pt = mk(catt, Wt[lvl], pb, T_NUM, UNITS, 3 * F, 3 * F, UNITS, UNITS, nullptr);
            mma_gemm_f<0, false, true, 2><<<grid2_64(pd, pt, 2), GTHREADS>>>(pd, pt);
            reduce2<1, 2><<<red_grid(pd, pt), 256>>>(
                hdb, UNITS, pa, nullptr, D_NUM, UNITS,
                htb, UNITS, pb, nullptr, T_NUM, UNITS);
        }
        hd = hdb; ht = htb; F = UNITS;
    }

    // ---- output CGC on original (dense) R ----
    rowsum_rsqrt<<<D_NUM, 256>>>(R, D_NUM, T_NUM, nd);
    colsum_partial<<<dim3((T_NUM + 255) / 256, NCHUNK), 256>>>(R, D_NUM, T_NUM, part);
    colsum_finish<<<(T_NUM + 255) / 256, 256>>>(part, T_NUM, nt);
    transpose_kernel<<<tr_grid(D_NUM, T_NUM), dim3(32, 8)>>>(RT, R, D_NUM, T_NUM);

    prescale2<<<dim3((F / 4 + 255) / 256, D_NUM, 2), 256>>>(
        bsd, ht, nt, T_NUM, bst, hd, nd, D_NUM, F / 4);
    prescale2<<<dim3((F / 4 + 255) / 256, D_NUM, 2), 256>>>(
        bsd2, hd, sd, D_NUM, bst2, ht, st, T_NUM, F / 4);

    // split-K(4) R-pair — big-tile
    {
        GemmP pra = mk(R,  bsd, pa, D_NUM, F, T_NUM, T_NUM, F, F, nullptr);
        GemmP prb = mk(RT, bst, pb, T_NUM, F, D_NUM, D_NUM, F, F, nullptr);
        mma_gemm_b<0, true, false, 4><<<grid2_128(pra, prb, 4), GTHREADS>>>(pra, prb);
        reduce2<4, 4><<<red_grid(pra, prb), 256>>>(
            catd + F, 3 * F, pa, nd, D_NUM, F,
            catt + F, 3 * F, pb, nt, T_NUM, F);
    }
    // split-K(4) Dn/Tn pair — big-tile
    {
        GemmP pD = mk(Dm, bsd2, pa, D_NUM, F, D_NUM, D_NUM, F, F, nullptr);
        GemmP pT = mk(Tm, bst2, pb, T_NUM, F, T_NUM, T_NUM, F, F, nullptr);
        mma_gemm_b<0, true, false, 4><<<grid2_128(pD, pT, 4), GTHREADS>>>(pD, pT);
        reduce2<4, 4><<<red_grid(pD, pT), 256>>>(
            catd + 2 * F, 3 * F, pa, sd, D_NUM, F,
            catt + 2 * F, 3 * F, pb, st, T_NUM, F);
    }

    copy_round2<<<dim3((F + 255) / 256, D_NUM, 2), 256>>>(
        catd, 3 * F, hd, F, D_NUM, catt, 3 * F, ht, F, T_NUM, F);

    // split-K(2) output dense (K = 600, 64-tile)
    {
        GemmP pd = mk(catd, WdO, pa, D_NUM, UNITS, 3 * F, 3 * F, UNITS, UNITS, nullptr);
        GemmP pt = mk(catt, WtO, pb, T_NUM, UNITS, 3 * F, 3 * F, UNITS, UNITS, nullptr);
        mma_gemm_f<0, false, true, 2><<<grid2_64(pd, pt, 2), GTHREADS>>>(pd, pt);
        reduce2<4, 2><<<red_grid(pd, pt), 256>>>(
            hdp, UNITS, pa, nullptr, D_NUM, UNITS,
            htp, UNITS, pb, nullptr, T_NUM, UNITS);
    }

    // R_pred = sigmoid(hd_out @ ht_out^T)
    transpose_kernel<<<tr_grid(T_NUM, UNITS), dim3(32, 8)>>>(htpT, htp, T_NUM, UNITS);
    {
        GemmP ps = mk(hdp, htpT, out, D_NUM, T_NUM, UNITS, UNITS, T_NUM, T_NUM, nullptr);
        mma_gemm_f<2, false, false, 1><<<grid1_64(ps), GTHREADS>>>(ps, ps);
    }
}

// round 12
// speedup vs baseline: 1.1710x; 1.0938x over previous
#include <cuda_runtime.h>
#include <math.h>
#include <stdint.h>

#define D_NUM 4000
#define T_NUM 2000
#define FEAT  256
#define UNITS 200
#define TOPK  10
#define NCHUNK 16

// ---------------- scratch ----------------
__device__ float g_S[(size_t)D_NUM * T_NUM];
__device__ float g_RT[(size_t)T_NUM * D_NUM];
__device__ float g_catd[(size_t)D_NUM * 3 * FEAT];
__device__ float g_catt[(size_t)T_NUM * 3 * FEAT];
__device__ float g_hd[(size_t)D_NUM * FEAT];
__device__ float g_ht[(size_t)T_NUM * FEAT];
__device__ float g_hdp[(size_t)D_NUM * UNITS];
__device__ float g_htp[(size_t)T_NUM * UNITS];
__device__ float g_htpT[(size_t)UNITS * T_NUM];
__device__ float g_bsd[(size_t)D_NUM * FEAT];
__device__ float g_bst[(size_t)D_NUM * FEAT];
__device__ float g_bsd2[(size_t)D_NUM * FEAT];
__device__ float g_bst2[(size_t)D_NUM * FEAT];
__device__ float g_pa[(size_t)8 * D_NUM * FEAT];   // split-K partials, problem 0
__device__ float g_pb[(size_t)8 * D_NUM * FEAT];   // split-K partials, problem 1
__device__ float g_sd[D_NUM];
__device__ float g_st[T_NUM];
__device__ float g_nd[D_NUM];
__device__ float g_nt[T_NUM];
__device__ float g_ntraw[T_NUM];
__device__ float g_part[NCHUNK * T_NUM];
__device__ int   g_selidx[D_NUM * TOPK];
__device__ float g_selval[D_NUM * TOPK];

__device__ __forceinline__ uint32_t f2tf(float x) {
    uint32_t r;
    asm("cvt.rna.tf32.f32 %0, %1;" : "=r"(r) : "f"(x));
    return r;
}
__device__ __forceinline__ float roundtf(float x) {
    return __uint_as_float(f2tf(x));
}

// ---------------- reductions ----------------
__global__ void rowsum_rsqrt(const float* __restrict__ A, int rows, int cols,
                             float* __restrict__ out) {
    int row = blockIdx.x;
    if (row >= rows) return;
    const float* a = A + (size_t)row * cols;
    float s = 0.f;
    for (int j = threadIdx.x; j < cols; j += blockDim.x) s += a[j];
    __shared__ float red[256];
    red[threadIdx.x] = s;
    __syncthreads();
    for (int off = 128; off > 0; off >>= 1) {
        if (threadIdx.x < off) red[threadIdx.x] += red[threadIdx.x + off];
        __syncthreads();
    }
    if (threadIdx.x == 0) {
        float n = red[0];
        if (n == 0.f) n = 1.f;
        out[row] = rsqrtf(n);
    }
}

__global__ void colsum_partial(const float* __restrict__ A, int rows, int cols,
                               float* __restrict__ part) {
    int j = blockIdx.x * blockDim.x + threadIdx.x;
    if (j >= cols) return;
    int chunk = (rows + NCHUNK - 1) / NCHUNK;
    int r0 = blockIdx.y * chunk;
    int r1 = r0 + chunk; if (r1 > rows) r1 = rows;
    float s = 0.f;
    for (int i = r0; i < r1; i++) s += A[(size_t)i * cols + j];
    part[blockIdx.y * cols + j] = s;
}

__global__ void colsum_finish(const float* __restrict__ part, int cols,
                              float* __restrict__ out) {
    int j = blockIdx.x * blockDim.x + threadIdx.x;
    if (j >= cols) return;
    float s = 0.f;
    for (int c = 0; c < NCHUNK; c++) s += part[c * cols + j];
    if (s == 0.f) s = 1.f;
    out[j] = rsqrtf(s);
}

// ---------------- prep kernels ----------------
__global__ void prescale2(float* dst0, const float* src0, const float* sc0, int rows0,
                          float* dst1, const float* src1, const float* sc1, int rows1,
                          int cols4) {
    int c4 = blockIdx.x * blockDim.x + threadIdx.x;
    int r = blockIdx.y;
    float* dst = blockIdx.z ? dst1 : dst0;
    const float* src = blockIdx.z ? src1 : src0;
    const float* sc = blockIdx.z ? sc1 : sc0;
    int rows = blockIdx.z ? rows1 : rows0;
    if (c4 >= cols4 || r >= rows) return;
    float s = sc[r];
    float4 v = reinterpret_cast<const float4*>(src + (size_t)r * cols4 * 4)[c4];
    v.x = roundtf(v.x * s); v.y = roundtf(v.y * s);
    v.z = roundtf(v.z * s); v.w = roundtf(v.w * s);
    reinterpret_cast<float4*>(dst + (size_t)r * cols4 * 4)[c4] = v;
}

__global__ void transpose_kernel(float* __restrict__ dst, const float* __restrict__ src,
                                 int rows, int cols) {
    __shared__ float t[32][33];
    int bx = blockIdx.x * 32, by = blockIdx.y * 32;
    int x = bx + threadIdx.x;
    #pragma unroll
    for (int i = 0; i < 32; i += 8) {
        int y = by + threadIdx.y + i;
        if (x < cols && y < rows) t[threadIdx.y + i][threadIdx.x] = src[(size_t)y * cols + x];
    }
    __syncthreads();
    int x2 = by + threadIdx.x;
    #pragma unroll
    for (int i = 0; i < 32; i += 8) {
        int y2 = bx + threadIdx.y + i;
        if (x2 < rows && y2 < cols) dst[(size_t)y2 * rows + x2] = t[threadIdx.x][threadIdx.y + i];
    }
}

__global__ void zero_vec(float* __restrict__ p, int n) {
    int i = blockIdx.x * blockDim.x + threadIdx.x;
    if (i < n) p[i] = 0.f;
}

__global__ void zero_strided(float* __restrict__ dst, int ld, int rows, int cols) {
    int c = blockIdx.x * blockDim.x + threadIdx.x;
    int r = blockIdx.y;
    if (c < cols && r < rows) dst[(size_t)r * ld + c] = 0.f;
}

__global__ void relu_round_strided(float* __restrict__ dst, int ld, int rows, int cols) {
    int c = blockIdx.x * blockDim.x + threadIdx.x;
    int r = blockIdx.y;
    if (c < cols && r < rows) {
        size_t o = (size_t)r * ld + c;
        dst[o] = roundtf(fmaxf(dst[o], 0.f));
    }
}

__global__ void copy_round2(float* dst0, int ldd0, const float* src0, int lds0, int rows0,
                            float* dst1, int ldd1, const float* src1, int lds1, int rows1,
                            int cols) {
    int c = blockIdx.x * blockDim.x + threadIdx.x;
    int r = blockIdx.y;
    float* dst = blockIdx.z ? dst1 : dst0;
    const float* src = blockIdx.z ? src1 : src0;
    int ldd = blockIdx.z ? ldd1 : ldd0;
    int lds = blockIdx.z ? lds1 : lds0;
    int rows = blockIdx.z ? rows1 : rows0;
    if (c < cols && r < rows)
        dst[(size_t)r * ldd + c] = roundtf(src[(size_t)r * lds + c]);
}

// split-K reduce + epilogue, z-fused pair, NS slabs.
template <int EPI, int NS>
__global__ void reduce2(float* out0, int ld0, const float* part0, const float* rs0, int M0, int N0,
                        float* out1, int ld1, const float* part1, const float* rs1, int M1, int N1) {
    int c = blockIdx.x * blockDim.x + threadIdx.x;
    int r = blockIdx.y;
    float* out = blockIdx.z ? out1 : out0;
    const float* part = blockIdx.z ? part1 : part0;
    const float* rs = blockIdx.z ? rs1 : rs0;
    int M = blockIdx.z ? M1 : M0;
    int N = blockIdx.z ? N1 : N0;
    int ld = blockIdx.z ? ld1 : ld0;
    if (r >= M || c >= N) return;
    size_t o = (size_t)r * N + c;
    size_t slab = (size_t)M * N;
    float v = 0.f;
    #pragma unroll
    for (int s = 0; s < NS; s++) v += part[s * slab + o];
    if (rs) v *= rs[r];
    if (EPI == 1 || EPI == 4) v = fmaxf(v, 0.f);
    if (EPI >= 3) v = roundtf(v);
    out[(size_t)r * ld + c] = v;
}

// ---------------- top-k ----------------
__global__ void topk_kernel(const float* __restrict__ S,
                            int* __restrict__ selidx, float* __restrict__ selval,
                            float* __restrict__ nd_out, float* __restrict__ ntraw) {
    int row = blockIdx.x;
    int tid = threadIdx.x;
    int lane = tid & 31, wid = tid >> 5;
    const float* srow = S + (size_t)row * T_NUM;

    float v[8];
    #pragma unroll
    for (int i = 0; i < 8; i++) {
        int j = tid + i * 256;
        v[i] = (j < T_NUM) ? srow[j] : -3.f;
    }

    __shared__ float wv[8];
    __shared__ int   wi[8];
    __shared__ int   bidx_s;
    __shared__ int   sel[TOPK];
    __shared__ float selv[TOPK];

    for (int it = 0; it < TOPK; it++) {
        float best = v[0]; int bi = tid;
        #pragma unroll
        for (int i = 1; i < 8; i++) {
            int j = tid + i * 256;
            if (v[i] > best) { best = v[i]; bi = j; }
        }
        #pragma unroll
        for (int off = 16; off > 0; off >>= 1) {
            float ov = __shfl_xor_sync(0xffffffffu, best, off);
            int   oi = __shfl_xor_sync(0xffffffffu, bi, off);
            if (ov > best || (ov == best && oi < bi)) { best = ov; bi = oi; }
        }
        if (lane == 0) { wv[wid] = best; wi[wid] = bi; }
        __syncthreads();
        if (tid == 0) {
            float b = wv[0]; int x = wi[0];
            #pragma unroll
            for (int w = 1; w < 8; w++)
                if (wv[w] > b || (wv[w] == b && wi[w] < x)) { b = wv[w]; x = wi[w]; }
            bidx_s = x; sel[it] = x; selv[it] = b;
        }
        __syncthreads();
        int x = bidx_s;
        if ((x & 255) == tid) v[x >> 8] = -3.f;
    }

    if (tid < TOPK) {
        selidx[row * TOPK + tid] = sel[tid];
        selval[row * TOPK + tid] = selv[tid];
        atomicAdd(&ntraw[sel[tid]], selv[tid]);
    }
    if (tid == 0) {
        float s = 0.f;
        #pragma unroll
        for (int t = 0; t < TOPK; t++) s += selv[t];
        if (s == 0.f) s = 1.f;
        nd_out[row] = rsqrtf(s);
    }
}

// ---------------- sparse CGC ----------------
__global__ void gather_dt(const int* __restrict__ selidx, const float* __restrict__ selval,
                          const float* __restrict__ nd, const float* __restrict__ ntraw,
                          const float* __restrict__ ht, int F,
                          float* __restrict__ outd, int ldo) {
    int d = blockIdx.x;
    __shared__ int   ci[TOPK];
    __shared__ float cw[TOPK];
    if (threadIdx.x < TOPK) {
        int c = selidx[d * TOPK + threadIdx.x];
        float s = ntraw[c];
        if (s == 0.f) s = 1.f;
        ci[threadIdx.x] = c;
        cw[threadIdx.x] = selval[d * TOPK + threadIdx.x] * rsqrtf(s);
    }
    __syncthreads();
    float ndv = nd[d];
    for (int f = threadIdx.x; f < F; f += blockDim.x) {
        float s = 0.f;
        #pragma unroll
        for (int j = 0; j < TOPK; j++) s += cw[j] * ht[(size_t)ci[j] * F + f];
        outd[(size_t)d * ldo + f] = roundtf(fmaxf(s * ndv, 0.f));
    }
}

__global__ void scatter_td(const int* __restrict__ selidx, const float* __restrict__ selval,
                           const float* __restrict__ nd, const float* __restrict__ ntraw,
                           const float* __restrict__ hd, int F,
                           float* __restrict__ outt, int ldo) {
    int e = blockIdx.x;
    int d = e / TOPK;
    int t = selidx[e];
    float s = ntraw[t];
    if (s == 0.f) s = 1.f;
    float w = selval[e] * nd[d] * rsqrtf(s);
    const float* src = hd + (size_t)d * F;
    float* dst = outt + (size_t)t * ldo;
    for (int f = threadIdx.x; f < F; f += blockDim.x)
        atomicAdd(&dst[f], w * src[f]);
}

// ---------------- TF32 GEMM: 64x64 tile, cp.async pipeline, split-K NS ----------
struct GemmP {
    const float* A;
    const float* B;
    float* C;            // output, or split-K partial base (ld = N, NS slabs)
    int M, N, K, lda, ldb, ldc;
    const float* rowscale;
};

__device__ __forceinline__ void mma_tf32(float c[4], uint32_t a0, uint32_t a1,
                                         uint32_t a2, uint32_t a3,
                                         uint32_t b0, uint32_t b1) {
    asm volatile(
        "mma.sync.aligned.m16n8k8.row.col.f32.tf32.tf32.f32 "
        "{%0,%1,%2,%3}, {%4,%5,%6,%7}, {%8,%9}, {%0,%1,%2,%3};"
        : "+f"(c[0]), "+f"(c[1]), "+f"(c[2]), "+f"(c[3])
        : "r"(a0), "r"(a1), "r"(a2), "r"(a3), "r"(b0), "r"(b1));
}

__device__ __forceinline__ uint32_t cvt_bits(uint32_t raw) {
    return f2tf(__uint_as_float(raw));
}

__device__ __forceinline__ void cp_async16(uint32_t dst_smem, const void* src, bool pred) {
    int sz = pred ? 16 : 0;
    asm volatile("cp.async.cg.shared.global [%0], [%1], 16, %2;"
                 :: "r"(dst_smem), "l"(src), "r"(sz));
}
#define CP_COMMIT() asm volatile("cp.async.commit_group;")
#define CP_WAIT1()  asm volatile("cp.async.wait_group 1;")

#define GBM 64
#define GBN 64
#define GBK 16
#define NSTAGE 3
#define GTHREADS 128
#define ASTR (GBK + 4)
#define BSTR (GBN + 8)

template <int EPI, bool ACVT, bool BCVT, int NS>
__global__ __launch_bounds__(GTHREADS)
void mma_gemm_f(GemmP p0, GemmP p1) {
    int prob = blockIdx.z / NS;
    int split = blockIdx.z % NS;
    const GemmP p = prob ? p1 : p0;
    int bm = blockIdx.y * GBM;
    int bn = blockIdx.x * GBN;
    if (bm >= p.M || bn >= p.N) return;

    __shared__ uint32_t As[NSTAGE][GBM][ASTR];
    __shared__ uint32_t Bs[NSTAGE][GBK][BSTR];

    int tid = threadIdx.x;
    int lane = tid & 31;
    int warp = tid >> 5;
    int gid = lane >> 2, tig = lane & 3;
    int mw = (warp & 1) * 32;
    int nw = (warp >> 1) * 32;

    uint32_t sa = (uint32_t)__cvta_generic_to_shared(&As[0][0][0]);
    uint32_t sb = (uint32_t)__cvta_generic_to_shared(&Bs[0][0][0]);

    float acc[2][4][4];
    #pragma unroll
    for (int i = 0; i < 2; i++)
        #pragma unroll
        for (int j = 0; j < 4; j++)
            #pragma unroll
            for (int l = 0; l < 4; l++) acc[i][j][l] = 0.f;

    int nkt_total = (p.K + GBK - 1) / GBK;
    int chunk = (nkt_total + NS - 1) / NS;
    int kt_begin = split * chunk;
    int kt_end = min(nkt_total, kt_begin + chunk);
    int niter = kt_end - kt_begin;
    if (niter < 0) niter = 0;

    int a_m0 = tid >> 1;
    int a_kq = (tid & 1) * 8;
    int b_kb = tid >> 3;
    int b_nq = (tid & 7) * 8;

    auto issue_tile = [&](int kt, int st) {
        int k0 = kt * GBK;
        {
            int gm = bm + a_m0;
            const float* src = p.A + (size_t)gm * p.lda + k0 + a_kq;
            uint32_t dst = sa + (((st * GBM + a_m0) * ASTR) + a_kq) * 4;
            bool rowok = (gm < p.M);
            cp_async16(dst,      src,     rowok && (k0 + a_kq     < p.K));
            cp_async16(dst + 16, src + 4, rowok && (k0 + a_kq + 4 < p.K));
        }
        {
            int gk = k0 + b_kb;
            const float* src = p.B + (size_t)gk * p.ldb + bn + b_nq;
            uint32_t dst = sb + (((st * GBK + b_kb) * BSTR) + b_nq) * 4;
            bool kok = (gk < p.K);
            cp_async16(dst,      src,     kok && (bn + b_nq     < p.N));
            cp_async16(dst + 16, src + 4, kok && (bn + b_nq + 4 < p.N));
        }
    };

    #pragma unroll
    for (int s = 0; s < NSTAGE - 1; s++) {
        if (s < niter) issue_tile(kt_begin + s, s);
        CP_COMMIT();
    }

    int cur = 0;
    for (int it = 0; it < niter; it++) {
        CP_WAIT1();
        __syncthreads();

        #pragma unroll
        for (int kk = 0; kk < GBK; kk += 8) {
            uint32_t b0[4], b1[4];
            #pragma unroll
            for (int nt = 0; nt < 4; nt++) {
                b0[nt] = Bs[cur][kk + tig][nw + nt * 8 + gid];
                b1[nt] = Bs[cur][kk + tig + 4][nw + nt * 8 + gid];
                if (BCVT) { b0[nt] = cvt_bits(b0[nt]); b1[nt] = cvt_bits(b1[nt]); }
            }
            #pragma unroll
            for (int mt = 0; mt < 2; mt++) {
                int mb = mw + mt * 16;
                uint32_t a0 = As[cur][mb + gid][kk + tig];
                uint32_t a1 = As[cur][mb + gid + 8][kk + tig];
                uint32_t a2 = As[cur][mb + gid][kk + tig + 4];
                uint32_t a3 = As[cur][mb + gid + 8][kk + tig + 4];
                if (ACVT) {
                    a0 = cvt_bits(a0); a1 = cvt_bits(a1);
                    a2 = cvt_bits(a2); a3 = cvt_bits(a3);
                }
                #pragma unroll
                for (int nt = 0; nt < 4; nt++)
                    mma_tf32(acc[mt][nt], a0, a1, a2, a3, b0[nt], b1[nt]);
            }
        }

        if (it + NSTAGE - 1 < niter) {
            int st = (cur + NSTAGE - 1) % NSTAGE;
            issue_tile(kt_begin + it + NSTAGE - 1, st);
        }
        CP_COMMIT();
        cur = (cur + 1) % NSTAGE;
    }

    if (NS > 1) {
        float* dst = p.C + (size_t)split * p.M * p.N;
        #pragma unroll
        for (int mt = 0; mt < 2; mt++) {
            int gm0 = bm + mw + mt * 16 + gid;
            int gm1 = gm0 + 8;
            #pragma unroll
            for (int nt = 0; nt < 4; nt++) {
                int gn0 = bn + nw + nt * 8 + 2 * tig;
                int gn1 = gn0 + 1;
                #pragma unroll
                for (int q = 0; q < 4; q++) {
                    int gm = (q < 2) ? gm0 : gm1;
                    int gn = (q & 1) ? gn1 : gn0;
                    if (gm >= p.M || gn >= p.N) continue;
                    dst[(size_t)gm * p.N + gn] = acc[mt][nt][q];
                }
            }
        }
        return;
    }

    #pragma unroll
    for (int mt = 0; mt < 2; mt++) {
        int gm0 = bm + mw + mt * 16 + gid;
        int gm1 = gm0 + 8;
        float rs0 = 1.f, rs1 = 1.f;
        if (p.rowscale) {
            if (gm0 < p.M) rs0 = p.rowscale[gm0];
            if (gm1 < p.M) rs1 = p.rowscale[gm1];
        }
        #pragma unroll
        for (int nt = 0; nt < 4; nt++) {
            int gn0 = bn + nw + nt * 8 + 2 * tig;
            int gn1 = gn0 + 1;
            #pragma unroll
            for (int q = 0; q < 4; q++) {
                int gm = (q < 2) ? gm0 : gm1;
                int gn = (q & 1) ? gn1 : gn0;
                if (gm >= p.M || gn >= p.N) continue;
                float v = acc[mt][nt][q] * ((q < 2) ? rs0 : rs1);
                if (EPI == 1 || EPI == 4) v = fmaxf(v, 0.f);
                else if (EPI == 2) v = 1.f / (1.f + __expf(-v));
                if (EPI >= 3) v = roundtf(v);
                p.C[(size_t)gm * p.ldc + gn] = v;
            }
        }
    }
}

static inline GemmP mk(const float* A, const float* B, float* C,
                       int M, int N, int K, int lda, int ldb, int ldc,
                       const float* rs) {
    GemmP p; p.A = A; p.B = B; p.C = C; p.M = M; p.N = N; p.K = K;
    p.lda = lda; p.ldb = ldb; p.ldc = ldc; p.rowscale = rs; return p;
}
static inline dim3 grid1(const GemmP& p) {
    return dim3((p.N + GBN - 1) / GBN, (p.M + GBM - 1) / GBM, 1);
}
static inline dim3 grid2(const GemmP& a, const GemmP& b, int ns) {
    int gx = max((a.N + GBN - 1) / GBN, (b.N + GBN - 1) / GBN);
    int gy = max((a.M + GBM - 1) / GBM, (b.M + GBM - 1) / GBM);
    return dim3(gx, gy, 2 * ns);
}
static inline dim3 tr_grid(int rows, int cols) {
    return dim3((cols + 31) / 32, (rows + 31) / 32);
}
static inline dim3 red_grid(const GemmP& a, const GemmP& b) {
    int n = max(a.N, b.N);
    int m = max(a.M, b.M);
    return dim3((n + 255) / 256, m, 2);
}

// ---------------- host orchestration ----------------
extern "C" void kernel_launch(void* const* d_in, const int* in_sizes, int n_in,
                              void* d_out, int out_size) {
    const float* R    = (const float*)d_in[0];
    const float* Dm   = (const float*)d_in[1];
    const float* Tm   = (const float*)d_in[2];
    const float* H_d  = (const float*)d_in[3];
    const float* H_t  = (const float*)d_in[4];
    const float* W1g[2] = {(const float*)d_in[5], (const float*)d_in[7]};
    const float* W2g[2] = {(const float*)d_in[6], (const float*)d_in[8]};
    const float* Wd[2]  = {(const float*)d_in[9], (const float*)d_in[11]};
    const float* Wt[2]  = {(const float*)d_in[10], (const float*)d_in[12]};
    const float* WdO  = (const float*)d_in[13];
    const float* WtO  = (const float*)d_in[14];
    float* out = (float*)d_out;

    float *S, *RT, *catd, *catt, *hdb, *htb, *hdp, *htp, *htpT;
    float *bsd, *bst, *bsd2, *bst2, *pa, *pb;
    float *sd, *st, *nd, *nt, *ntraw, *part, *selval;
    int* selidx;
    cudaGetSymbolAddress((void**)&S,     g_S);
    cudaGetSymbolAddress((void**)&RT,    g_RT);
    cudaGetSymbolAddress((void**)&catd,  g_catd);
    cudaGetSymbolAddress((void**)&catt,  g_catt);
    cudaGetSymbolAddress((void**)&hdb,   g_hd);
    cudaGetSymbolAddress((void**)&htb,   g_ht);
    cudaGetSymbolAddress((void**)&hdp,   g_hdp);
    cudaGetSymbolAddress((void**)&htp,   g_htp);
    cudaGetSymbolAddress((void**)&htpT,  g_htpT);
    cudaGetSymbolAddress((void**)&bsd,   g_bsd);
    cudaGetSymbolAddress((void**)&bst,   g_bst);
    cudaGetSymbolAddress((void**)&bsd2,  g_bsd2);
    cudaGetSymbolAddress((void**)&bst2,  g_bst2);
    cudaGetSymbolAddress((void**)&pa,    g_pa);
    cudaGetSymbolAddress((void**)&pb,    g_pb);
    cudaGetSymbolAddress((void**)&sd,    g_sd);
    cudaGetSymbolAddress((void**)&st,    g_st);
    cudaGetSymbolAddress((void**)&nd,    g_nd);
    cudaGetSymbolAddress((void**)&nt,    g_nt);
    cudaGetSymbolAddress((void**)&ntraw, g_ntraw);
    cudaGetSymbolAddress((void**)&part,  g_part);
    cudaGetSymbolAddress((void**)&selidx, g_selidx);
    cudaGetSymbolAddress((void**)&selval, g_selval);

    rowsum_rsqrt<<<D_NUM, 256>>>(Dm, D_NUM, D_NUM, sd);
    rowsum_rsqrt<<<T_NUM, 256>>>(Tm, T_NUM, T_NUM, st);

    const float* hd = H_d;
    const float* ht = H_t;
    int F = FEAT;

    for (int lvl = 0; lvl < 2; lvl++) {
        prescale2<<<dim3((F / 4 + 255) / 256, D_NUM, 2), 256>>>(
            bsd, hd, sd, D_NUM, bst, ht, st, T_NUM, F / 4);
        // split-K(8) Dn/Tn
        {
            GemmP pD = mk(Dm, bsd, pa, D_NUM, F, D_NUM, D_NUM, F, F, nullptr);
            GemmP pT = mk(Tm, bst, pb, T_NUM, F, T_NUM, T_NUM, F, F, nullptr);
            mma_gemm_f<0, true, false, 8><<<grid2(pD, pT, 8), GTHREADS>>>(pD, pT);
            reduce2<4, 8><<<red_grid(pD, pT), 256>>>(
                catd + 2 * F, 3 * F, pa, sd, D_NUM, F,
                catt + 2 * F, 3 * F, pb, st, T_NUM, F);
        }
        // projections (small K, no split)
        {
            GemmP pd = mk(hd, W1g[lvl], hdp, D_NUM, UNITS, F, F, UNITS, UNITS, nullptr);
            GemmP pt = mk(ht, W2g[lvl], htp, T_NUM, UNITS, F, F, UNITS, UNITS, nullptr);
            mma_gemm_f<3, true, true, 1><<<grid2(pd, pt, 1), GTHREADS>>>(pd, pt);
        }
        transpose_kernel<<<tr_grid(T_NUM, UNITS), dim3(32, 8)>>>(htpT, htp, T_NUM, UNITS);
        {
            GemmP ps = mk(hdp, htpT, S, D_NUM, T_NUM, UNITS, UNITS, T_NUM, T_NUM, nullptr);
            mma_gemm_f<2, false, false, 1><<<grid1(ps), GTHREADS>>>(ps, ps);
        }

        zero_vec<<<(T_NUM + 255) / 256, 256>>>(ntraw, T_NUM);
        topk_kernel<<<D_NUM, 256>>>(S, selidx, selval, nd, ntraw);

        gather_dt<<<D_NUM, 256>>>(selidx, selval, nd, ntraw, ht, F, catd + F, 3 * F);
        zero_strided<<<dim3((F + 255) / 256, T_NUM), 256>>>(catt + F, 3 * F, T_NUM, F);
        scatter_td<<<D_NUM * TOPK, 256>>>(selidx, selval, nd, ntraw, hd, F, catt + F, 3 * F);
        relu_round_strided<<<dim3((F + 255) / 256, T_NUM), 256>>>(catt + F, 3 * F, T_NUM, F);
        copy_round2<<<dim3((F + 255) / 256, D_NUM, 2), 256>>>(
            catd, 3 * F, hd, F, D_NUM, catt, 3 * F, ht, F, T_NUM, F);

        // split-K(2) concat dense (K = 768)
        {
            GemmP pd = mk(catd, Wd[lvl], pa, D_NUM, UNITS, 3 * F, 3 * F, UNITS, UNITS, nullptr);
            GemmP pt = mk(catt, Wt[lvl], pb, T_NUM, UNITS, 3 * F, 3 * F, UNITS, UNITS, nullptr);
            mma_gemm_f<0, false, true, 2><<<grid2(pd, pt, 2), GTHREADS>>>(pd, pt);
            reduce2<1, 2><<<red_grid(pd, pt), 256>>>(
                hdb, UNITS, pa, nullptr, D_NUM, UNITS,
                htb, UNITS, pb, nullptr, T_NUM, UNITS);
        }
        hd = hdb; ht = htb; F = UNITS;
    }

    // ---- output CGC on original (dense) R ----
    rowsum_rsqrt<<<D_NUM, 256>>>(R, D_NUM, T_NUM, nd);
    colsum_partial<<<dim3((T_NUM + 255) / 256, NCHUNK), 256>>>(R, D_NUM, T_NUM, part);
    colsum_finish<<<(T_NUM + 255) / 256, 256>>>(part, T_NUM, nt);
    transpose_kernel<<<tr_grid(D_NUM, T_NUM), dim3(32, 8)>>>(RT, R, D_NUM, T_NUM);

    prescale2<<<dim3((F / 4 + 255) / 256, D_NUM, 2), 256>>>(
        bsd, ht, nt, T_NUM, bst, hd, nd, D_NUM, F / 4);
    prescale2<<<dim3((F / 4 + 255) / 256, D_NUM, 2), 256>>>(
        bsd2, hd, sd, D_NUM, bst2, ht, st, T_NUM, F / 4);

    // split-K(8) R-pair
    {
        GemmP pra = mk(R,  bsd, pa, D_NUM, F, T_NUM, T_NUM, F, F, nullptr);
        GemmP prb = mk(RT, bst, pb, T_NUM, F, D_NUM, D_NUM, F, F, nullptr);
        mma_gemm_f<0, true, false, 8><<<grid2(pra, prb, 8), GTHREADS>>>(pra, prb);
        reduce2<4, 8><<<red_grid(pra, prb), 256>>>(
            catd + F, 3 * F, pa, nd, D_NUM, F,
            catt + F, 3 * F, pb, nt, T_NUM, F);
    }
    // split-K(8) Dn/Tn pair
    {
        GemmP pD = mk(Dm, bsd2, pa, D_NUM, F, D_NUM, D_NUM, F, F, nullptr);
        GemmP pT = mk(Tm, bst2, pb, T_NUM, F, T_NUM, T_NUM, F, F, nullptr);
        mma_gemm_f<0, true, false, 8><<<grid2(pD, pT, 8), GTHREADS>>>(pD, pT);
        reduce2<4, 8><<<red_grid(pD, pT), 256>>>(
            catd + 2 * F, 3 * F, pa, sd, D_NUM, F,
            catt + 2 * F, 3 * F, pb, st, T_NUM, F);
    }

    copy_round2<<<dim3((F + 255) / 256, D_NUM, 2), 256>>>(
        catd, 3 * F, hd, F, D_NUM, catt, 3 * F, ht, F, T_NUM, F);

    // split-K(2) output dense (K = 600)
    {
        GemmP pd = mk(catd, WdO, pa, D_NUM, UNITS, 3 * F, 3 * F, UNITS, UNITS, nullptr);
        GemmP pt = mk(catt, WtO, pb, T_NUM, UNITS, 3 * F, 3 * F, UNITS, UNITS, nullptr);
        mma_gemm_f<0, false, true, 2><<<grid2(pd, pt, 2), GTHREADS>>>(pd, pt);
        reduce2<4, 2><<<red_grid(pd, pt), 256>>>(
            hdp, UNITS, pa, nullptr, D_NUM, UNITS,
            htp, UNITS, pb, nullptr, T_NUM, UNITS);
    }

    // R_pred = sigmoid(hd_out @ ht_out^T)
    transpose_kernel<<<tr_grid(T_NUM, UNITS), dim3(32, 8)>>>(htpT, htp, T_NUM, UNITS);
    {
        GemmP ps = mk(hdp, htpT, out, D_NUM, T_NUM, UNITS, UNITS, T_NUM, T_NUM, nullptr);
        mma_gemm_f<2, false, false, 1><<<grid1(ps), GTHREADS>>>(ps, ps);
    }
}

// round 13
// speedup vs baseline: 1.2708x; 1.0852x over previous
#include <cuda_runtime.h>
#include <math.h>
#include <stdint.h>

#define D_NUM 4000
#define T_NUM 2000
#define FEAT  256
#define UNITS 200
#define TOPK  10
#define NCHUNK 16

// ---------------- scratch ----------------
__device__ float g_S[(size_t)D_NUM * T_NUM];
__device__ float g_RT[(size_t)T_NUM * D_NUM];
__device__ float g_catd[(size_t)D_NUM * 3 * FEAT];
__device__ float g_catt[(size_t)T_NUM * 3 * FEAT];
__device__ float g_hd[(size_t)D_NUM * FEAT];
__device__ float g_ht[(size_t)T_NUM * FEAT];
__device__ float g_hdp[(size_t)D_NUM * UNITS];
__device__ float g_htp[(size_t)T_NUM * UNITS];
__device__ float g_htpT[(size_t)UNITS * T_NUM];
__device__ float g_bsd[(size_t)D_NUM * FEAT];
__device__ float g_bst[(size_t)D_NUM * FEAT];
__device__ float g_bsd2[(size_t)D_NUM * FEAT];
__device__ float g_bst2[(size_t)D_NUM * FEAT];
__device__ float g_pa[(size_t)8 * D_NUM * FEAT];
__device__ float g_pb[(size_t)8 * D_NUM * FEAT];
__device__ float g_sd[D_NUM];
__device__ float g_st[T_NUM];
__device__ float g_nd[D_NUM];
__device__ float g_nt[T_NUM];
__device__ float g_ntraw[T_NUM];
__device__ float g_part[NCHUNK * T_NUM];
__device__ int   g_selidx[D_NUM * TOPK];
__device__ float g_selval[D_NUM * TOPK];

__device__ __forceinline__ uint32_t f2tf(float x) {
    uint32_t r;
    asm("cvt.rna.tf32.f32 %0, %1;" : "=r"(r) : "f"(x));
    return r;
}
__device__ __forceinline__ float roundtf(float x) {
    return __uint_as_float(f2tf(x));
}

// ---------------- reductions ----------------
__global__ void rowsum_rsqrt(const float* __restrict__ A, int rows, int cols,
                             float* __restrict__ out) {
    int row = blockIdx.x;
    if (row >= rows) return;
    const float* a = A + (size_t)row * cols;
    float s = 0.f;
    for (int j = threadIdx.x; j < cols; j += blockDim.x) s += a[j];
    __shared__ float red[256];
    red[threadIdx.x] = s;
    __syncthreads();
    for (int off = 128; off > 0; off >>= 1) {
        if (threadIdx.x < off) red[threadIdx.x] += red[threadIdx.x + off];
        __syncthreads();
    }
    if (threadIdx.x == 0) {
        float n = red[0];
        if (n == 0.f) n = 1.f;
        out[row] = rsqrtf(n);
    }
}

__global__ void colsum_partial(const float* __restrict__ A, int rows, int cols,
                               float* __restrict__ part) {
    int j = blockIdx.x * blockDim.x + threadIdx.x;
    if (j >= cols) return;
    int chunk = (rows + NCHUNK - 1) / NCHUNK;
    int r0 = blockIdx.y * chunk;
    int r1 = r0 + chunk; if (r1 > rows) r1 = rows;
    float s = 0.f;
    for (int i = r0; i < r1; i++) s += A[(size_t)i * cols + j];
    part[blockIdx.y * cols + j] = s;
}

__global__ void colsum_finish(const float* __restrict__ part, int cols,
                              float* __restrict__ out) {
    int j = blockIdx.x * blockDim.x + threadIdx.x;
    if (j >= cols) return;
    float s = 0.f;
    for (int c = 0; c < NCHUNK; c++) s += part[c * cols + j];
    if (s == 0.f) s = 1.f;
    out[j] = rsqrtf(s);
}

// ---------------- prep kernels ----------------
__global__ void prescale2(float* dst0, const float* src0, const float* sc0, int rows0,
                          float* dst1, const float* src1, const float* sc1, int rows1,
                          int cols4) {
    int c4 = blockIdx.x * blockDim.x + threadIdx.x;
    int r = blockIdx.y;
    float* dst = blockIdx.z ? dst1 : dst0;
    const float* src = blockIdx.z ? src1 : src0;
    const float* sc = blockIdx.z ? sc1 : sc0;
    int rows = blockIdx.z ? rows1 : rows0;
    if (c4 >= cols4 || r >= rows) return;
    float s = sc[r];
    float4 v = reinterpret_cast<const float4*>(src + (size_t)r * cols4 * 4)[c4];
    v.x = roundtf(v.x * s); v.y = roundtf(v.y * s);
    v.z = roundtf(v.z * s); v.w = roundtf(v.w * s);
    reinterpret_cast<float4*>(dst + (size_t)r * cols4 * 4)[c4] = v;
}

__global__ void transpose_kernel(float* __restrict__ dst, const float* __restrict__ src,
                                 int rows, int cols) {
    __shared__ float t[32][33];
    int bx = blockIdx.x * 32, by = blockIdx.y * 32;
    int x = bx + threadIdx.x;
    #pragma unroll
    for (int i = 0; i < 32; i += 8) {
        int y = by + threadIdx.y + i;
        if (x < cols && y < rows) t[threadIdx.y + i][threadIdx.x] = src[(size_t)y * cols + x];
    }
    __syncthreads();
    int x2 = by + threadIdx.x;
    #pragma unroll
    for (int i = 0; i < 32; i += 8) {
        int y2 = bx + threadIdx.y + i;
        if (x2 < rows && y2 < cols) dst[(size_t)y2 * rows + x2] = t[threadIdx.x][threadIdx.y + i];
    }
}

__global__ void zero_vec(float* __restrict__ p, int n) {
    int i = blockIdx.x * blockDim.x + threadIdx.x;
    if (i < n) p[i] = 0.f;
}

__global__ void zero_strided(float* __restrict__ dst, int ld, int rows, int cols) {
    int c = blockIdx.x * blockDim.x + threadIdx.x;
    int r = blockIdx.y;
    if (c < cols && r < rows) dst[(size_t)r * ld + c] = 0.f;
}

__global__ void relu_round_strided(float* __restrict__ dst, int ld, int rows, int cols) {
    int c = blockIdx.x * blockDim.x + threadIdx.x;
    int r = blockIdx.y;
    if (c < cols && r < rows) {
        size_t o = (size_t)r * ld + c;
        dst[o] = roundtf(fmaxf(dst[o], 0.f));
    }
}

__global__ void copy_round2(float* dst0, int ldd0, const float* src0, int lds0, int rows0,
                            float* dst1, int ldd1, const float* src1, int lds1, int rows1,
                            int cols) {
    int c = blockIdx.x * blockDim.x + threadIdx.x;
    int r = blockIdx.y;
    float* dst = blockIdx.z ? dst1 : dst0;
    const float* src = blockIdx.z ? src1 : src0;
    int ldd = blockIdx.z ? ldd1 : ldd0;
    int lds = blockIdx.z ? lds1 : lds0;
    int rows = blockIdx.z ? rows1 : rows0;
    if (c < cols && r < rows)
        dst[(size_t)r * ldd + c] = roundtf(src[(size_t)r * lds + c]);
}

// split-K reduce + epilogue, z-fused pair, NS slabs.
template <int EPI, int NS>
__global__ void reduce2(float* out0, int ld0, const float* part0, const float* rs0, int M0, int N0,
                        float* out1, int ld1, const float* part1, const float* rs1, int M1, int N1) {
    int c = blockIdx.x * blockDim.x + threadIdx.x;
    int r = blockIdx.y;
    float* out = blockIdx.z ? out1 : out0;
    const float* part = blockIdx.z ? part1 : part0;
    const float* rs = blockIdx.z ? rs1 : rs0;
    int M = blockIdx.z ? M1 : M0;
    int N = blockIdx.z ? N1 : N0;
    int ld = blockIdx.z ? ld1 : ld0;
    if (r >= M || c >= N) return;
    size_t o = (size_t)r * N + c;
    size_t slab = (size_t)M * N;
    float v = 0.f;
    #pragma unroll
    for (int s = 0; s < NS; s++) v += part[s * slab + o];
    if (rs) v *= rs[r];
    if (EPI == 1 || EPI == 4) v = fmaxf(v, 0.f);
    if (EPI >= 3) v = roundtf(v);
    out[(size_t)r * ld + c] = v;
}

// ---------------- top-k ----------------
__global__ void topk_kernel(const float* __restrict__ S,
                            int* __restrict__ selidx, float* __restrict__ selval,
                            float* __restrict__ nd_out, float* __restrict__ ntraw) {
    int row = blockIdx.x;
    int tid = threadIdx.x;
    int lane = tid & 31, wid = tid >> 5;
    const float* srow = S + (size_t)row * T_NUM;

    float v[8];
    #pragma unroll
    for (int i = 0; i < 8; i++) {
        int j = tid + i * 256;
        v[i] = (j < T_NUM) ? srow[j] : -3.f;
    }

    __shared__ float wv[8];
    __shared__ int   wi[8];
    __shared__ int   bidx_s;
    __shared__ int   sel[TOPK];
    __shared__ float selv[TOPK];

    for (int it = 0; it < TOPK; it++) {
        float best = v[0]; int bi = tid;
        #pragma unroll
        for (int i = 1; i < 8; i++) {
            int j = tid + i * 256;
            if (v[i] > best) { best = v[i]; bi = j; }
        }
        #pragma unroll
        for (int off = 16; off > 0; off >>= 1) {
            float ov = __shfl_xor_sync(0xffffffffu, best, off);
            int   oi = __shfl_xor_sync(0xffffffffu, bi, off);
            if (ov > best || (ov == best && oi < bi)) { best = ov; bi = oi; }
        }
        if (lane == 0) { wv[wid] = best; wi[wid] = bi; }
        __syncthreads();
        if (tid == 0) {
            float b = wv[0]; int x = wi[0];
            #pragma unroll
            for (int w = 1; w < 8; w++)
                if (wv[w] > b || (wv[w] == b && wi[w] < x)) { b = wv[w]; x = wi[w]; }
            bidx_s = x; sel[it] = x; selv[it] = b;
        }
        __syncthreads();
        int x = bidx_s;
        if ((x & 255) == tid) v[x >> 8] = -3.f;
    }

    if (tid < TOPK) {
        selidx[row * TOPK + tid] = sel[tid];
        selval[row * TOPK + tid] = selv[tid];
        atomicAdd(&ntraw[sel[tid]], selv[tid]);
    }
    if (tid == 0) {
        float s = 0.f;
        #pragma unroll
        for (int t = 0; t < TOPK; t++) s += selv[t];
        if (s == 0.f) s = 1.f;
        nd_out[row] = rsqrtf(s);
    }
}

// ---------------- sparse CGC ----------------
__global__ void gather_dt(const int* __restrict__ selidx, const float* __restrict__ selval,
                          const float* __restrict__ nd, const float* __restrict__ ntraw,
                          const float* __restrict__ ht, int F,
                          float* __restrict__ outd, int ldo) {
    int d = blockIdx.x;
    __shared__ int   ci[TOPK];
    __shared__ float cw[TOPK];
    if (threadIdx.x < TOPK) {
        int c = selidx[d * TOPK + threadIdx.x];
        float s = ntraw[c];
        if (s == 0.f) s = 1.f;
        ci[threadIdx.x] = c;
        cw[threadIdx.x] = selval[d * TOPK + threadIdx.x] * rsqrtf(s);
    }
    __syncthreads();
    float ndv = nd[d];
    for (int f = threadIdx.x; f < F; f += blockDim.x) {
        float s = 0.f;
        #pragma unroll
        for (int j = 0; j < TOPK; j++) s += cw[j] * ht[(size_t)ci[j] * F + f];
        outd[(size_t)d * ldo + f] = roundtf(fmaxf(s * ndv, 0.f));
    }
}

__global__ void scatter_td(const int* __restrict__ selidx, const float* __restrict__ selval,
                           const float* __restrict__ nd, const float* __restrict__ ntraw,
                           const float* __restrict__ hd, int F,
                           float* __restrict__ outt, int ldo) {
    int e = blockIdx.x;
    int d = e / TOPK;
    int t = selidx[e];
    float s = ntraw[t];
    if (s == 0.f) s = 1.f;
    float w = selval[e] * nd[d] * rsqrtf(s);
    const float* src = hd + (size_t)d * F;
    float* dst = outt + (size_t)t * ldo;
    for (int f = threadIdx.x; f < F; f += blockDim.x)
        atomicAdd(&dst[f], w * src[f]);
}

// ---------------- common GEMM bits ----------------
struct GemmP {
    const float* A;
    const float* B;
    float* C;
    int M, N, K, lda, ldb, ldc;
    const float* rowscale;
};

__device__ __forceinline__ void mma_tf32(float c[4], uint32_t a0, uint32_t a1,
                                         uint32_t a2, uint32_t a3,
                                         uint32_t b0, uint32_t b1) {
    asm volatile(
        "mma.sync.aligned.m16n8k8.row.col.f32.tf32.tf32.f32 "
        "{%0,%1,%2,%3}, {%4,%5,%6,%7}, {%8,%9}, {%0,%1,%2,%3};"
        : "+f"(c[0]), "+f"(c[1]), "+f"(c[2]), "+f"(c[3])
        : "r"(a0), "r"(a1), "r"(a2), "r"(a3), "r"(b0), "r"(b1));
}

__device__ __forceinline__ uint32_t cvt_bits(uint32_t raw) {
    return f2tf(__uint_as_float(raw));
}

__device__ __forceinline__ void cp_async16(uint32_t dst_smem, const void* src, bool pred) {
    int sz = pred ? 16 : 0;
    asm volatile("cp.async.cg.shared.global [%0], [%1], 16, %2;"
                 :: "r"(dst_smem), "l"(src), "r"(sz));
}
#define CP_COMMIT() asm volatile("cp.async.commit_group;")
#define CP_WAIT1()  asm volatile("cp.async.wait_group 1;")

#define GBK 16
#define NSTAGE 3
#define ASTR (GBK + 4)

// ============ 64x64 kernel, 128 threads (proven; small/medium launches) ============
#define GBM 64
#define GBN 64
#define BSTR (GBN + 8)
#define GTHREADS 128

template <int EPI, bool ACVT, bool BCVT, int NS>
__global__ __launch_bounds__(GTHREADS)
void mma_gemm_f(GemmP p0, GemmP p1) {
    int prob = blockIdx.z / NS;
    int split = blockIdx.z % NS;
    const GemmP p = prob ? p1 : p0;
    int bm = blockIdx.y * GBM;
    int bn = blockIdx.x * GBN;
    if (bm >= p.M || bn >= p.N) return;

    __shared__ uint32_t As[NSTAGE][GBM][ASTR];
    __shared__ uint32_t Bs[NSTAGE][GBK][BSTR];

    int tid = threadIdx.x;
    int lane = tid & 31;
    int warp = tid >> 5;
    int gid = lane >> 2, tig = lane & 3;
    int mw = (warp & 1) * 32;
    int nw = (warp >> 1) * 32;

    uint32_t sa = (uint32_t)__cvta_generic_to_shared(&As[0][0][0]);
    uint32_t sb = (uint32_t)__cvta_generic_to_shared(&Bs[0][0][0]);

    float acc[2][4][4];
    #pragma unroll
    for (int i = 0; i < 2; i++)
        #pragma unroll
        for (int j = 0; j < 4; j++)
            #pragma unroll
            for (int l = 0; l < 4; l++) acc[i][j][l] = 0.f;

    int nkt_total = (p.K + GBK - 1) / GBK;
    int chunk = (nkt_total + NS - 1) / NS;
    int kt_begin = split * chunk;
    int kt_end = min(nkt_total, kt_begin + chunk);
    int niter = kt_end - kt_begin;
    if (niter < 0) niter = 0;

    int a_m0 = tid >> 1;
    int a_kq = (tid & 1) * 8;
    int b_kb = tid >> 3;
    int b_nq = (tid & 7) * 8;

    auto issue_tile = [&](int kt, int st) {
        int k0 = kt * GBK;
        {
            int gm = bm + a_m0;
            const float* src = p.A + (size_t)gm * p.lda + k0 + a_kq;
            uint32_t dst = sa + (((st * GBM + a_m0) * ASTR) + a_kq) * 4;
            bool rowok = (gm < p.M);
            cp_async16(dst,      src,     rowok && (k0 + a_kq     < p.K));
            cp_async16(dst + 16, src + 4, rowok && (k0 + a_kq + 4 < p.K));
        }
        {
            int gk = k0 + b_kb;
            const float* src = p.B + (size_t)gk * p.ldb + bn + b_nq;
            uint32_t dst = sb + (((st * GBK + b_kb) * BSTR) + b_nq) * 4;
            bool kok = (gk < p.K);
            cp_async16(dst,      src,     kok && (bn + b_nq     < p.N));
            cp_async16(dst + 16, src + 4, kok && (bn + b_nq + 4 < p.N));
        }
    };

    #pragma unroll
    for (int s = 0; s < NSTAGE - 1; s++) {
        if (s < niter) issue_tile(kt_begin + s, s);
        CP_COMMIT();
    }

    int cur = 0;
    for (int it = 0; it < niter; it++) {
        CP_WAIT1();
        __syncthreads();

        #pragma unroll
        for (int kk = 0; kk < GBK; kk += 8) {
            uint32_t b0[4], b1[4];
            #pragma unroll
            for (int nt = 0; nt < 4; nt++) {
                b0[nt] = Bs[cur][kk + tig][nw + nt * 8 + gid];
                b1[nt] = Bs[cur][kk + tig + 4][nw + nt * 8 + gid];
                if (BCVT) { b0[nt] = cvt_bits(b0[nt]); b1[nt] = cvt_bits(b1[nt]); }
            }
            #pragma unroll
            for (int mt = 0; mt < 2; mt++) {
                int mb = mw + mt * 16;
                uint32_t a0 = As[cur][mb + gid][kk + tig];
                uint32_t a1 = As[cur][mb + gid + 8][kk + tig];
                uint32_t a2 = As[cur][mb + gid][kk + tig + 4];
                uint32_t a3 = As[cur][mb + gid + 8][kk + tig + 4];
                if (ACVT) {
                    a0 = cvt_bits(a0); a1 = cvt_bits(a1);
                    a2 = cvt_bits(a2); a3 = cvt_bits(a3);
                }
                #pragma unroll
                for (int nt = 0; nt < 4; nt++)
                    mma_tf32(acc[mt][nt], a0, a1, a2, a3, b0[nt], b1[nt]);
            }
        }

        if (it + NSTAGE - 1 < niter) {
            int st = (cur + NSTAGE - 1) % NSTAGE;
            issue_tile(kt_begin + it + NSTAGE - 1, st);
        }
        CP_COMMIT();
        cur = (cur + 1) % NSTAGE;
    }

    if (NS > 1) {
        float* dst = p.C + (size_t)split * p.M * p.N;
        #pragma unroll
        for (int mt = 0; mt < 2; mt++) {
            int gm0 = bm + mw + mt * 16 + gid;
            int gm1 = gm0 + 8;
            #pragma unroll
            for (int nt = 0; nt < 4; nt++) {
                int gn0 = bn + nw + nt * 8 + 2 * tig;
                int gn1 = gn0 + 1;
                #pragma unroll
                for (int q = 0; q < 4; q++) {
                    int gm = (q < 2) ? gm0 : gm1;
                    int gn = (q & 1) ? gn1 : gn0;
                    if (gm >= p.M || gn >= p.N) continue;
                    dst[(size_t)gm * p.N + gn] = acc[mt][nt][q];
                }
            }
        }
        return;
    }

    #pragma unroll
    for (int mt = 0; mt < 2; mt++) {
        int gm0 = bm + mw + mt * 16 + gid;
        int gm1 = gm0 + 8;
        float rs0 = 1.f, rs1 = 1.f;
        if (p.rowscale) {
            if (gm0 < p.M) rs0 = p.rowscale[gm0];
            if (gm1 < p.M) rs1 = p.rowscale[gm1];
        }
        #pragma unroll
        for (int nt = 0; nt < 4; nt++) {
            int gn0 = bn + nw + nt * 8 + 2 * tig;
            int gn1 = gn0 + 1;
            #pragma unroll
            for (int q = 0; q < 4; q++) {
                int gm = (q < 2) ? gm0 : gm1;
                int gn = (q & 1) ? gn1 : gn0;
                if (gm >= p.M || gn >= p.N) continue;
                float v = acc[mt][nt][q] * ((q < 2) ? rs0 : rs1);
                if (EPI == 1 || EPI == 4) v = fmaxf(v, 0.f);
                else if (EPI == 2) v = 1.f / (1.f + __expf(-v));
                if (EPI >= 3) v = roundtf(v);
                p.C[(size_t)gm * p.ldc + gn] = v;
            }
        }
    }
}

// ============ 64x128 kernel, 256 threads (wide-N; big launches) ============
#define GBNW 128
#define BSTRW (GBNW + 8)
#define GTHREADSW 256

template <int EPI, bool ACVT, bool BCVT, int NS>
__global__ __launch_bounds__(GTHREADSW)
void mma_gemm_w(GemmP p0, GemmP p1) {
    int prob = blockIdx.z / NS;
    int split = blockIdx.z % NS;
    const GemmP p = prob ? p1 : p0;
    int bm = blockIdx.y * GBM;
    int bn = blockIdx.x * GBNW;
    if (bm >= p.M || bn >= p.N) return;

    __shared__ uint32_t As[NSTAGE][GBM][ASTR];
    __shared__ uint32_t Bs[NSTAGE][GBK][BSTRW];

    int tid = threadIdx.x;
    int lane = tid & 31;
    int warp = tid >> 5;                  // 0..7
    int gid = lane >> 2, tig = lane & 3;
    int mw = (warp & 1) * 32;             // 2 warps in M
    int nw = (warp >> 1) * 32;            // 4 warps in N

    uint32_t sa = (uint32_t)__cvta_generic_to_shared(&As[0][0][0]);
    uint32_t sb = (uint32_t)__cvta_generic_to_shared(&Bs[0][0][0]);

    float acc[2][4][4];
    #pragma unroll
    for (int i = 0; i < 2; i++)
        #pragma unroll
        for (int j = 0; j < 4; j++)
            #pragma unroll
            for (int l = 0; l < 4; l++) acc[i][j][l] = 0.f;

    int nkt_total = (p.K + GBK - 1) / GBK;
    int chunk = (nkt_total + NS - 1) / NS;
    int kt_begin = split * chunk;
    int kt_end = min(nkt_total, kt_begin + chunk);
    int niter = kt_end - kt_begin;
    if (niter < 0) niter = 0;

    // A: 64 rows x 16k = 256 16B-chunks / 256 thr = 1 chunk each.
    int a_m0 = tid >> 2;
    int a_kq = (tid & 3) * 4;
    // B: 16 rows x 128 n = 512 chunks / 256 thr = 2 chunks each (8 floats).
    int b_kb = tid >> 4;
    int b_nq = (tid & 15) * 8;

    auto issue_tile = [&](int kt, int st) {
        int k0 = kt * GBK;
        {
            int gm = bm + a_m0;
            const float* src = p.A + (size_t)gm * p.lda + k0 + a_kq;
            uint32_t dst = sa + (((st * GBM + a_m0) * ASTR) + a_kq) * 4;
            cp_async16(dst, src, (gm < p.M) && (k0 + a_kq < p.K));
        }
        {
            int gk = k0 + b_kb;
            const float* src = p.B + (size_t)gk * p.ldb + bn + b_nq;
            uint32_t dst = sb + (((st * GBK + b_kb) * BSTRW) + b_nq) * 4;
            bool kok = (gk < p.K);
            cp_async16(dst,      src,     kok && (bn + b_nq     < p.N));
            cp_async16(dst + 16, src + 4, kok && (bn + b_nq + 4 < p.N));
        }
    };

    #pragma unroll
    for (int s = 0; s < NSTAGE - 1; s++) {
        if (s < niter) issue_tile(kt_begin + s, s);
        CP_COMMIT();
    }

    int cur = 0;
    for (int it = 0; it < niter; it++) {
        CP_WAIT1();
        __syncthreads();

        #pragma unroll
        for (int kk = 0; kk < GBK; kk += 8) {
            uint32_t b0[4], b1[4];
            #pragma unroll
            for (int nt = 0; nt < 4; nt++) {
                b0[nt] = Bs[cur][kk + tig][nw + nt * 8 + gid];
                b1[nt] = Bs[cur][kk + tig + 4][nw + nt * 8 + gid];
                if (BCVT) { b0[nt] = cvt_bits(b0[nt]); b1[nt] = cvt_bits(b1[nt]); }
            }
            #pragma unroll
            for (int mt = 0; mt < 2; mt++) {
                int mb = mw + mt * 16;
                uint32_t a0 = As[cur][mb + gid][kk + tig];
                uint32_t a1 = As[cur][mb + gid + 8][kk + tig];
                uint32_t a2 = As[cur][mb + gid][kk + tig + 4];
                uint32_t a3 = As[cur][mb + gid + 8][kk + tig + 4];
                if (ACVT) {
                    a0 = cvt_bits(a0); a1 = cvt_bits(a1);
                    a2 = cvt_bits(a2); a3 = cvt_bits(a3);
                }
                #pragma unroll
                for (int nt = 0; nt < 4; nt++)
                    mma_tf32(acc[mt][nt], a0, a1, a2, a3, b0[nt], b1[nt]);
            }
        }

        if (it + NSTAGE - 1 < niter) {
            int st = (cur + NSTAGE - 1) % NSTAGE;
            issue_tile(kt_begin + it + NSTAGE - 1, st);
        }
        CP_COMMIT();
        cur = (cur + 1) % NSTAGE;
    }

    if (NS > 1) {
        float* dst = p.C + (size_t)split * p.M * p.N;
        #pragma unroll
        for (int mt = 0; mt < 2; mt++) {
            int gm0 = bm + mw + mt * 16 + gid;
            int gm1 = gm0 + 8;
            #pragma unroll
            for (int nt = 0; nt < 4; nt++) {
                int gn0 = bn + nw + nt * 8 + 2 * tig;
                int gn1 = gn0 + 1;
                #pragma unroll
                for (int q = 0; q < 4; q++) {
                    int gm = (q < 2) ? gm0 : gm1;
                    int gn = (q & 1) ? gn1 : gn0;
                    if (gm >= p.M || gn >= p.N) continue;
                    dst[(size_t)gm * p.N + gn] = acc[mt][nt][q];
                }
            }
        }
        return;
    }

    #pragma unroll
    for (int mt = 0; mt < 2; mt++) {
        int gm0 = bm + mw + mt * 16 + gid;
        int gm1 = gm0 + 8;
        float rs0 = 1.f, rs1 = 1.f;
        if (p.rowscale) {
            if (gm0 < p.M) rs0 = p.rowscale[gm0];
            if (gm1 < p.M) rs1 = p.rowscale[gm1];
        }
        #pragma unroll
        for (int nt = 0; nt < 4; nt++) {
            int gn0 = bn + nw + nt * 8 + 2 * tig;
            int gn1 = gn0 + 1;
            #pragma unroll
            for (int q = 0; q < 4; q++) {
                int gm = (q < 2) ? gm0 : gm1;
                int gn = (q & 1) ? gn1 : gn0;
                if (gm >= p.M || gn >= p.N) continue;
                float v = acc[mt][nt][q] * ((q < 2) ? rs0 : rs1);
                if (EPI == 1 || EPI == 4) v = fmaxf(v, 0.f);
                else if (EPI == 2) v = 1.f / (1.f + __expf(-v));
                if (EPI >= 3) v = roundtf(v);
                p.C[(size_t)gm * p.ldc + gn] = v;
            }
        }
    }
}

static inline GemmP mk(const float* A, const float* B, float* C,
                       int M, int N, int K, int lda, int ldb, int ldc,
                       const float* rs) {
    GemmP p; p.A = A; p.B = B; p.C = C; p.M = M; p.N = N; p.K = K;
    p.lda = lda; p.ldb = ldb; p.ldc = ldc; p.rowscale = rs; return p;
}
static inline dim3 grid2_f(const GemmP& a, const GemmP& b, int ns) {
    int gx = max((a.N + GBN - 1) / GBN, (b.N + GBN - 1) / GBN);
    int gy = max((a.M + GBM - 1) / GBM, (b.M + GBM - 1) / GBM);
    return dim3(gx, gy, 2 * ns);
}
static inline dim3 grid1_w(const GemmP& p) {
    return dim3((p.N + GBNW - 1) / GBNW, (p.M + GBM - 1) / GBM, 1);
}
static inline dim3 grid2_w(const GemmP& a, const GemmP& b, int ns) {
    int gx = max((a.N + GBNW - 1) / GBNW, (b.N + GBNW - 1) / GBNW);
    int gy = max((a.M + GBM - 1) / GBM, (b.M + GBM - 1) / GBM);
    return dim3(gx, gy, 2 * ns);
}
static inline dim3 tr_grid(int rows, int cols) {
    return dim3((cols + 31) / 32, (rows + 31) / 32);
}
static inline dim3 red_grid(const GemmP& a, const GemmP& b) {
    int n = max(a.N, b.N);
    int m = max(a.M, b.M);
    return dim3((n + 255) / 256, m, 2);
}

// ---------------- host orchestration ----------------
extern "C" void kernel_launch(void* const* d_in, const int* in_sizes, int n_in,
                              void* d_out, int out_size) {
    const float* R    = (const float*)d_in[0];
    const float* Dm   = (const float*)d_in[1];
    const float* Tm   = (const float*)d_in[2];
    const float* H_d  = (const float*)d_in[3];
    const float* H_t  = (const float*)d_in[4];
    const float* W1g[2] = {(const float*)d_in[5], (const float*)d_in[7]};
    const float* W2g[2] = {(const float*)d_in[6], (const float*)d_in[8]};
    const float* Wd[2]  = {(const float*)d_in[9], (const float*)d_in[11]};
    const float* Wt[2]  = {(const float*)d_in[10], (const float*)d_in[12]};
    const float* WdO  = (const float*)d_in[13];
    const float* WtO  = (const float*)d_in[14];
    float* out = (float*)d_out;

    float *S, *RT, *catd, *catt, *hdb, *htb, *hdp, *htp, *htpT;
    float *bsd, *bst, *bsd2, *bst2, *pa, *pb;
    float *sd, *st, *nd, *nt, *ntraw, *part, *selval;
    int* selidx;
    cudaGetSymbolAddress((void**)&S,     g_S);
    cudaGetSymbolAddress((void**)&RT,    g_RT);
    cudaGetSymbolAddress((void**)&catd,  g_catd);
    cudaGetSymbolAddress((void**)&catt,  g_catt);
    cudaGetSymbolAddress((void**)&hdb,   g_hd);
    cudaGetSymbolAddress((void**)&htb,   g_ht);
    cudaGetSymbolAddress((void**)&hdp,   g_hdp);
    cudaGetSymbolAddress((void**)&htp,   g_htp);
    cudaGetSymbolAddress((void**)&htpT,  g_htpT);
    cudaGetSymbolAddress((void**)&bsd,   g_bsd);
    cudaGetSymbolAddress((void**)&bst,   g_bst);
    cudaGetSymbolAddress((void**)&bsd2,  g_bsd2);
    cudaGetSymbolAddress((void**)&bst2,  g_bst2);
    cudaGetSymbolAddress((void**)&pa,    g_pa);
    cudaGetSymbolAddress((void**)&pb,    g_pb);
    cudaGetSymbolAddress((void**)&sd,    g_sd);
    cudaGetSymbolAddress((void**)&st,    g_st);
    cudaGetSymbolAddress((void**)&nd,    g_nd);
    cudaGetSymbolAddress((void**)&nt,    g_nt);
    cudaGetSymbolAddress((void**)&ntraw, g_ntraw);
    cudaGetSymbolAddress((void**)&part,  g_part);
    cudaGetSymbolAddress((void**)&selidx, g_selidx);
    cudaGetSymbolAddress((void**)&selval, g_selval);

    rowsum_rsqrt<<<D_NUM, 256>>>(Dm, D_NUM, D_NUM, sd);
    rowsum_rsqrt<<<T_NUM, 256>>>(Tm, T_NUM, T_NUM, st);

    const float* hd = H_d;
    const float* ht = H_t;
    int F = FEAT;

    for (int lvl = 0; lvl < 2; lvl++) {
        prescale2<<<dim3((F / 4 + 255) / 256, D_NUM, 2), 256>>>(
            bsd, hd, sd, D_NUM, bst, ht, st, T_NUM, F / 4);
        // split-K(8) Dn/Tn — wide kernel
        {
            GemmP pD = mk(Dm, bsd, pa, D_NUM, F, D_NUM, D_NUM, F, F, nullptr);
            GemmP pT = mk(Tm, bst, pb, T_NUM, F, T_NUM, T_NUM, F, F, nullptr);
            mma_gemm_w<0, true, false, 8><<<grid2_w(pD, pT, 8), GTHREADSW>>>(pD, pT);
            reduce2<4, 8><<<red_grid(pD, pT), 256>>>(
                catd + 2 * F, 3 * F, pa, sd, D_NUM, F,
                catt + 2 * F, 3 * F, pb, st, T_NUM, F);
        }
        // projections (64-tile)
        {
            GemmP pd = mk(hd, W1g[lvl], hdp, D_NUM, UNITS, F, F, UNITS, UNITS, nullptr);
            GemmP pt = mk(ht, W2g[lvl], htp, T_NUM, UNITS, F, F, UNITS, UNITS, nullptr);
            mma_gemm_f<3, true, true, 1><<<grid2_f(pd, pt, 1), GTHREADS>>>(pd, pt);
        }
        transpose_kernel<<<tr_grid(T_NUM, UNITS), dim3(32, 8)>>>(htpT, htp, T_NUM, UNITS);
        // sigmoid relation GEMM (N=2000) — wide kernel
        {
            GemmP ps = mk(hdp, htpT, S, D_NUM, T_NUM, UNITS, UNITS, T_NUM, T_NUM, nullptr);
            mma_gemm_w<2, false, false, 1><<<grid1_w(ps), GTHREADSW>>>(ps, ps);
        }

        zero_vec<<<(T_NUM + 255) / 256, 256>>>(ntraw, T_NUM);
        topk_kernel<<<D_NUM, 256>>>(S, selidx, selval, nd, ntraw);

        gather_dt<<<D_NUM, 256>>>(selidx, selval, nd, ntraw, ht, F, catd + F, 3 * F);
        zero_strided<<<dim3((F + 255) / 256, T_NUM), 256>>>(catt + F, 3 * F, T_NUM, F);
        scatter_td<<<D_NUM * TOPK, 256>>>(selidx, selval, nd, ntraw, hd, F, catt + F, 3 * F);
        relu_round_strided<<<dim3((F + 255) / 256, T_NUM), 256>>>(catt + F, 3 * F, T_NUM, F);
        copy_round2<<<dim3((F + 255) / 256, D_NUM, 2), 256>>>(
            catd, 3 * F, hd, F, D_NUM, catt, 3 * F, ht, F, T_NUM, F);

        // split-K(2) concat dense (64-tile)
        {
            GemmP pd = mk(catd, Wd[lvl], pa, D_NUM, UNITS, 3 * F, 3 * F, UNITS, UNITS, nullptr);
            GemmP pt = mk(catt, Wt[lvl], pb, T_NUM, UNITS, 3 * F, 3 * F, UNITS, UNITS, nullptr);
            mma_gemm_f<0, false, true, 2><<<grid2_f(pd, pt, 2), GTHREADS>>>(pd, pt);
            reduce2<1, 2><<<red_grid(pd, pt), 256>>>(
                hdb, UNITS, pa, nullptr, D_NUM, UNITS,
                htb, UNITS, pb, nullptr, T_NUM, UNITS);
        }
        hd = hdb; ht = htb; F = UNITS;
    }

    // ---- output CGC on original (dense) R ----
    rowsum_rsqrt<<<D_NUM, 256>>>(R, D_NUM, T_NUM, nd);
    colsum_partial<<<dim3((T_NUM + 255) / 256, NCHUNK), 256>>>(R, D_NUM, T_NUM, part);
    colsum_finish<<<(T_NUM + 255) / 256, 256>>>(part, T_NUM, nt);
    transpose_kernel<<<tr_grid(D_NUM, T_NUM), dim3(32, 8)>>>(RT, R, D_NUM, T_NUM);

    prescale2<<<dim3((F / 4 + 255) / 256, D_NUM, 2), 256>>>(
        bsd, ht, nt, T_NUM, bst, hd, nd, D_NUM, F / 4);
    prescale2<<<dim3((F / 4 + 255) / 256, D_NUM, 2), 256>>>(
        bsd2, hd, sd, D_NUM, bst2, ht, st, T_NUM, F / 4);

    // split-K(8) R-pair — wide kernel
    {
        GemmP pra = mk(R,  bsd, pa, D_NUM, F, T_NUM, T_NUM, F, F, nullptr);
        GemmP prb = mk(RT, bst, pb, T_NUM, F, D_NUM, D_NUM, F, F, nullptr);
        mma_gemm_w<0, true, false, 8><<<grid2_w(pra, prb, 8), GTHREADSW>>>(pra, prb);
        reduce2<4, 8><<<red_grid(pra, prb), 256>>>(
            catd + F, 3 * F, pa, nd, D_NUM, F,
            catt + F, 3 * F, pb, nt, T_NUM, F);
    }
    // split-K(8) Dn/Tn pair — wide kernel
    {
        GemmP pD = mk(Dm, bsd2, pa, D_NUM, F, D_NUM, D_NUM, F, F, nullptr);
        GemmP pT = mk(Tm, bst2, pb, T_NUM, F, T_NUM, T_NUM, F, F, nullptr);
        mma_gemm_w<0, true, false, 8><<<grid2_w(pD, pT, 8), GTHREADSW>>>(pD, pT);
        reduce2<4, 8><<<red_grid(pD, pT), 256>>>(
            catd + 2 * F, 3 * F, pa, sd, D_NUM, F,
            catt + 2 * F, 3 * F, pb, st, T_NUM, F);
    }

    copy_round2<<<dim3((F + 255) / 256, D_NUM, 2), 256>>>(
        catd, 3 * F, hd, F, D_NUM, catt, 3 * F, ht, F, T_NUM, F);

    // split-K(2) output dense (64-tile)
    {
        GemmP pd = mk(catd, WdO, pa, D_NUM, UNITS, 3 * F, 3 * F, UNITS, UNITS, nullptr);
        GemmP pt = mk(catt, WtO, pb, T_NUM, UNITS, 3 * F, 3 * F, UNITS, UNITS, nullptr);
        mma_gemm_f<0, false, true, 2><<<grid2_f(pd, pt, 2), GTHREADS>>>(pd, pt);
        reduce2<4, 2><<<red_grid(pd, pt), 256>>>(
            hdp, UNITS, pa, nullptr, D_NUM, UNITS,
            htp, UNITS, pb, nullptr, T_NUM, UNITS);
    }

    // R_pred = sigmoid(hd_out @ ht_out^T) — wide kernel
    transpose_kernel<<<tr_grid(T_NUM, UNITS), dim3(32, 8)>>>(htpT, htp, T_NUM, UNITS);
    {
        GemmP ps = mk(hdp, htpT, out, D_NUM, T_NUM, UNITS, UNITS, T_NUM, T_NUM, nullptr);
        mma_gemm_w<2, false, false, 1><<<grid1_w(ps), GTHREADSW>>>(ps, ps);
    }
}

// round 14
// speedup vs baseline: 1.2729x; 1.0017x over previous
#include <cuda_runtime.h>
#include <math.h>
#include <stdint.h>

#define D_NUM 4000
#define T_NUM 2000
#define FEAT  256
#define UNITS 200
#define TOPK  10
#define NCHUNK 16

// ---------------- scratch ----------------
__device__ float g_S[(size_t)D_NUM * T_NUM];
__device__ float g_RT[(size_t)T_NUM * D_NUM];
__device__ float g_catd[(size_t)D_NUM * 3 * FEAT];
__device__ float g_catt[(size_t)T_NUM * 3 * FEAT];
__device__ float g_hd[(size_t)D_NUM * FEAT];
__device__ float g_ht[(size_t)T_NUM * FEAT];
__device__ float g_hdp[(size_t)D_NUM * UNITS];
__device__ float g_htp[(size_t)T_NUM * UNITS];
__device__ float g_htpT[(size_t)UNITS * T_NUM];
__device__ float g_bsd[(size_t)D_NUM * FEAT];
__device__ float g_bst[(size_t)D_NUM * FEAT];
__device__ float g_bsd2[(size_t)D_NUM * FEAT];
__device__ float g_bst2[(size_t)D_NUM * FEAT];
__device__ float g_pa[(size_t)8 * D_NUM * FEAT];
__device__ float g_pb[(size_t)8 * D_NUM * FEAT];
__device__ float g_sd[D_NUM];
__device__ float g_st[T_NUM];
__device__ float g_nd[D_NUM];
__device__ float g_nt[T_NUM];
__device__ float g_ntraw[T_NUM];
__device__ float g_part[NCHUNK * T_NUM];
__device__ int   g_selidx[D_NUM * TOPK];
__device__ float g_selval[D_NUM * TOPK];

__device__ __forceinline__ uint32_t f2tf(float x) {
    uint32_t r;
    asm("cvt.rna.tf32.f32 %0, %1;" : "=r"(r) : "f"(x));
    return r;
}
__device__ __forceinline__ float roundtf(float x) {
    return __uint_as_float(f2tf(x));
}

// ---------------- reductions ----------------
__global__ void rowsum_rsqrt(const float* __restrict__ A, int rows, int cols,
                             float* __restrict__ out) {
    int row = blockIdx.x;
    if (row >= rows) return;
    const float* a = A + (size_t)row * cols;
    float s = 0.f;
    for (int j = threadIdx.x; j < cols; j += blockDim.x) s += a[j];
    __shared__ float red[256];
    red[threadIdx.x] = s;
    __syncthreads();
    for (int off = 128; off > 0; off >>= 1) {
        if (threadIdx.x < off) red[threadIdx.x] += red[threadIdx.x + off];
        __syncthreads();
    }
    if (threadIdx.x == 0) {
        float n = red[0];
        if (n == 0.f) n = 1.f;
        out[row] = rsqrtf(n);
    }
}

__global__ void colsum_partial(const float* __restrict__ A, int rows, int cols,
                               float* __restrict__ part) {
    int j = blockIdx.x * blockDim.x + threadIdx.x;
    if (j >= cols) return;
    int chunk = (rows + NCHUNK - 1) / NCHUNK;
    int r0 = blockIdx.y * chunk;
    int r1 = r0 + chunk; if (r1 > rows) r1 = rows;
    float s = 0.f;
    for (int i = r0; i < r1; i++) s += A[(size_t)i * cols + j];
    part[blockIdx.y * cols + j] = s;
}

__global__ void colsum_finish(const float* __restrict__ part, int cols,
                              float* __restrict__ out) {
    int j = blockIdx.x * blockDim.x + threadIdx.x;
    if (j >= cols) return;
    float s = 0.f;
    for (int c = 0; c < NCHUNK; c++) s += part[c * cols + j];
    if (s == 0.f) s = 1.f;
    out[j] = rsqrtf(s);
}

// ---------------- prep kernels ----------------
__global__ void prescale2(float* dst0, const float* src0, const float* sc0, int rows0,
                          float* dst1, const float* src1, const float* sc1, int rows1,
                          int cols4) {
    int c4 = blockIdx.x * blockDim.x + threadIdx.x;
    int r = blockIdx.y;
    float* dst = blockIdx.z ? dst1 : dst0;
    const float* src = blockIdx.z ? src1 : src0;
    const float* sc = blockIdx.z ? sc1 : sc0;
    int rows = blockIdx.z ? rows1 : rows0;
    if (c4 >= cols4 || r >= rows) return;
    float s = sc[r];
    float4 v = reinterpret_cast<const float4*>(src + (size_t)r * cols4 * 4)[c4];
    v.x = roundtf(v.x * s); v.y = roundtf(v.y * s);
    v.z = roundtf(v.z * s); v.w = roundtf(v.w * s);
    reinterpret_cast<float4*>(dst + (size_t)r * cols4 * 4)[c4] = v;
}

__global__ void transpose_kernel(float* __restrict__ dst, const float* __restrict__ src,
                                 int rows, int cols) {
    __shared__ float t[32][33];
    int bx = blockIdx.x * 32, by = blockIdx.y * 32;
    int x = bx + threadIdx.x;
    #pragma unroll
    for (int i = 0; i < 32; i += 8) {
        int y = by + threadIdx.y + i;
        if (x < cols && y < rows) t[threadIdx.y + i][threadIdx.x] = src[(size_t)y * cols + x];
    }
    __syncthreads();
    int x2 = by + threadIdx.x;
    #pragma unroll
    for (int i = 0; i < 32; i += 8) {
        int y2 = bx + threadIdx.y + i;
        if (x2 < rows && y2 < cols) dst[(size_t)y2 * rows + x2] = t[threadIdx.x][threadIdx.y + i];
    }
}

__global__ void zero_vec(float* __restrict__ p, int n) {
    int i = blockIdx.x * blockDim.x + threadIdx.x;
    if (i < n) p[i] = 0.f;
}

__global__ void zero_strided(float* __restrict__ dst, int ld, int rows, int cols) {
    int c = blockIdx.x * blockDim.x + threadIdx.x;
    int r = blockIdx.y;
    if (c < cols && r < rows) dst[(size_t)r * ld + c] = 0.f;
}

__global__ void relu_round_strided(float* __restrict__ dst, int ld, int rows, int cols) {
    int c = blockIdx.x * blockDim.x + threadIdx.x;
    int r = blockIdx.y;
    if (c < cols && r < rows) {
        size_t o = (size_t)r * ld + c;
        dst[o] = roundtf(fmaxf(dst[o], 0.f));
    }
}

__global__ void copy_round2(float* dst0, int ldd0, const float* src0, int lds0, int rows0,
                            float* dst1, int ldd1, const float* src1, int lds1, int rows1,
                            int cols) {
    int c = blockIdx.x * blockDim.x + threadIdx.x;
    int r = blockIdx.y;
    float* dst = blockIdx.z ? dst1 : dst0;
    const float* src = blockIdx.z ? src1 : src0;
    int ldd = blockIdx.z ? ldd1 : ldd0;
    int lds = blockIdx.z ? lds1 : lds0;
    int rows = blockIdx.z ? rows1 : rows0;
    if (c < cols && r < rows)
        dst[(size_t)r * ldd + c] = roundtf(src[(size_t)r * lds + c]);
}

// split-K reduce + epilogue, z-fused pair, NS slabs.
template <int EPI, int NS>
__global__ void reduce2(float* out0, int ld0, const float* part0, const float* rs0, int M0, int N0,
                        float* out1, int ld1, const float* part1, const float* rs1, int M1, int N1) {
    int c = blockIdx.x * blockDim.x + threadIdx.x;
    int r = blockIdx.y;
    float* out = blockIdx.z ? out1 : out0;
    const float* part = blockIdx.z ? part1 : part0;
    const float* rs = blockIdx.z ? rs1 : rs0;
    int M = blockIdx.z ? M1 : M0;
    int N = blockIdx.z ? N1 : N0;
    int ld = blockIdx.z ? ld1 : ld0;
    if (r >= M || c >= N) return;
    size_t o = (size_t)r * N + c;
    size_t slab = (size_t)M * N;
    float v = 0.f;
    #pragma unroll
    for (int s = 0; s < NS; s++) v += part[s * slab + o];
    if (rs) v *= rs[r];
    if (EPI == 1 || EPI == 4) v = fmaxf(v, 0.f);
    if (EPI >= 3) v = roundtf(v);
    out[(size_t)r * ld + c] = v;
}

// ---------------- top-k ----------------
__global__ void topk_kernel(const float* __restrict__ S,
                            int* __restrict__ selidx, float* __restrict__ selval,
                            float* __restrict__ nd_out, float* __restrict__ ntraw) {
    int row = blockIdx.x;
    int tid = threadIdx.x;
    int lane = tid & 31, wid = tid >> 5;
    const float* srow = S + (size_t)row * T_NUM;

    float v[8];
    #pragma unroll
    for (int i = 0; i < 8; i++) {
        int j = tid + i * 256;
        v[i] = (j < T_NUM) ? srow[j] : -3.f;
    }

    __shared__ float wv[8];
    __shared__ int   wi[8];
    __shared__ int   bidx_s;
    __shared__ int   sel[TOPK];
    __shared__ float selv[TOPK];

    for (int it = 0; it < TOPK; it++) {
        float best = v[0]; int bi = tid;
        #pragma unroll
        for (int i = 1; i < 8; i++) {
            int j = tid + i * 256;
            if (v[i] > best) { best = v[i]; bi = j; }
        }
        #pragma unroll
        for (int off = 16; off > 0; off >>= 1) {
            float ov = __shfl_xor_sync(0xffffffffu, best, off);
            int   oi = __shfl_xor_sync(0xffffffffu, bi, off);
            if (ov > best || (ov == best && oi < bi)) { best = ov; bi = oi; }
        }
        if (lane == 0) { wv[wid] = best; wi[wid] = bi; }
        __syncthreads();
        if (tid == 0) {
            float b = wv[0]; int x = wi[0];
            #pragma unroll
            for (int w = 1; w < 8; w++)
                if (wv[w] > b || (wv[w] == b && wi[w] < x)) { b = wv[w]; x = wi[w]; }
            bidx_s = x; sel[it] = x; selv[it] = b;
        }
        __syncthreads();
        int x = bidx_s;
        if ((x & 255) == tid) v[x >> 8] = -3.f;
    }

    if (tid < TOPK) {
        selidx[row * TOPK + tid] = sel[tid];
        selval[row * TOPK + tid] = selv[tid];
        atomicAdd(&ntraw[sel[tid]], selv[tid]);
    }
    if (tid == 0) {
        float s = 0.f;
        #pragma unroll
        for (int t = 0; t < TOPK; t++) s += selv[t];
        if (s == 0.f) s = 1.f;
        nd_out[row] = rsqrtf(s);
    }
}

// ---------------- sparse CGC ----------------
__global__ void gather_dt(const int* __restrict__ selidx, const float* __restrict__ selval,
                          const float* __restrict__ nd, const float* __restrict__ ntraw,
                          const float* __restrict__ ht, int F,
                          float* __restrict__ outd, int ldo) {
    int d = blockIdx.x;
    __shared__ int   ci[TOPK];
    __shared__ float cw[TOPK];
    if (threadIdx.x < TOPK) {
        int c = selidx[d * TOPK + threadIdx.x];
        float s = ntraw[c];
        if (s == 0.f) s = 1.f;
        ci[threadIdx.x] = c;
        cw[threadIdx.x] = selval[d * TOPK + threadIdx.x] * rsqrtf(s);
    }
    __syncthreads();
    float ndv = nd[d];
    for (int f = threadIdx.x; f < F; f += blockDim.x) {
        float s = 0.f;
        #pragma unroll
        for (int j = 0; j < TOPK; j++) s += cw[j] * ht[(size_t)ci[j] * F + f];
        outd[(size_t)d * ldo + f] = roundtf(fmaxf(s * ndv, 0.f));
    }
}

__global__ void scatter_td(const int* __restrict__ selidx, const float* __restrict__ selval,
                           const float* __restrict__ nd, const float* __restrict__ ntraw,
                           const float* __restrict__ hd, int F,
                           float* __restrict__ outt, int ldo) {
    int e = blockIdx.x;
    int d = e / TOPK;
    int t = selidx[e];
    float s = ntraw[t];
    if (s == 0.f) s = 1.f;
    float w = selval[e] * nd[d] * rsqrtf(s);
    const float* src = hd + (size_t)d * F;
    float* dst = outt + (size_t)t * ldo;
    for (int f = threadIdx.x; f < F; f += blockDim.x)
        atomicAdd(&dst[f], w * src[f]);
}

// ---------------- common GEMM bits ----------------
struct GemmP {
    const float* A;
    const float* B;
    float* C;
    int M, N, K, lda, ldb, ldc;
    const float* rowscale;
};

__device__ __forceinline__ void mma_tf32(float c[4], uint32_t a0, uint32_t a1,
                                         uint32_t a2, uint32_t a3,
                                         uint32_t b0, uint32_t b1) {
    asm volatile(
        "mma.sync.aligned.m16n8k8.row.col.f32.tf32.tf32.f32 "
        "{%0,%1,%2,%3}, {%4,%5,%6,%7}, {%8,%9}, {%0,%1,%2,%3};"
        : "+f"(c[0]), "+f"(c[1]), "+f"(c[2]), "+f"(c[3])
        : "r"(a0), "r"(a1), "r"(a2), "r"(a3), "r"(b0), "r"(b1));
}

__device__ __forceinline__ uint32_t cvt_bits(uint32_t raw) {
    return f2tf(__uint_as_float(raw));
}

__device__ __forceinline__ void cp_async16(uint32_t dst_smem, const void* src, bool pred) {
    int sz = pred ? 16 : 0;
    asm volatile("cp.async.cg.shared.global [%0], [%1], 16, %2;"
                 :: "r"(dst_smem), "l"(src), "r"(sz));
}
#define CP_COMMIT() asm volatile("cp.async.commit_group;")
#define CP_WAIT1()  asm volatile("cp.async.wait_group 1;")

#define GBK 16
#define NSTAGE 3
#define ASTR (GBK + 4)

// ============ 64x64 kernel, 128 threads (proven; small/medium launches) ============
#define GBM 64
#define GBN 64
#define BSTR (GBN + 8)
#define GTHREADS 128

template <int EPI, bool ACVT, bool BCVT, int NS>
__global__ __launch_bounds__(GTHREADS)
void mma_gemm_f(GemmP p0, GemmP p1) {
    int prob = blockIdx.z / NS;
    int split = blockIdx.z % NS;
    const GemmP p = prob ? p1 : p0;
    int bm = blockIdx.y * GBM;
    int bn = blockIdx.x * GBN;
    if (bm >= p.M || bn >= p.N) return;

    __shared__ uint32_t As[NSTAGE][GBM][ASTR];
    __shared__ uint32_t Bs[NSTAGE][GBK][BSTR];

    int tid = threadIdx.x;
    int lane = tid & 31;
    int warp = tid >> 5;
    int gid = lane >> 2, tig = lane & 3;
    int mw = (warp & 1) * 32;
    int nw = (warp >> 1) * 32;

    uint32_t sa = (uint32_t)__cvta_generic_to_shared(&As[0][0][0]);
    uint32_t sb = (uint32_t)__cvta_generic_to_shared(&Bs[0][0][0]);

    float acc[2][4][4];
    #pragma unroll
    for (int i = 0; i < 2; i++)
        #pragma unroll
        for (int j = 0; j < 4; j++)
            #pragma unroll
            for (int l = 0; l < 4; l++) acc[i][j][l] = 0.f;

    int nkt_total = (p.K + GBK - 1) / GBK;
    int chunk = (nkt_total + NS - 1) / NS;
    int kt_begin = split * chunk;
    int kt_end = min(nkt_total, kt_begin + chunk);
    int niter = kt_end - kt_begin;
    if (niter < 0) niter = 0;

    int a_m0 = tid >> 1;
    int a_kq = (tid & 1) * 8;
    int b_kb = tid >> 3;
    int b_nq = (tid & 7) * 8;

    auto issue_tile = [&](int kt, int st) {
        int k0 = kt * GBK;
        {
            int gm = bm + a_m0;
            const float* src = p.A + (size_t)gm * p.lda + k0 + a_kq;
            uint32_t dst = sa + (((st * GBM + a_m0) * ASTR) + a_kq) * 4;
            bool rowok = (gm < p.M);
            cp_async16(dst,      src,     rowok && (k0 + a_kq     < p.K));
            cp_async16(dst + 16, src + 4, rowok && (k0 + a_kq + 4 < p.K));
        }
        {
            int gk = k0 + b_kb;
            const float* src = p.B + (size_t)gk * p.ldb + bn + b_nq;
            uint32_t dst = sb + (((st * GBK + b_kb) * BSTR) + b_nq) * 4;
            bool kok = (gk < p.K);
            cp_async16(dst,      src,     kok && (bn + b_nq     < p.N));
            cp_async16(dst + 16, src + 4, kok && (bn + b_nq + 4 < p.N));
        }
    };

    #pragma unroll
    for (int s = 0; s < NSTAGE - 1; s++) {
        if (s < niter) issue_tile(kt_begin + s, s);
        CP_COMMIT();
    }

    int cur = 0;
    for (int it = 0; it < niter; it++) {
        CP_WAIT1();
        __syncthreads();

        #pragma unroll
        for (int kk = 0; kk < GBK; kk += 8) {
            uint32_t b0[4], b1[4];
            #pragma unroll
            for (int nt = 0; nt < 4; nt++) {
                b0[nt] = Bs[cur][kk + tig][nw + nt * 8 + gid];
                b1[nt] = Bs[cur][kk + tig + 4][nw + nt * 8 + gid];
                if (BCVT) { b0[nt] = cvt_bits(b0[nt]); b1[nt] = cvt_bits(b1[nt]); }
            }
            #pragma unroll
            for (int mt = 0; mt < 2; mt++) {
                int mb = mw + mt * 16;
                uint32_t a0 = As[cur][mb + gid][kk + tig];
                uint32_t a1 = As[cur][mb + gid + 8][kk + tig];
                uint32_t a2 = As[cur][mb + gid][kk + tig + 4];
                uint32_t a3 = As[cur][mb + gid + 8][kk + tig + 4];
                if (ACVT) {
                    a0 = cvt_bits(a0); a1 = cvt_bits(a1);
                    a2 = cvt_bits(a2); a3 = cvt_bits(a3);
                }
                #pragma unroll
                for (int nt = 0; nt < 4; nt++)
                    mma_tf32(acc[mt][nt], a0, a1, a2, a3, b0[nt], b1[nt]);
            }
        }

        if (it + NSTAGE - 1 < niter) {
            int st = (cur + NSTAGE - 1) % NSTAGE;
            issue_tile(kt_begin + it + NSTAGE - 1, st);
        }
        CP_COMMIT();
        cur = (cur + 1) % NSTAGE;
    }

    if (NS > 1) {
        float* dst = p.C + (size_t)split * p.M * p.N;
        #pragma unroll
        for (int mt = 0; mt < 2; mt++) {
            int gm0 = bm + mw + mt * 16 + gid;
            int gm1 = gm0 + 8;
            #pragma unroll
            for (int nt = 0; nt < 4; nt++) {
                int gn0 = bn + nw + nt * 8 + 2 * tig;
                int gn1 = gn0 + 1;
                #pragma unroll
                for (int q = 0; q < 4; q++) {
                    int gm = (q < 2) ? gm0 : gm1;
                    int gn = (q & 1) ? gn1 : gn0;
                    if (gm >= p.M || gn >= p.N) continue;
                    dst[(size_t)gm * p.N + gn] = acc[mt][nt][q];
                }
            }
        }
        return;
    }

    #pragma unroll
    for (int mt = 0; mt < 2; mt++) {
        int gm0 = bm + mw + mt * 16 + gid;
        int gm1 = gm0 + 8;
        float rs0 = 1.f, rs1 = 1.f;
        if (p.rowscale) {
            if (gm0 < p.M) rs0 = p.rowscale[gm0];
            if (gm1 < p.M) rs1 = p.rowscale[gm1];
        }
        #pragma unroll
        for (int nt = 0; nt < 4; nt++) {
            int gn0 = bn + nw + nt * 8 + 2 * tig;
            int gn1 = gn0 + 1;
            #pragma unroll
            for (int q = 0; q < 4; q++) {
                int gm = (q < 2) ? gm0 : gm1;
                int gn = (q & 1) ? gn1 : gn0;
                if (gm >= p.M || gn >= p.N) continue;
                float v = acc[mt][nt][q] * ((q < 2) ? rs0 : rs1);
                if (EPI == 1 || EPI == 4) v = fmaxf(v, 0.f);
                else if (EPI == 2) v = 1.f / (1.f + __expf(-v));
                if (EPI >= 3) v = roundtf(v);
                p.C[(size_t)gm * p.ldc + gn] = v;
            }
        }
    }
}

// ============ 64x128 kernel, 256 threads (wide-N; sigmoid GEMMs) ============
#define GBNW 128
#define BSTRW (GBNW + 8)
#define GTHREADSW 256

template <int EPI, bool ACVT, bool BCVT, int NS>
__global__ __launch_bounds__(GTHREADSW)
void mma_gemm_w(GemmP p0, GemmP p1) {
    int prob = blockIdx.z / NS;
    int split = blockIdx.z % NS;
    const GemmP p = prob ? p1 : p0;
    int bm = blockIdx.y * GBM;
    int bn = blockIdx.x * GBNW;
    if (bm >= p.M || bn >= p.N) return;

    __shared__ uint32_t As[NSTAGE][GBM][ASTR];
    __shared__ uint32_t Bs[NSTAGE][GBK][BSTRW];

    int tid = threadIdx.x;
    int lane = tid & 31;
    int warp = tid >> 5;
    int gid = lane >> 2, tig = lane & 3;
    int mw = (warp & 1) * 32;
    int nw = (warp >> 1) * 32;

    uint32_t sa = (uint32_t)__cvta_generic_to_shared(&As[0][0][0]);
    uint32_t sb = (uint32_t)__cvta_generic_to_shared(&Bs[0][0][0]);

    float acc[2][4][4];
    #pragma unroll
    for (int i = 0; i < 2; i++)
        #pragma unroll
        for (int j = 0; j < 4; j++)
            #pragma unroll
            for (int l = 0; l < 4; l++) acc[i][j][l] = 0.f;

    int nkt_total = (p.K + GBK - 1) / GBK;
    int chunk = (nkt_total + NS - 1) / NS;
    int kt_begin = split * chunk;
    int kt_end = min(nkt_total, kt_begin + chunk);
    int niter = kt_end - kt_begin;
    if (niter < 0) niter = 0;

    int a_m0 = tid >> 2;
    int a_kq = (tid & 3) * 4;
    int b_kb = tid >> 4;
    int b_nq = (tid & 15) * 8;

    auto issue_tile = [&](int kt, int st) {
        int k0 = kt * GBK;
        {
            int gm = bm + a_m0;
            const float* src = p.A + (size_t)gm * p.lda + k0 + a_kq;
            uint32_t dst = sa + (((st * GBM + a_m0) * ASTR) + a_kq) * 4;
            cp_async16(dst, src, (gm < p.M) && (k0 + a_kq < p.K));
        }
        {
            int gk = k0 + b_kb;
            const float* src = p.B + (size_t)gk * p.ldb + bn + b_nq;
            uint32_t dst = sb + (((st * GBK + b_kb) * BSTRW) + b_nq) * 4;
            bool kok = (gk < p.K);
            cp_async16(dst,      src,     kok && (bn + b_nq     < p.N));
            cp_async16(dst + 16, src + 4, kok && (bn + b_nq + 4 < p.N));
        }
    };

    #pragma unroll
    for (int s = 0; s < NSTAGE - 1; s++) {
        if (s < niter) issue_tile(kt_begin + s, s);
        CP_COMMIT();
    }

    int cur = 0;
    for (int it = 0; it < niter; it++) {
        CP_WAIT1();
        __syncthreads();

        #pragma unroll
        for (int kk = 0; kk < GBK; kk += 8) {
            uint32_t b0[4], b1[4];
            #pragma unroll
            for (int nt = 0; nt < 4; nt++) {
                b0[nt] = Bs[cur][kk + tig][nw + nt * 8 + gid];
                b1[nt] = Bs[cur][kk + tig + 4][nw + nt * 8 + gid];
                if (BCVT) { b0[nt] = cvt_bits(b0[nt]); b1[nt] = cvt_bits(b1[nt]); }
            }
            #pragma unroll
            for (int mt = 0; mt < 2; mt++) {
                int mb = mw + mt * 16;
                uint32_t a0 = As[cur][mb + gid][kk + tig];
                uint32_t a1 = As[cur][mb + gid + 8][kk + tig];
                uint32_t a2 = As[cur][mb + gid][kk + tig + 4];
                uint32_t a3 = As[cur][mb + gid + 8][kk + tig + 4];
                if (ACVT) {
                    a0 = cvt_bits(a0); a1 = cvt_bits(a1);
                    a2 = cvt_bits(a2); a3 = cvt_bits(a3);
                }
                #pragma unroll
                for (int nt = 0; nt < 4; nt++)
                    mma_tf32(acc[mt][nt], a0, a1, a2, a3, b0[nt], b1[nt]);
            }
        }

        if (it + NSTAGE - 1 < niter) {
            int st = (cur + NSTAGE - 1) % NSTAGE;
            issue_tile(kt_begin + it + NSTAGE - 1, st);
        }
        CP_COMMIT();
        cur = (cur + 1) % NSTAGE;
    }

    if (NS > 1) {
        float* dst = p.C + (size_t)split * p.M * p.N;
        #pragma unroll
        for (int mt = 0; mt < 2; mt++) {
            int gm0 = bm + mw + mt * 16 + gid;
            int gm1 = gm0 + 8;
            #pragma unroll
            for (int nt = 0; nt < 4; nt++) {
                int gn0 = bn + nw + nt * 8 + 2 * tig;
                int gn1 = gn0 + 1;
                #pragma unroll
                for (int q = 0; q < 4; q++) {
                    int gm = (q < 2) ? gm0 : gm1;
                    int gn = (q & 1) ? gn1 : gn0;
                    if (gm >= p.M || gn >= p.N) continue;
                    dst[(size_t)gm * p.N + gn] = acc[mt][nt][q];
                }
            }
        }
        return;
    }

    #pragma unroll
    for (int mt = 0; mt < 2; mt++) {
        int gm0 = bm + mw + mt * 16 + gid;
        int gm1 = gm0 + 8;
        float rs0 = 1.f, rs1 = 1.f;
        if (p.rowscale) {
            if (gm0 < p.M) rs0 = p.rowscale[gm0];
            if (gm1 < p.M) rs1 = p.rowscale[gm1];
        }
        #pragma unroll
        for (int nt = 0; nt < 4; nt++) {
            int gn0 = bn + nw + nt * 8 + 2 * tig;
            int gn1 = gn0 + 1;
            #pragma unroll
            for (int q = 0; q < 4; q++) {
                int gm = (q < 2) ? gm0 : gm1;
                int gn = (q & 1) ? gn1 : gn0;
                if (gm >= p.M || gn >= p.N) continue;
                float v = acc[mt][nt][q] * ((q < 2) ? rs0 : rs1);
                if (EPI == 1 || EPI == 4) v = fmaxf(v, 0.f);
                else if (EPI == 2) v = 1.f / (1.f + __expf(-v));
                if (EPI >= 3) v = roundtf(v);
                p.C[(size_t)gm * p.ldc + gn] = v;
            }
        }
    }
}

// ============ 64x256 kernel, 256 threads, warp tile 32x64 (big split-K pairs) ===
#define GBNX 256
#define BSTRX (GBNX + 8)

template <bool ACVT, int NS>
__global__ __launch_bounds__(GTHREADSW)
void mma_gemm_x(GemmP p0, GemmP p1) {
    int prob = blockIdx.z / NS;
    int split = blockIdx.z % NS;
    const GemmP p = prob ? p1 : p0;
    int bm = blockIdx.y * GBM;
    int bn = blockIdx.x * GBNX;
    if (bm >= p.M || bn >= p.N) return;

    __shared__ uint32_t As[NSTAGE][GBM][ASTR];
    __shared__ uint32_t Bs[NSTAGE][GBK][BSTRX];

    int tid = threadIdx.x;
    int lane = tid & 31;
    int warp = tid >> 5;                 // 0..7
    int gid = lane >> 2, tig = lane & 3;
    int mw = (warp & 1) * 32;            // 2 warps in M
    int nw = (warp >> 1) * 64;           // 4 warps in N, 64 wide each

    uint32_t sa = (uint32_t)__cvta_generic_to_shared(&As[0][0][0]);
    uint32_t sb = (uint32_t)__cvta_generic_to_shared(&Bs[0][0][0]);

    float acc[2][8][4];
    #pragma unroll
    for (int i = 0; i < 2; i++)
        #pragma unroll
        for (int j = 0; j < 8; j++)
            #pragma unroll
            for (int l = 0; l < 4; l++) acc[i][j][l] = 0.f;

    int nkt_total = (p.K + GBK - 1) / GBK;
    int chunk = (nkt_total + NS - 1) / NS;
    int kt_begin = split * chunk;
    int kt_end = min(nkt_total, kt_begin + chunk);
    int niter = kt_end - kt_begin;
    if (niter < 0) niter = 0;

    // A: 64x16 = 256 chunks / 256 thr = 1 each.
    int a_m0 = tid >> 2;
    int a_kq = (tid & 3) * 4;
    // B: 16x256 = 1024 chunks / 256 thr = 4 each (16 consecutive floats).
    int b_kb = tid >> 4;
    int b_nq = (tid & 15) * 16;

    auto issue_tile = [&](int kt, int st) {
        int k0 = kt * GBK;
        {
            int gm = bm + a_m0;
            const float* src = p.A + (size_t)gm * p.lda + k0 + a_kq;
            uint32_t dst = sa + (((st * GBM + a_m0) * ASTR) + a_kq) * 4;
            cp_async16(dst, src, (gm < p.M) && (k0 + a_kq < p.K));
        }
        {
            int gk = k0 + b_kb;
            const float* src = p.B + (size_t)gk * p.ldb + bn + b_nq;
            uint32_t dst = sb + (((st * GBK + b_kb) * BSTRX) + b_nq) * 4;
            bool kok = (gk < p.K);
            #pragma unroll
            for (int u = 0; u < 4; u++)
                cp_async16(dst + u * 16, src + u * 4, kok && (bn + b_nq + u * 4 < p.N));
        }
    };

    #pragma unroll
    for (int s = 0; s < NSTAGE - 1; s++) {
        if (s < niter) issue_tile(kt_begin + s, s);
        CP_COMMIT();
    }

    int cur = 0;
    for (int it = 0; it < niter; it++) {
        CP_WAIT1();
        __syncthreads();

        #pragma unroll
        for (int kk = 0; kk < GBK; kk += 8) {
            uint32_t b0[8], b1[8];
            #pragma unroll
            for (int nt = 0; nt < 8; nt++) {
                b0[nt] = Bs[cur][kk + tig][nw + nt * 8 + gid];
                b1[nt] = Bs[cur][kk + tig + 4][nw + nt * 8 + gid];
            }
            #pragma unroll
            for (int mt = 0; mt < 2; mt++) {
                int mb = mw + mt * 16;
                uint32_t a0 = As[cur][mb + gid][kk + tig];
                uint32_t a1 = As[cur][mb + gid + 8][kk + tig];
                uint32_t a2 = As[cur][mb + gid][kk + tig + 4];
                uint32_t a3 = As[cur][mb + gid + 8][kk + tig + 4];
                if (ACVT) {
                    a0 = cvt_bits(a0); a1 = cvt_bits(a1);
                    a2 = cvt_bits(a2); a3 = cvt_bits(a3);
                }
                #pragma unroll
                for (int nt = 0; nt < 8; nt++)
                    mma_tf32(acc[mt][nt], a0, a1, a2, a3, b0[nt], b1[nt]);
            }
        }

        if (it + NSTAGE - 1 < niter) {
            int st = (cur + NSTAGE - 1) % NSTAGE;
            issue_tile(kt_begin + it + NSTAGE - 1, st);
        }
        CP_COMMIT();
        cur = (cur + 1) % NSTAGE;
    }

    // split-K partial epilogue (float2 stores; gn0 is even)
    float* dst = p.C + (size_t)split * p.M * p.N;
    #pragma unroll
    for (int mt = 0; mt < 2; mt++) {
        int gm0 = bm + mw + mt * 16 + gid;
        int gm1 = gm0 + 8;
        #pragma unroll
        for (int nt = 0; nt < 8; nt++) {
            int gn0 = bn + nw + nt * 8 + 2 * tig;
            if (gm0 < p.M && gn0 + 1 < p.N)
                *reinterpret_cast<float2*>(&dst[(size_t)gm0 * p.N + gn0]) =
                    make_float2(acc[mt][nt][0], acc[mt][nt][1]);
            if (gm1 < p.M && gn0 + 1 < p.N)
                *reinterpret_cast<float2*>(&dst[(size_t)gm1 * p.N + gn0]) =
                    make_float2(acc[mt][nt][2], acc[mt][nt][3]);
        }
    }
}

static inline GemmP mk(const float* A, const float* B, float* C,
                       int M, int N, int K, int lda, int ldb, int ldc,
                       const float* rs) {
    GemmP p; p.A = A; p.B = B; p.C = C; p.M = M; p.N = N; p.K = K;
    p.lda = lda; p.ldb = ldb; p.ldc = ldc; p.rowscale = rs; return p;
}
static inline dim3 grid2_f(const GemmP& a, const GemmP& b, int ns) {
    int gx = max((a.N + GBN - 1) / GBN, (b.N + GBN - 1) / GBN);
    int gy = max((a.M + GBM - 1) / GBM, (b.M + GBM - 1) / GBM);
    return dim3(gx, gy, 2 * ns);
}
static inline dim3 grid1_w(const GemmP& p) {
    return dim3((p.N + GBNW - 1) / GBNW, (p.M + GBM - 1) / GBM, 1);
}
static inline dim3 grid2_x(const GemmP& a, const GemmP& b, int ns) {
    int gx = max((a.N + GBNX - 1) / GBNX, (b.N + GBNX - 1) / GBNX);
    int gy = max((a.M + GBM - 1) / GBM, (b.M + GBM - 1) / GBM);
    return dim3(gx, gy, 2 * ns);
}
static inline dim3 tr_grid(int rows, int cols) {
    return dim3((cols + 31) / 32, (rows + 31) / 32);
}
static inline dim3 red_grid(const GemmP& a, const GemmP& b) {
    int n = max(a.N, b.N);
    int m = max(a.M, b.M);
    return dim3((n + 255) / 256, m, 2);
}

// ---------------- host orchestration ----------------
extern "C" void kernel_launch(void* const* d_in, const int* in_sizes, int n_in,
                              void* d_out, int out_size) {
    const float* R    = (const float*)d_in[0];
    const float* Dm   = (const float*)d_in[1];
    const float* Tm   = (const float*)d_in[2];
    const float* H_d  = (const float*)d_in[3];
    const float* H_t  = (const float*)d_in[4];
    const float* W1g[2] = {(const float*)d_in[5], (const float*)d_in[7]};
    const float* W2g[2] = {(const float*)d_in[6], (const float*)d_in[8]};
    const float* Wd[2]  = {(const float*)d_in[9], (const float*)d_in[11]};
    const float* Wt[2]  = {(const float*)d_in[10], (const float*)d_in[12]};
    const float* WdO  = (const float*)d_in[13];
    const float* WtO  = (const float*)d_in[14];
    float* out = (float*)d_out;

    float *S, *RT, *catd, *catt, *hdb, *htb, *hdp, *htp, *htpT;
    float *bsd, *bst, *bsd2, *bst2, *pa, *pb;
    float *sd, *st, *nd, *nt, *ntraw, *part, *selval;
    int* selidx;
    cudaGetSymbolAddress((void**)&S,     g_S);
    cudaGetSymbolAddress((void**)&RT,    g_RT);
    cudaGetSymbolAddress((void**)&catd,  g_catd);
    cudaGetSymbolAddress((void**)&catt,  g_catt);
    cudaGetSymbolAddress((void**)&hdb,   g_hd);
    cudaGetSymbolAddress((void**)&htb,   g_ht);
    cudaGetSymbolAddress((void**)&hdp,   g_hdp);
    cudaGetSymbolAddress((void**)&htp,   g_htp);
    cudaGetSymbolAddress((void**)&htpT,  g_htpT);
    cudaGetSymbolAddress((void**)&bsd,   g_bsd);
    cudaGetSymbolAddress((void**)&bst,   g_bst);
    cudaGetSymbolAddress((void**)&bsd2,  g_bsd2);
    cudaGetSymbolAddress((void**)&bst2,  g_bst2);
    cudaGetSymbolAddress((void**)&pa,    g_pa);
    cudaGetSymbolAddress((void**)&pb,    g_pb);
    cudaGetSymbolAddress((void**)&sd,    g_sd);
    cudaGetSymbolAddress((void**)&st,    g_st);
    cudaGetSymbolAddress((void**)&nd,    g_nd);
    cudaGetSymbolAddress((void**)&nt,    g_nt);
    cudaGetSymbolAddress((void**)&ntraw, g_ntraw);
    cudaGetSymbolAddress((void**)&part,  g_part);
    cudaGetSymbolAddress((void**)&selidx, g_selidx);
    cudaGetSymbolAddress((void**)&selval, g_selval);

    rowsum_rsqrt<<<D_NUM, 256>>>(Dm, D_NUM, D_NUM, sd);
    rowsum_rsqrt<<<T_NUM, 256>>>(Tm, T_NUM, T_NUM, st);

    const float* hd = H_d;
    const float* ht = H_t;
    int F = FEAT;

    for (int lvl = 0; lvl < 2; lvl++) {
        prescale2<<<dim3((F / 4 + 255) / 256, D_NUM, 2), 256>>>(
            bsd, hd, sd, D_NUM, bst, ht, st, T_NUM, F / 4);
        // split-K(8) Dn/Tn — 64x256 kernel
        {
            GemmP pD = mk(Dm, bsd, pa, D_NUM, F, D_NUM, D_NUM, F, F, nullptr);
            GemmP pT = mk(Tm, bst, pb, T_NUM, F, T_NUM, T_NUM, F, F, nullptr);
            mma_gemm_x<true, 8><<<grid2_x(pD, pT, 8), GTHREADSW>>>(pD, pT);
            reduce2<4, 8><<<red_grid(pD, pT), 256>>>(
                catd + 2 * F, 3 * F, pa, sd, D_NUM, F,
                catt + 2 * F, 3 * F, pb, st, T_NUM, F);
        }
        // projections (64-tile)
        {
            GemmP pd = mk(hd, W1g[lvl], hdp, D_NUM, UNITS, F, F, UNITS, UNITS, nullptr);
            GemmP pt = mk(ht, W2g[lvl], htp, T_NUM, UNITS, F, F, UNITS, UNITS, nullptr);
            mma_gemm_f<3, true, true, 1><<<grid2_f(pd, pt, 1), GTHREADS>>>(pd, pt);
        }
        transpose_kernel<<<tr_grid(T_NUM, UNITS), dim3(32, 8)>>>(htpT, htp, T_NUM, UNITS);
        // sigmoid relation GEMM (N=2000) — wide kernel
        {
            GemmP ps = mk(hdp, htpT, S, D_NUM, T_NUM, UNITS, UNITS, T_NUM, T_NUM, nullptr);
            mma_gemm_w<2, false, false, 1><<<grid1_w(ps), GTHREADSW>>>(ps, ps);
        }

        zero_vec<<<(T_NUM + 255) / 256, 256>>>(ntraw, T_NUM);
        topk_kernel<<<D_NUM, 256>>>(S, selidx, selval, nd, ntraw);

        gather_dt<<<D_NUM, 256>>>(selidx, selval, nd, ntraw, ht, F, catd + F, 3 * F);
        zero_strided<<<dim3((F + 255) / 256, T_NUM), 256>>>(catt + F, 3 * F, T_NUM, F);
        scatter_td<<<D_NUM * TOPK, 256>>>(selidx, selval, nd, ntraw, hd, F, catt + F, 3 * F);
        relu_round_strided<<<dim3((F + 255) / 256, T_NUM), 256>>>(catt + F, 3 * F, T_NUM, F);
        copy_round2<<<dim3((F + 255) / 256, D_NUM, 2), 256>>>(
            catd, 3 * F, hd, F, D_NUM, catt, 3 * F, ht, F, T_NUM, F);

        // split-K(2) concat dense (64-tile)
        {
            GemmP pd = mk(catd, Wd[lvl], pa, D_NUM, UNITS, 3 * F, 3 * F, UNITS, UNITS, nullptr);
            GemmP pt = mk(catt, Wt[lvl], pb, T_NUM, UNITS, 3 * F, 3 * F, UNITS, UNITS, nullptr);
            mma_gemm_f<0, false, true, 2><<<grid2_f(pd, pt, 2), GTHREADS>>>(pd, pt);
            reduce2<1, 2><<<red_grid(pd, pt), 256>>>(
                hdb, UNITS, pa, nullptr, D_NUM, UNITS,
                htb, UNITS, pb, nullptr, T_NUM, UNITS);
        }
        hd = hdb; ht = htb; F = UNITS;
    }

    // ---- output CGC on original (dense) R ----
    rowsum_rsqrt<<<D_NUM, 256>>>(R, D_NUM, T_NUM, nd);
    colsum_partial<<<dim3((T_NUM + 255) / 256, NCHUNK), 256>>>(R, D_NUM, T_NUM, part);
    colsum_finish<<<(T_NUM + 255) / 256, 256>>>(part, T_NUM, nt);
    transpose_kernel<<<tr_grid(D_NUM, T_NUM), dim3(32, 8)>>>(RT, R, D_NUM, T_NUM);

    prescale2<<<dim3((F / 4 + 255) / 256, D_NUM, 2), 256>>>(
        bsd, ht, nt, T_NUM, bst, hd, nd, D_NUM, F / 4);
    prescale2<<<dim3((F / 4 + 255) / 256, D_NUM, 2), 256>>>(
        bsd2, hd, sd, D_NUM, bst2, ht, st, T_NUM, F / 4);

    // split-K(8) R-pair — 64x256 kernel
    {
        GemmP pra = mk(R,  bsd, pa, D_NUM, F, T_NUM, T_NUM, F, F, nullptr);
        GemmP prb = mk(RT, bst, pb, T_NUM, F, D_NUM, D_NUM, F, F, nullptr);
        mma_gemm_x<true, 8><<<grid2_x(pra, prb, 8), GTHREADSW>>>(pra, prb);
        reduce2<4, 8><<<red_grid(pra, prb), 256>>>(
            catd + F, 3 * F, pa, nd, D_NUM, F,
            catt + F, 3 * F, pb, nt, T_NUM, F);
    }
    // split-K(8) Dn/Tn pair — 64x256 kernel
    {
        GemmP pD = mk(Dm, bsd2, pa, D_NUM, F, D_NUM, D_NUM, F, F, nullptr);
        GemmP pT = mk(Tm, bst2, pb, T_NUM, F, T_NUM, T_NUM, F, F, nullptr);
        mma_gemm_x<true, 8><<<grid2_x(pD, pT, 8), GTHREADSW>>>(pD, pT);
        reduce2<4, 8><<<red_grid(pD, pT), 256>>>(
            catd + 2 * F, 3 * F, pa, sd, D_NUM, F,
            catt + 2 * F, 3 * F, pb, st, T_NUM, F);
    }

    copy_round2<<<dim3((F + 255) / 256, D_NUM, 2), 256>>>(
        catd, 3 * F, hd, F, D_NUM, catt, 3 * F, ht, F, T_NUM, F);

    // split-K(2) output dense (64-tile)
    {
        GemmP pd = mk(catd, WdO, pa, D_NUM, UNITS, 3 * F, 3 * F, UNITS, UNITS, nullptr);
        GemmP pt = mk(catt, WtO, pb, T_NUM, UNITS, 3 * F, 3 * F, UNITS, UNITS, nullptr);
        mma_gemm_f<0, false, true, 2><<<grid2_f(pd, pt, 2), GTHREADS>>>(pd, pt);
        reduce2<4, 2><<<red_grid(pd, pt), 256>>>(
            hdp, UNITS, pa, nullptr, D_NUM, UNITS,
            htp, UNITS, pb, nullptr, T_NUM, UNITS);
    }

    // R_pred = sigmoid(hd_out @ ht_out^T) — wide kernel
    transpose_kernel<<<tr_grid(T_NUM, UNITS), dim3(32, 8)>>>(htpT, htp, T_NUM, UNITS);
    {
        GemmP ps = mk(hdp, htpT, out, D_NUM, T_NUM, UNITS, UNITS, T_NUM, T_NUM, nullptr);
        mma_gemm_w<2, false, false, 1><<<grid1_w(ps), GTHREADSW>>>(ps, ps);
    }
}

// round 15
// speedup vs baseline: 1.2821x; 1.0072x over previous
#include <cuda_runtime.h>
#include <math.h>
#include <stdint.h>

#define D_NUM 4000
#define T_NUM 2000
#define FEAT  256
#define UNITS 200
#define TOPK  10
#define NCHUNK 16

// ---------------- scratch ----------------
__device__ float g_S[(size_t)D_NUM * T_NUM];
__device__ float g_RT[(size_t)T_NUM * D_NUM];
__device__ float g_catd[(size_t)D_NUM * 3 * FEAT];
__device__ float g_catt[(size_t)T_NUM * 3 * FEAT];
__device__ float g_hd[(size_t)D_NUM * FEAT];
__device__ float g_ht[(size_t)T_NUM * FEAT];
__device__ float g_hdp[(size_t)D_NUM * UNITS];
__device__ float g_htp[(size_t)T_NUM * UNITS];
__device__ float g_htpT[(size_t)UNITS * T_NUM];
__device__ float g_bsd[(size_t)D_NUM * FEAT];
__device__ float g_bst[(size_t)D_NUM * FEAT];
__device__ float g_bsd2[(size_t)D_NUM * FEAT];
__device__ float g_bst2[(size_t)D_NUM * FEAT];
__device__ float g_pa[(size_t)8 * D_NUM * FEAT];
__device__ float g_pb[(size_t)8 * D_NUM * FEAT];
__device__ float g_pc[(size_t)8 * D_NUM * FEAT];
__device__ float g_pd[(size_t)8 * D_NUM * FEAT];
__device__ float g_sd[D_NUM];
__device__ float g_st[T_NUM];
__device__ float g_nd[D_NUM];
__device__ float g_nt[T_NUM];
__device__ float g_ntraw[T_NUM];
__device__ float g_part[NCHUNK * T_NUM];
__device__ int   g_selidx[D_NUM * TOPK];
__device__ float g_selval[D_NUM * TOPK];

__device__ __forceinline__ uint32_t f2tf(float x) {
    uint32_t r;
    asm("cvt.rna.tf32.f32 %0, %1;" : "=r"(r) : "f"(x));
    return r;
}
__device__ __forceinline__ float roundtf(float x) {
    return __uint_as_float(f2tf(x));
}

// ---------------- reductions ----------------
__global__ void rowsum_rsqrt(const float* __restrict__ A, int rows, int cols,
                             float* __restrict__ out) {
    int row = blockIdx.x;
    if (row >= rows) return;
    const float* a = A + (size_t)row * cols;
    float s = 0.f;
    for (int j = threadIdx.x; j < cols; j += blockDim.x) s += a[j];
    __shared__ float red[256];
    red[threadIdx.x] = s;
    __syncthreads();
    for (int off = 128; off > 0; off >>= 1) {
        if (threadIdx.x < off) red[threadIdx.x] += red[threadIdx.x + off];
        __syncthreads();
    }
    if (threadIdx.x == 0) {
        float n = red[0];
        if (n == 0.f) n = 1.f;
        out[row] = rsqrtf(n);
    }
}

__global__ void colsum_partial(const float* __restrict__ A, int rows, int cols,
                               float* __restrict__ part) {
    int j = blockIdx.x * blockDim.x + threadIdx.x;
    if (j >= cols) return;
    int chunk = (rows + NCHUNK - 1) / NCHUNK;
    int r0 = blockIdx.y * chunk;
    int r1 = r0 + chunk; if (r1 > rows) r1 = rows;
    float s = 0.f;
    for (int i = r0; i < r1; i++) s += A[(size_t)i * cols + j];
    part[blockIdx.y * cols + j] = s;
}

__global__ void colsum_finish(const float* __restrict__ part, int cols,
                              float* __restrict__ out) {
    int j = blockIdx.x * blockDim.x + threadIdx.x;
    if (j >= cols) return;
    float s = 0.f;
    for (int c = 0; c < NCHUNK; c++) s += part[c * cols + j];
    if (s == 0.f) s = 1.f;
    out[j] = rsqrtf(s);
}

// ---------------- prep kernels ----------------
__global__ void prescale2(float* dst0, const float* src0, const float* sc0, int rows0,
                          float* dst1, const float* src1, const float* sc1, int rows1,
                          int cols4) {
    int c4 = blockIdx.x * blockDim.x + threadIdx.x;
    int r = blockIdx.y;
    float* dst = blockIdx.z ? dst1 : dst0;
    const float* src = blockIdx.z ? src1 : src0;
    const float* sc = blockIdx.z ? sc1 : sc0;
    int rows = blockIdx.z ? rows1 : rows0;
    if (c4 >= cols4 || r >= rows) return;
    float s = sc[r];
    float4 v = reinterpret_cast<const float4*>(src + (size_t)r * cols4 * 4)[c4];
    v.x = roundtf(v.x * s); v.y = roundtf(v.y * s);
    v.z = roundtf(v.z * s); v.w = roundtf(v.w * s);
    reinterpret_cast<float4*>(dst + (size_t)r * cols4 * 4)[c4] = v;
}

__global__ void transpose_kernel(float* __restrict__ dst, const float* __restrict__ src,
                                 int rows, int cols) {
    __shared__ float t[32][33];
    int bx = blockIdx.x * 32, by = blockIdx.y * 32;
    int x = bx + threadIdx.x;
    #pragma unroll
    for (int i = 0; i < 32; i += 8) {
        int y = by + threadIdx.y + i;
        if (x < cols && y < rows) t[threadIdx.y + i][threadIdx.x] = src[(size_t)y * cols + x];
    }
    __syncthreads();
    int x2 = by + threadIdx.x;
    #pragma unroll
    for (int i = 0; i < 32; i += 8) {
        int y2 = bx + threadIdx.y + i;
        if (x2 < rows && y2 < cols) dst[(size_t)y2 * rows + x2] = t[threadIdx.x][threadIdx.y + i];
    }
}

__global__ void zero_vec(float* __restrict__ p, int n) {
    int i = blockIdx.x * blockDim.x + threadIdx.x;
    if (i < n) p[i] = 0.f;
}

__global__ void zero_strided(float* __restrict__ dst, int ld, int rows, int cols) {
    int c = blockIdx.x * blockDim.x + threadIdx.x;
    int r = blockIdx.y;
    if (c < cols && r < rows) dst[(size_t)r * ld + c] = 0.f;
}

__global__ void relu_round_strided(float* __restrict__ dst, int ld, int rows, int cols) {
    int c = blockIdx.x * blockDim.x + threadIdx.x;
    int r = blockIdx.y;
    if (c < cols && r < rows) {
        size_t o = (size_t)r * ld + c;
        dst[o] = roundtf(fmaxf(dst[o], 0.f));
    }
}

__global__ void copy_round2(float* dst0, int ldd0, const float* src0, int lds0, int rows0,
                            float* dst1, int ldd1, const float* src1, int lds1, int rows1,
                            int cols) {
    int c = blockIdx.x * blockDim.x + threadIdx.x;
    int r = blockIdx.y;
    float* dst = blockIdx.z ? dst1 : dst0;
    const float* src = blockIdx.z ? src1 : src0;
    int ldd = blockIdx.z ? ldd1 : ldd0;
    int lds = blockIdx.z ? lds1 : lds0;
    int rows = blockIdx.z ? rows1 : rows0;
    if (c < cols && r < rows)
        dst[(size_t)r * ldd + c] = roundtf(src[(size_t)r * lds + c]);
}

// split-K reduce + epilogue, z-fused pair, NS slabs.
template <int EPI, int NS>
__global__ void reduce2(float* out0, int ld0, const float* part0, const float* rs0, int M0, int N0,
                        float* out1, int ld1, const float* part1, const float* rs1, int M1, int N1) {
    int c = blockIdx.x * blockDim.x + threadIdx.x;
    int r = blockIdx.y;
    float* out = blockIdx.z ? out1 : out0;
    const float* part = blockIdx.z ? part1 : part0;
    const float* rs = blockIdx.z ? rs1 : rs0;
    int M = blockIdx.z ? M1 : M0;
    int N = blockIdx.z ? N1 : N0;
    int ld = blockIdx.z ? ld1 : ld0;
    if (r >= M || c >= N) return;
    size_t o = (size_t)r * N + c;
    size_t slab = (size_t)M * N;
    float v = 0.f;
    #pragma unroll
    for (int s = 0; s < NS; s++) v += part[s * slab + o];
    if (rs) v *= rs[r];
    if (EPI == 1 || EPI == 4) v = fmaxf(v, 0.f);
    if (EPI >= 3) v = roundtf(v);
    out[(size_t)r * ld + c] = v;
}

// 4-way fused reduce (output-stage quad)
struct RedP { float* out; int ld; const float* part; const float* rs; int M, N; };
struct RedP4 { RedP q[4]; };

template <int EPI, int NS>
__global__ void reduce4(RedP4 rp) {
    const RedP p = rp.q[blockIdx.z];
    int c = blockIdx.x * blockDim.x + threadIdx.x;
    int r = blockIdx.y;
    if (r >= p.M || c >= p.N) return;
    size_t o = (size_t)r * p.N + c;
    size_t slab = (size_t)p.M * p.N;
    float v = 0.f;
    #pragma unroll
    for (int s = 0; s < NS; s++) v += p.part[s * slab + o];
    if (p.rs) v *= p.rs[r];
    if (EPI == 1 || EPI == 4) v = fmaxf(v, 0.f);
    if (EPI >= 3) v = roundtf(v);
    p.out[(size_t)r * p.ld + c] = v;
}

// ---------------- top-k ----------------
__global__ void topk_kernel(const float* __restrict__ S,
                            int* __restrict__ selidx, float* __restrict__ selval,
                            float* __restrict__ nd_out, float* __restrict__ ntraw) {
    int row = blockIdx.x;
    int tid = threadIdx.x;
    int lane = tid & 31, wid = tid >> 5;
    const float* srow = S + (size_t)row * T_NUM;

    float v[8];
    #pragma unroll
    for (int i = 0; i < 8; i++) {
        int j = tid + i * 256;
        v[i] = (j < T_NUM) ? srow[j] : -3.f;
    }

    __shared__ float wv[8];
    __shared__ int   wi[8];
    __shared__ int   bidx_s;
    __shared__ int   sel[TOPK];
    __shared__ float selv[TOPK];

    for (int it = 0; it < TOPK; it++) {
        float best = v[0]; int bi = tid;
        #pragma unroll
        for (int i = 1; i < 8; i++) {
            int j = tid + i * 256;
            if (v[i] > best) { best = v[i]; bi = j; }
        }
        #pragma unroll
        for (int off = 16; off > 0; off >>= 1) {
            float ov = __shfl_xor_sync(0xffffffffu, best, off);
            int   oi = __shfl_xor_sync(0xffffffffu, bi, off);
            if (ov > best || (ov == best && oi < bi)) { best = ov; bi = oi; }
        }
        if (lane == 0) { wv[wid] = best; wi[wid] = bi; }
        __syncthreads();
        if (tid == 0) {
            float b = wv[0]; int x = wi[0];
            #pragma unroll
            for (int w = 1; w < 8; w++)
                if (wv[w] > b || (wv[w] == b && wi[w] < x)) { b = wv[w]; x = wi[w]; }
            bidx_s = x; sel[it] = x; selv[it] = b;
        }
        __syncthreads();
        int x = bidx_s;
        if ((x & 255) == tid) v[x >> 8] = -3.f;
    }

    if (tid < TOPK) {
        selidx[row * TOPK + tid] = sel[tid];
        selval[row * TOPK + tid] = selv[tid];
        atomicAdd(&ntraw[sel[tid]], selv[tid]);
    }
    if (tid == 0) {
        float s = 0.f;
        #pragma unroll
        for (int t = 0; t < TOPK; t++) s += selv[t];
        if (s == 0.f) s = 1.f;
        nd_out[row] = rsqrtf(s);
    }
}

// ---------------- sparse CGC ----------------
__global__ void gather_dt(const int* __restrict__ selidx, const float* __restrict__ selval,
                          const float* __restrict__ nd, const float* __restrict__ ntraw,
                          const float* __restrict__ ht, int F,
                          float* __restrict__ outd, int ldo) {
    int d = blockIdx.x;
    __shared__ int   ci[TOPK];
    __shared__ float cw[TOPK];
    if (threadIdx.x < TOPK) {
        int c = selidx[d * TOPK + threadIdx.x];
        float s = ntraw[c];
        if (s == 0.f) s = 1.f;
        ci[threadIdx.x] = c;
        cw[threadIdx.x] = selval[d * TOPK + threadIdx.x] * rsqrtf(s);
    }
    __syncthreads();
    float ndv = nd[d];
    for (int f = threadIdx.x; f < F; f += blockDim.x) {
        float s = 0.f;
        #pragma unroll
        for (int j = 0; j < TOPK; j++) s += cw[j] * ht[(size_t)ci[j] * F + f];
        outd[(size_t)d * ldo + f] = roundtf(fmaxf(s * ndv, 0.f));
    }
}

__global__ void scatter_td(const int* __restrict__ selidx, const float* __restrict__ selval,
                           const float* __restrict__ nd, const float* __restrict__ ntraw,
                           const float* __restrict__ hd, int F,
                           float* __restrict__ outt, int ldo) {
    int e = blockIdx.x;
    int d = e / TOPK;
    int t = selidx[e];
    float s = ntraw[t];
    if (s == 0.f) s = 1.f;
    float w = selval[e] * nd[d] * rsqrtf(s);
    const float* src = hd + (size_t)d * F;
    float* dst = outt + (size_t)t * ldo;
    for (int f = threadIdx.x; f < F; f += blockDim.x)
        atomicAdd(&dst[f], w * src[f]);
}

// ---------------- common GEMM bits ----------------
struct GemmP {
    const float* A;
    const float* B;
    float* C;
    int M, N, K, lda, ldb, ldc;
    const float* rowscale;
};
struct GemmP4 { GemmP p[4]; };

__device__ __forceinline__ void mma_tf32(float c[4], uint32_t a0, uint32_t a1,
                                         uint32_t a2, uint32_t a3,
                                         uint32_t b0, uint32_t b1) {
    asm volatile(
        "mma.sync.aligned.m16n8k8.row.col.f32.tf32.tf32.f32 "
        "{%0,%1,%2,%3}, {%4,%5,%6,%7}, {%8,%9}, {%0,%1,%2,%3};"
        : "+f"(c[0]), "+f"(c[1]), "+f"(c[2]), "+f"(c[3])
        : "r"(a0), "r"(a1), "r"(a2), "r"(a3), "r"(b0), "r"(b1));
}

__device__ __forceinline__ uint32_t cvt_bits(uint32_t raw) {
    return f2tf(__uint_as_float(raw));
}

__device__ __forceinline__ void cp_async16(uint32_t dst_smem, const void* src, bool pred) {
    int sz = pred ? 16 : 0;
    asm volatile("cp.async.cg.shared.global [%0], [%1], 16, %2;"
                 :: "r"(dst_smem), "l"(src), "r"(sz));
}
#define CP_COMMIT() asm volatile("cp.async.commit_group;")
#define CP_WAIT1()  asm volatile("cp.async.wait_group 1;")

#define GBK 16
#define NSTAGE 3
#define ASTR (GBK + 4)

// ============ 64x64 kernel, 128 threads (small/medium launches) ============
#define GBM 64
#define GBN 64
#define BSTR (GBN + 8)
#define GTHREADS 128

template <int EPI, bool ACVT, bool BCVT, int NS>
__global__ __launch_bounds__(GTHREADS)
void mma_gemm_f(GemmP p0, GemmP p1) {
    int prob = blockIdx.z / NS;
    int split = blockIdx.z % NS;
    const GemmP p = prob ? p1 : p0;
    int bm = blockIdx.y * GBM;
    int bn = blockIdx.x * GBN;
    if (bm >= p.M || bn >= p.N) return;

    __shared__ uint32_t As[NSTAGE][GBM][ASTR];
    __shared__ uint32_t Bs[NSTAGE][GBK][BSTR];

    int tid = threadIdx.x;
    int lane = tid & 31;
    int warp = tid >> 5;
    int gid = lane >> 2, tig = lane & 3;
    int mw = (warp & 1) * 32;
    int nw = (warp >> 1) * 32;

    uint32_t sa = (uint32_t)__cvta_generic_to_shared(&As[0][0][0]);
    uint32_t sb = (uint32_t)__cvta_generic_to_shared(&Bs[0][0][0]);

    float acc[2][4][4];
    #pragma unroll
    for (int i = 0; i < 2; i++)
        #pragma unroll
        for (int j = 0; j < 4; j++)
            #pragma unroll
            for (int l = 0; l < 4; l++) acc[i][j][l] = 0.f;

    int nkt_total = (p.K + GBK - 1) / GBK;
    int chunk = (nkt_total + NS - 1) / NS;
    int kt_begin = split * chunk;
    int kt_end = min(nkt_total, kt_begin + chunk);
    int niter = kt_end - kt_begin;
    if (niter < 0) niter = 0;

    int a_m0 = tid >> 1;
    int a_kq = (tid & 1) * 8;
    int b_kb = tid >> 3;
    int b_nq = (tid & 7) * 8;

    auto issue_tile = [&](int kt, int st) {
        int k0 = kt * GBK;
        {
            int gm = bm + a_m0;
            const float* src = p.A + (size_t)gm * p.lda + k0 + a_kq;
            uint32_t dst = sa + (((st * GBM + a_m0) * ASTR) + a_kq) * 4;
            bool rowok = (gm < p.M);
            cp_async16(dst,      src,     rowok && (k0 + a_kq     < p.K));
            cp_async16(dst + 16, src + 4, rowok && (k0 + a_kq + 4 < p.K));
        }
        {
            int gk = k0 + b_kb;
            const float* src = p.B + (size_t)gk * p.ldb + bn + b_nq;
            uint32_t dst = sb + (((st * GBK + b_kb) * BSTR) + b_nq) * 4;
            bool kok = (gk < p.K);
            cp_async16(dst,      src,     kok && (bn + b_nq     < p.N));
            cp_async16(dst + 16, src + 4, kok && (bn + b_nq + 4 < p.N));
        }
    };

    #pragma unroll
    for (int s = 0; s < NSTAGE - 1; s++) {
        if (s < niter) issue_tile(kt_begin + s, s);
        CP_COMMIT();
    }

    int cur = 0;
    for (int it = 0; it < niter; it++) {
        CP_WAIT1();
        __syncthreads();

        #pragma unroll
        for (int kk = 0; kk < GBK; kk += 8) {
            uint32_t b0[4], b1[4];
            #pragma unroll
            for (int nt = 0; nt < 4; nt++) {
                b0[nt] = Bs[cur][kk + tig][nw + nt * 8 + gid];
                b1[nt] = Bs[cur][kk + tig + 4][nw + nt * 8 + gid];
                if (BCVT) { b0[nt] = cvt_bits(b0[nt]); b1[nt] = cvt_bits(b1[nt]); }
            }
            #pragma unroll
            for (int mt = 0; mt < 2; mt++) {
                int mb = mw + mt * 16;
                uint32_t a0 = As[cur][mb + gid][kk + tig];
                uint32_t a1 = As[cur][mb + gid + 8][kk + tig];
                uint32_t a2 = As[cur][mb + gid][kk + tig + 4];
                uint32_t a3 = As[cur][mb + gid + 8][kk + tig + 4];
                if (ACVT) {
                    a0 = cvt_bits(a0); a1 = cvt_bits(a1);
                    a2 = cvt_bits(a2); a3 = cvt_bits(a3);
                }
                #pragma unroll
                for (int nt = 0; nt < 4; nt++)
                    mma_tf32(acc[mt][nt], a0, a1, a2, a3, b0[nt], b1[nt]);
            }
        }

        if (it + NSTAGE - 1 < niter) {
            int st = (cur + NSTAGE - 1) % NSTAGE;
            issue_tile(kt_begin + it + NSTAGE - 1, st);
        }
        CP_COMMIT();
        cur = (cur + 1) % NSTAGE;
    }

    if (NS > 1) {
        float* dst = p.C + (size_t)split * p.M * p.N;
        #pragma unroll
        for (int mt = 0; mt < 2; mt++) {
            int gm0 = bm + mw + mt * 16 + gid;
            int gm1 = gm0 + 8;
            #pragma unroll
            for (int nt = 0; nt < 4; nt++) {
                int gn0 = bn + nw + nt * 8 + 2 * tig;
                int gn1 = gn0 + 1;
                #pragma unroll
                for (int q = 0; q < 4; q++) {
                    int gm = (q < 2) ? gm0 : gm1;
                    int gn = (q & 1) ? gn1 : gn0;
                    if (gm >= p.M || gn >= p.N) continue;
                    dst[(size_t)gm * p.N + gn] = acc[mt][nt][q];
                }
            }
        }
        return;
    }

    #pragma unroll
    for (int mt = 0; mt < 2; mt++) {
        int gm0 = bm + mw + mt * 16 + gid;
        int gm1 = gm0 + 8;
        float rs0 = 1.f, rs1 = 1.f;
        if (p.rowscale) {
            if (gm0 < p.M) rs0 = p.rowscale[gm0];
            if (gm1 < p.M) rs1 = p.rowscale[gm1];
        }
        #pragma unroll
        for (int nt = 0; nt < 4; nt++) {
            int gn0 = bn + nw + nt * 8 + 2 * tig;
            int gn1 = gn0 + 1;
            #pragma unroll
            for (int q = 0; q < 4; q++) {
                int gm = (q < 2) ? gm0 : gm1;
                int gn = (q & 1) ? gn1 : gn0;
                if (gm >= p.M || gn >= p.N) continue;
                float v = acc[mt][nt][q] * ((q < 2) ? rs0 : rs1);
                if (EPI == 1 || EPI == 4) v = fmaxf(v, 0.f);
                else if (EPI == 2) v = 1.f / (1.f + __expf(-v));
                if (EPI >= 3) v = roundtf(v);
                p.C[(size_t)gm * p.ldc + gn] = v;
            }
        }
    }
}

// ============ 64x128 kernel, 256 threads (wide-N; big launches), up to 4 problems =
#define GBNW 128
#define BSTRW (GBNW + 8)
#define GTHREADSW 256

template <int EPI, bool ACVT, bool BCVT, int NS, int NPROB>
__global__ __launch_bounds__(GTHREADSW)
void mma_gemm_w(GemmP4 ps) {
    int prob = blockIdx.z / NS;
    int split = blockIdx.z % NS;
    const GemmP p = ps.p[NPROB == 1 ? 0 : prob];
    int bm = blockIdx.y * GBM;
    int bn = blockIdx.x * GBNW;
    if (bm >= p.M || bn >= p.N) return;

    __shared__ uint32_t As[NSTAGE][GBM][ASTR];
    __shared__ uint32_t Bs[NSTAGE][GBK][BSTRW];

    int tid = threadIdx.x;
    int lane = tid & 31;
    int warp = tid >> 5;
    int gid = lane >> 2, tig = lane & 3;
    int mw = (warp & 1) * 32;
    int nw = (warp >> 1) * 32;

    uint32_t sa = (uint32_t)__cvta_generic_to_shared(&As[0][0][0]);
    uint32_t sb = (uint32_t)__cvta_generic_to_shared(&Bs[0][0][0]);

    float acc[2][4][4];
    #pragma unroll
    for (int i = 0; i < 2; i++)
        #pragma unroll
        for (int j = 0; j < 4; j++)
            #pragma unroll
            for (int l = 0; l < 4; l++) acc[i][j][l] = 0.f;

    int nkt_total = (p.K + GBK - 1) / GBK;
    int chunk = (nkt_total + NS - 1) / NS;
    int kt_begin = split * chunk;
    int kt_end = min(nkt_total, kt_begin + chunk);
    int niter = kt_end - kt_begin;
    if (niter < 0) niter = 0;

    int a_m0 = tid >> 2;
    int a_kq = (tid & 3) * 4;
    int b_kb = tid >> 4;
    int b_nq = (tid & 15) * 8;

    auto issue_tile = [&](int kt, int st) {
        int k0 = kt * GBK;
        {
            int gm = bm + a_m0;
            const float* src = p.A + (size_t)gm * p.lda + k0 + a_kq;
            uint32_t dst = sa + (((st * GBM + a_m0) * ASTR) + a_kq) * 4;
            cp_async16(dst, src, (gm < p.M) && (k0 + a_kq < p.K));
        }
        {
            int gk = k0 + b_kb;
            const float* src = p.B + (size_t)gk * p.ldb + bn + b_nq;
            uint32_t dst = sb + (((st * GBK + b_kb) * BSTRW) + b_nq) * 4;
            bool kok = (gk < p.K);
            cp_async16(dst,      src,     kok && (bn + b_nq     < p.N));
            cp_async16(dst + 16, src + 4, kok && (bn + b_nq + 4 < p.N));
        }
    };

    #pragma unroll
    for (int s = 0; s < NSTAGE - 1; s++) {
        if (s < niter) issue_tile(kt_begin + s, s);
        CP_COMMIT();
    }

    int cur = 0;
    for (int it = 0; it < niter; it++) {
        CP_WAIT1();
        __syncthreads();

        #pragma unroll
        for (int kk = 0; kk < GBK; kk += 8) {
            uint32_t b0[4], b1[4];
            #pragma unroll
            for (int nt = 0; nt < 4; nt++) {
                b0[nt] = Bs[cur][kk + tig][nw + nt * 8 + gid];
                b1[nt] = Bs[cur][kk + tig + 4][nw + nt * 8 + gid];
                if (BCVT) { b0[nt] = cvt_bits(b0[nt]); b1[nt] = cvt_bits(b1[nt]); }
            }
            #pragma unroll
            for (int mt = 0; mt < 2; mt++) {
                int mb = mw + mt * 16;
                uint32_t a0 = As[cur][mb + gid][kk + tig];
                uint32_t a1 = As[cur][mb + gid + 8][kk + tig];
                uint32_t a2 = As[cur][mb + gid][kk + tig + 4];
                uint32_t a3 = As[cur][mb + gid + 8][kk + tig + 4];
                if (ACVT) {
                    a0 = cvt_bits(a0); a1 = cvt_bits(a1);
                    a2 = cvt_bits(a2); a3 = cvt_bits(a3);
                }
                #pragma unroll
                for (int nt = 0; nt < 4; nt++)
                    mma_tf32(acc[mt][nt], a0, a1, a2, a3, b0[nt], b1[nt]);
            }
        }

        if (it + NSTAGE - 1 < niter) {
            int st = (cur + NSTAGE - 1) % NSTAGE;
            issue_tile(kt_begin + it + NSTAGE - 1, st);
        }
        CP_COMMIT();
        cur = (cur + 1) % NSTAGE;
    }

    if (NS > 1) {
        float* dst = p.C + (size_t)split * p.M * p.N;
        #pragma unroll
        for (int mt = 0; mt < 2; mt++) {
            int gm0 = bm + mw + mt * 16 + gid;
            int gm1 = gm0 + 8;
            #pragma unroll
            for (int nt = 0; nt < 4; nt++) {
                int gn0 = bn + nw + nt * 8 + 2 * tig;
                int gn1 = gn0 + 1;
                #pragma unroll
                for (int q = 0; q < 4; q++) {
                    int gm = (q < 2) ? gm0 : gm1;
                    int gn = (q & 1) ? gn1 : gn0;
                    if (gm >= p.M || gn >= p.N) continue;
                    dst[(size_t)gm * p.N + gn] = acc[mt][nt][q];
                }
            }
        }
        return;
    }

    #pragma unroll
    for (int mt = 0; mt < 2; mt++) {
        int gm0 = bm + mw + mt * 16 + gid;
        int gm1 = gm0 + 8;
        float rs0 = 1.f, rs1 = 1.f;
        if (p.rowscale) {
            if (gm0 < p.M) rs0 = p.rowscale[gm0];
            if (gm1 < p.M) rs1 = p.rowscale[gm1];
        }
        #pragma unroll
        for (int nt = 0; nt < 4; nt++) {
            int gn0 = bn + nw + nt * 8 + 2 * tig;
            int gn1 = gn0 + 1;
            #pragma unroll
            for (int q = 0; q < 4; q++) {
                int gm = (q < 2) ? gm0 : gm1;
                int gn = (q & 1) ? gn1 : gn0;
                if (gm >= p.M || gn >= p.N) continue;
                float v = acc[mt][nt][q] * ((q < 2) ? rs0 : rs1);
                if (EPI == 1 || EPI == 4) v = fmaxf(v, 0.f);
                else if (EPI == 2) v = 1.f / (1.f + __expf(-v));
                if (EPI >= 3) v = roundtf(v);
                p.C[(size_t)gm * p.ldc + gn] = v;
            }
        }
    }
}

static inline GemmP mk(const float* A, const float* B, float* C,
                       int M, int N, int K, int lda, int ldb, int ldc,
                       const float* rs) {
    GemmP p; p.A = A; p.B = B; p.C = C; p.M = M; p.N = N; p.K = K;
    p.lda = lda; p.ldb = ldb; p.ldc = ldc; p.rowscale = rs; return p;
}
static inline GemmP4 mk4(GemmP a, GemmP b, GemmP c, GemmP d) {
    GemmP4 q; q.p[0] = a; q.p[1] = b; q.p[2] = c; q.p[3] = d; return q;
}
static inline dim3 grid2_f(const GemmP& a, const GemmP& b, int ns) {
    int gx = max((a.N + GBN - 1) / GBN, (b.N + GBN - 1) / GBN);
    int gy = max((a.M + GBM - 1) / GBM, (b.M + GBM - 1) / GBM);
    return dim3(gx, gy, 2 * ns);
}
static inline dim3 gridw(const GemmP4& q, int nprob, int ns) {
    int gx = 1, gy = 1;
    for (int i = 0; i < nprob; i++) {
        gx = max(gx, (q.p[i].N + GBNW - 1) / GBNW);
        gy = max(gy, (q.p[i].M + GBM - 1) / GBM);
    }
    return dim3(gx, gy, nprob * ns);
}
static inline dim3 tr_grid(int rows, int cols) {
    return dim3((cols + 31) / 32, (rows + 31) / 32);
}
static inline dim3 red_grid(const GemmP& a, const GemmP& b) {
    int n = max(a.N, b.N);
    int m = max(a.M, b.M);
    return dim3((n + 255) / 256, m, 2);
}

// ---------------- host orchestration ----------------
extern "C" void kernel_launch(void* const* d_in, const int* in_sizes, int n_in,
                              void* d_out, int out_size) {
    const float* R    = (const float*)d_in[0];
    const float* Dm   = (const float*)d_in[1];
    const float* Tm   = (const float*)d_in[2];
    const float* H_d  = (const float*)d_in[3];
    const float* H_t  = (const float*)d_in[4];
    const float* W1g[2] = {(const float*)d_in[5], (const float*)d_in[7]};
    const float* W2g[2] = {(const float*)d_in[6], (const float*)d_in[8]};
    const float* Wd[2]  = {(const float*)d_in[9], (const float*)d_in[11]};
    const float* Wt[2]  = {(const float*)d_in[10], (const float*)d_in[12]};
    const float* WdO  = (const float*)d_in[13];
    const float* WtO  = (const float*)d_in[14];
    float* out = (float*)d_out;

    float *S, *RT, *catd, *catt, *hdb, *htb, *hdp, *htp, *htpT;
    float *bsd, *bst, *bsd2, *bst2, *pa, *pb, *pc, *pd;
    float *sd, *st, *nd, *nt, *ntraw, *part, *selval;
    int* selidx;
    cudaGetSymbolAddress((void**)&S,     g_S);
    cudaGetSymbolAddress((void**)&RT,    g_RT);
    cudaGetSymbolAddress((void**)&catd,  g_catd);
    cudaGetSymbolAddress((void**)&catt,  g_catt);
    cudaGetSymbolAddress((void**)&hdb,   g_hd);
    cudaGetSymbolAddress((void**)&htb,   g_ht);
    cudaGetSymbolAddress((void**)&hdp,   g_hdp);
    cudaGetSymbolAddress((void**)&htp,   g_htp);
    cudaGetSymbolAddress((void**)&htpT,  g_htpT);
    cudaGetSymbolAddress((void**)&bsd,   g_bsd);
    cudaGetSymbolAddress((void**)&bst,   g_bst);
    cudaGetSymbolAddress((void**)&bsd2,  g_bsd2);
    cudaGetSymbolAddress((void**)&bst2,  g_bst2);
    cudaGetSymbolAddress((void**)&pa,    g_pa);
    cudaGetSymbolAddress((void**)&pb,    g_pb);
    cudaGetSymbolAddress((void**)&pc,    g_pc);
    cudaGetSymbolAddress((void**)&pd,    g_pd);
    cudaGetSymbolAddress((void**)&sd,    g_sd);
    cudaGetSymbolAddress((void**)&st,    g_st);
    cudaGetSymbolAddress((void**)&nd,    g_nd);
    cudaGetSymbolAddress((void**)&nt,    g_nt);
    cudaGetSymbolAddress((void**)&ntraw, g_ntraw);
    cudaGetSymbolAddress((void**)&part,  g_part);
    cudaGetSymbolAddress((void**)&selidx, g_selidx);
    cudaGetSymbolAddress((void**)&selval, g_selval);

    rowsum_rsqrt<<<D_NUM, 256>>>(Dm, D_NUM, D_NUM, sd);
    rowsum_rsqrt<<<T_NUM, 256>>>(Tm, T_NUM, T_NUM, st);

    const float* hd = H_d;
    const float* ht = H_t;
    int F = FEAT;

    for (int lvl = 0; lvl < 2; lvl++) {
        prescale2<<<dim3((F / 4 + 255) / 256, D_NUM, 2), 256>>>(
            bsd, hd, sd, D_NUM, bst, ht, st, T_NUM, F / 4);
        // split-K(8) Dn/Tn — wide kernel (pair)
        {
            GemmP pD = mk(Dm, bsd, pa, D_NUM, F, D_NUM, D_NUM, F, F, nullptr);
            GemmP pT = mk(Tm, bst, pb, T_NUM, F, T_NUM, T_NUM, F, F, nullptr);
            GemmP4 q = mk4(pD, pT, pD, pT);
            mma_gemm_w<0, true, false, 8, 2><<<gridw(q, 2, 8), GTHREADSW>>>(q);
            reduce2<4, 8><<<red_grid(pD, pT), 256>>>(
                catd + 2 * F, 3 * F, pa, sd, D_NUM, F,
                catt + 2 * F, 3 * F, pb, st, T_NUM, F);
        }
        // projections (64-tile)
        {
            GemmP pdp = mk(hd, W1g[lvl], hdp, D_NUM, UNITS, F, F, UNITS, UNITS, nullptr);
            GemmP ptp = mk(ht, W2g[lvl], htp, T_NUM, UNITS, F, F, UNITS, UNITS, nullptr);
            mma_gemm_f<3, true, true, 1><<<grid2_f(pdp, ptp, 1), GTHREADS>>>(pdp, ptp);
        }
        transpose_kernel<<<tr_grid(T_NUM, UNITS), dim3(32, 8)>>>(htpT, htp, T_NUM, UNITS);
        // sigmoid relation GEMM (N=2000) — wide kernel
        {
            GemmP psx = mk(hdp, htpT, S, D_NUM, T_NUM, UNITS, UNITS, T_NUM, T_NUM, nullptr);
            GemmP4 q = mk4(psx, psx, psx, psx);
            mma_gemm_w<2, false, false, 1, 1><<<gridw(q, 1, 1), GTHREADSW>>>(q);
        }

        zero_vec<<<(T_NUM + 255) / 256, 256>>>(ntraw, T_NUM);
        topk_kernel<<<D_NUM, 256>>>(S, selidx, selval, nd, ntraw);

        gather_dt<<<D_NUM, 256>>>(selidx, selval, nd, ntraw, ht, F, catd + F, 3 * F);
        zero_strided<<<dim3((F + 255) / 256, T_NUM), 256>>>(catt + F, 3 * F, T_NUM, F);
        scatter_td<<<D_NUM * TOPK, 256>>>(selidx, selval, nd, ntraw, hd, F, catt + F, 3 * F);
        relu_round_strided<<<dim3((F + 255) / 256, T_NUM), 256>>>(catt + F, 3 * F, T_NUM, F);
        copy_round2<<<dim3((F + 255) / 256, D_NUM, 2), 256>>>(
            catd, 3 * F, hd, F, D_NUM, catt, 3 * F, ht, F, T_NUM, F);

        // split-K(2) concat dense (64-tile)
        {
            GemmP pdd = mk(catd, Wd[lvl], pa, D_NUM, UNITS, 3 * F, 3 * F, UNITS, UNITS, nullptr);
            GemmP ptt = mk(catt, Wt[lvl], pb, T_NUM, UNITS, 3 * F, 3 * F, UNITS, UNITS, nullptr);
            mma_gemm_f<0, false, true, 2><<<grid2_f(pdd, ptt, 2), GTHREADS>>>(pdd, ptt);
            reduce2<1, 2><<<red_grid(pdd, ptt), 256>>>(
                hdb, UNITS, pa, nullptr, D_NUM, UNITS,
                htb, UNITS, pb, nullptr, T_NUM, UNITS);
        }
        hd = hdb; ht = htb; F = UNITS;
    }

    // ---- output CGC on original (dense) R ----
    rowsum_rsqrt<<<D_NUM, 256>>>(R, D_NUM, T_NUM, nd);
    colsum_partial<<<dim3((T_NUM + 255) / 256, NCHUNK), 256>>>(R, D_NUM, T_NUM, part);
    colsum_finish<<<(T_NUM + 255) / 256, 256>>>(part, T_NUM, nt);
    transpose_kernel<<<tr_grid(D_NUM, T_NUM), dim3(32, 8)>>>(RT, R, D_NUM, T_NUM);

    prescale2<<<dim3((F / 4 + 255) / 256, D_NUM, 2), 256>>>(
        bsd, ht, nt, T_NUM, bst, hd, nd, D_NUM, F / 4);
    prescale2<<<dim3((F / 4 + 255) / 256, D_NUM, 2), 256>>>(
        bsd2, hd, sd, D_NUM, bst2, ht, st, T_NUM, F / 4);

    // QUAD-fused split-K(8): R-pair + Dn/Tn pair in one launch
    {
        GemmP pra = mk(R,   bsd,  pa, D_NUM, F, T_NUM, T_NUM, F, F, nullptr);
        GemmP prb = mk(RT,  bst,  pb, T_NUM, F, D_NUM, D_NUM, F, F, nullptr);
        GemmP pDD = mk(Dm,  bsd2, pc, D_NUM, F, D_NUM, D_NUM, F, F, nullptr);
        GemmP pTT = mk(Tm,  bst2, pd, T_NUM, F, T_NUM, T_NUM, F, F, nullptr);
        GemmP4 q = mk4(pra, prb, pDD, pTT);
        mma_gemm_w<0, true, false, 8, 4><<<gridw(q, 4, 8), GTHREADSW>>>(q);

        RedP4 rp;
        rp.q[0] = { catd + F,     3 * F, pa, nd, D_NUM, F };
        rp.q[1] = { catt + F,     3 * F, pb, nt, T_NUM, F };
        rp.q[2] = { catd + 2 * F, 3 * F, pc, sd, D_NUM, F };
        rp.q[3] = { catt + 2 * F, 3 * F, pd, st, T_NUM, F };
        reduce4<4, 8><<<dim3((F + 255) / 256, D_NUM, 4), 256>>>(rp);
    }

    copy_round2<<<dim3((F + 255) / 256, D_NUM, 2), 256>>>(
        catd, 3 * F, hd, F, D_NUM, catt, 3 * F, ht, F, T_NUM, F);

    // split-K(2) output dense (64-tile)
    {
        GemmP pdd = mk(catd, WdO, pa, D_NUM, UNITS, 3 * F, 3 * F, UNITS, UNITS, nullptr);
        GemmP ptt = mk(catt, WtO, pb, T_NUM, UNITS, 3 * F, 3 * F, UNITS, UNITS, nullptr);
        mma_gemm_f<0, false, true, 2><<<grid2_f(pdd, ptt, 2), GTHREADS>>>(pdd, ptt);
        reduce2<4, 2><<<red_grid(pdd, ptt), 256>>>(
            hdp, UNITS, pa, nullptr, D_NUM, UNITS,
            htp, UNITS, pb, nullptr, T_NUM, UNITS);
    }

    // R_pred = sigmoid(hd_out @ ht_out^T) — wide kernel
    transpose_kernel<<<tr_grid(T_NUM, UNITS), dim3(32, 8)>>>(htpT, htp, T_NUM, UNITS);
    {
        GemmP psx = mk(hdp, htpT, out, D_NUM, T_NUM, UNITS, UNITS, T_NUM, T_NUM, nullptr);
        GemmP4 q = mk4(psx, psx, psx, psx);
        mma_gemm_w<2, false, false, 1, 1><<<gridw(q, 1, 1), GTHREADSW>>>(q);
    }
}